// round 3
// baseline (speedup 1.0000x reference)
#include <cuda_runtime.h>
#include <cstdint>
#include <cstddef>

#define NB 8
#define HW 4096
#define CI 256
#define DQ 64

// scratch (device globals -- no allocation allowed)
__device__ float g_Q[(size_t)NB * HW * DQ];    // tf32-rounded, pre-scaled by sqrt(log2 e)
__device__ float g_rZ[NB * HW];                // 1 / softmax row sum
__device__ float g_att[(size_t)NB * CI * HW];  // att in (C, HW)-linear layout per batch

static __device__ __forceinline__ float to_tf32(float x) {
    unsigned r; asm("cvt.rna.tf32.f32 %0, %1;" : "=r"(r) : "f"(x));
    return __uint_as_float(r);
}
static __device__ __forceinline__ float ex2f(float x) {
    float y; asm("ex2.approx.ftz.f32 %0, %1;" : "=f"(y) : "f"(x));
    return y;
}
static __device__ __forceinline__ void mma8(float c[4], unsigned a0, unsigned a1, unsigned a2,
                                            unsigned a3, unsigned b0, unsigned b1) {
    asm volatile(
        "mma.sync.aligned.m16n8k8.row.col.f32.tf32.tf32.f32 "
        "{%0,%1,%2,%3},{%4,%5,%6,%7},{%8,%9},{%0,%1,%2,%3};"
        : "+f"(c[0]), "+f"(c[1]), "+f"(c[2]), "+f"(c[3])
        : "r"(a0), "r"(a1), "r"(a2), "r"(a3), "r"(b0), "r"(b1));
}
#define FU __float_as_uint

// ---------------------------------------------------------------------------
// K1: Q = (F @ W) * sqrt(log2 e), fp32 FMA, tf32-rounded on store.
// Block 256 threads: 128(p) x 64(d) tile, K=256 in chunks of 32.
// ---------------------------------------------------------------------------
__global__ __launch_bounds__(256) void k_query(const float* __restrict__ F,
                                               const float* __restrict__ W) {
    __shared__ float A_s[32][132];  // F chunk, transposed [k][p]
    __shared__ float W_s[32][68];   // W chunk [k][d]
    const int tid = threadIdx.x;
    const int n = blockIdx.y, p0 = blockIdx.x * 128;
    const int tx = tid & 15, ty = tid >> 4;  // cols 4*tx.., rows 8*ty..
    float acc[8][4];
#pragma unroll
    for (int i = 0; i < 8; i++)
#pragma unroll
        for (int j = 0; j < 4; j++) acc[i][j] = 0.f;
    const float* Fb = F + ((size_t)n * HW + p0) * CI;

    for (int kc = 0; kc < 8; kc++) {
        __syncthreads();
#pragma unroll
        for (int i = 0; i < 4; i++) {
            int idx = tid + i * 256;
            int row = idx >> 3, c4 = (idx & 7) * 4;
            float4 v = *(const float4*)(Fb + (size_t)row * CI + kc * 32 + c4);
            A_s[c4 + 0][row] = v.x; A_s[c4 + 1][row] = v.y;
            A_s[c4 + 2][row] = v.z; A_s[c4 + 3][row] = v.w;
        }
#pragma unroll
        for (int i = 0; i < 2; i++) {
            int idx = tid + i * 256;
            int row = idx >> 4, c4 = (idx & 15) * 4;
            *(float4*)&W_s[row][c4] = *(const float4*)(W + (kc * 32 + row) * DQ + c4);
        }
        __syncthreads();
#pragma unroll
        for (int k = 0; k < 32; k++) {
            float4 a0 = *(float4*)&A_s[k][8 * ty];
            float4 a1 = *(float4*)&A_s[k][8 * ty + 4];
            float4 b  = *(float4*)&W_s[k][4 * tx];
            float av[8] = {a0.x, a0.y, a0.z, a0.w, a1.x, a1.y, a1.z, a1.w};
            float bv[4] = {b.x, b.y, b.z, b.w};
#pragma unroll
            for (int i = 0; i < 8; i++)
#pragma unroll
                for (int j = 0; j < 4; j++) acc[i][j] += av[i] * bv[j];
        }
    }
    const float s = 1.2011224087864498f;  // sqrt(log2 e): Q.Q = log2(e) * logit
#pragma unroll
    for (int i = 0; i < 8; i++) {
        int p = p0 + 8 * ty + i;
        float4 o;
        o.x = to_tf32(acc[i][0] * s); o.y = to_tf32(acc[i][1] * s);
        o.z = to_tf32(acc[i][2] * s); o.w = to_tf32(acc[i][3] * s);
        *(float4*)(g_Q + ((size_t)n * HW + p) * DQ + 4 * tx) = o;
    }
}

// ---------------------------------------------------------------------------
// K2: rZ[p] = 1 / sum_q 2^(Q[p].Q[q]).  64 p-rows per block, q streamed in 64s.
// tf32 mma for logits; deterministic reduction (regs + shfl + smem, no atomics).
// ---------------------------------------------------------------------------
__global__ __launch_bounds__(256) void k_rowsum() {
    __shared__ float Qp_s[64][68];
    __shared__ float Qq_s[64][68];
    __shared__ float Zp[8][64];
    const int tid = threadIdx.x, w = tid >> 5, lane = tid & 31;
    const int gid = lane >> 2, t4 = lane & 3;
    const int n = blockIdx.y, p0 = blockIdx.x * 64;
    const int m0 = (w & 3) * 16, nb = (w >> 2) * 32;
    const float* Qb = g_Q + (size_t)n * HW * DQ;

#pragma unroll
    for (int i = 0; i < 4; i++) {
        int idx = tid + i * 256;
        int row = idx >> 4, c4 = (idx & 15) * 4;
        *(float4*)&Qp_s[row][c4] = *(const float4*)(Qb + (size_t)(p0 + row) * DQ + c4);
    }
    float zr0 = 0.f, zr1 = 0.f;
    for (int qc = 0; qc < 64; qc++) {
        __syncthreads();
#pragma unroll
        for (int i = 0; i < 4; i++) {
            int idx = tid + i * 256;
            int row = idx >> 4, c4 = (idx & 15) * 4;
            *(float4*)&Qq_s[row][c4] = *(const float4*)(Qb + (size_t)(qc * 64 + row) * DQ + c4);
        }
        __syncthreads();
        float acc[4][4] = {};
#pragma unroll
        for (int kt = 0; kt < 8; kt++) {
            int k0 = kt * 8;
            unsigned a0 = FU(Qp_s[m0 + gid][k0 + t4]), a1 = FU(Qp_s[m0 + gid + 8][k0 + t4]);
            unsigned a2 = FU(Qp_s[m0 + gid][k0 + t4 + 4]), a3 = FU(Qp_s[m0 + gid + 8][k0 + t4 + 4]);
#pragma unroll
            for (int nt = 0; nt < 4; nt++) {
                unsigned b0 = FU(Qq_s[nb + nt * 8 + gid][k0 + t4]);
                unsigned b1 = FU(Qq_s[nb + nt * 8 + gid][k0 + t4 + 4]);
                mma8(acc[nt], a0, a1, a2, a3, b0, b1);
            }
        }
#pragma unroll
        for (int nt = 0; nt < 4; nt++) {
            zr0 += to_tf32(ex2f(acc[nt][0])) + to_tf32(ex2f(acc[nt][1]));
            zr1 += to_tf32(ex2f(acc[nt][2])) + to_tf32(ex2f(acc[nt][3]));
        }
    }
    zr0 += __shfl_xor_sync(0xffffffffu, zr0, 1);
    zr0 += __shfl_xor_sync(0xffffffffu, zr0, 2);
    zr1 += __shfl_xor_sync(0xffffffffu, zr1, 1);
    zr1 += __shfl_xor_sync(0xffffffffu, zr1, 2);
    if (t4 == 0) { Zp[w][m0 + gid] = zr0; Zp[w][m0 + gid + 8] = zr1; }
    __syncthreads();
    if (tid < 64) {
        int mg = tid >> 4;
        float z = Zp[mg][tid] + Zp[mg + 4][tid];
        g_rZ[n * HW + p0 + tid] = 1.f / z;
    }
}

// ---------------------------------------------------------------------------
// K3: att[q,c] += 2^(Qq.Qp) * G[p,c], G = F * rZ.  Output tile 128q x 128c,
// 512 threads, p streamed in 64s.  att stored (C, HW)-linear.
// ---------------------------------------------------------------------------
#define K3_F_QQ 0
#define K3_F_QP 8704
#define K3_F_E  (8704 + 4352)
#define K3_F_G  (8704 + 4352 + 8704)
#define K3_SMEM ((8704 + 4352 + 8704 + 8704) * 4)

__global__ __launch_bounds__(512, 1) void k_att(const float* __restrict__ F) {
    extern __shared__ float sm[];
    float(*Qq_s)[68]  = (float(*)[68])(sm + K3_F_QQ);   // 128x68
    float(*Qp_s)[68]  = (float(*)[68])(sm + K3_F_QP);   // 64x68
    float(*E_s)[68]   = (float(*)[68])(sm + K3_F_E);    // 128x68
    float(*G_s)[136]  = (float(*)[136])(sm + K3_F_G);   // 64x136
    const int tid = threadIdx.x, w = tid >> 5, lane = tid & 31;
    const int gid = lane >> 2, t4 = lane & 3;
    const int q0 = blockIdx.x * 128, c0 = blockIdx.y * 128, n = blockIdx.z;
    const float* Qb = g_Q + (size_t)n * HW * DQ;
    const float* Fb = F + (size_t)n * HW * CI;
    const float* rZb = g_rZ + n * HW;

#pragma unroll
    for (int i = 0; i < 4; i++) {
        int idx = tid + i * 512;
        int row = idx >> 4, c4 = (idx & 15) * 4;
        *(float4*)&Qq_s[row][c4] = *(const float4*)(Qb + (size_t)(q0 + row) * DQ + c4);
    }
    const int m1 = (w & 7) * 16, n1 = (w >> 3) * 32;   // gemm1 warp tile
    const int wr = (w & 3) * 32, wc = (w >> 2) * 32;   // gemm2 warp tile
    float acc[2][4][4] = {};

    for (int pc = 0; pc < 64; pc++) {
        __syncthreads();
        const int p0 = pc * 64;
#pragma unroll
        for (int i = 0; i < 2; i++) {
            int idx = tid + i * 512;
            int row = idx >> 4, c4 = (idx & 15) * 4;
            *(float4*)&Qp_s[row][c4] = *(const float4*)(Qb + (size_t)(p0 + row) * DQ + c4);
        }
#pragma unroll
        for (int i = 0; i < 4; i++) {
            int idx = tid + i * 512;
            int row = idx >> 5, c4 = (idx & 31) * 4;
            float rz = rZb[p0 + row];
            float4 v = *(const float4*)(Fb + (size_t)(p0 + row) * CI + c0 + c4);
            float4 g;
            g.x = to_tf32(v.x * rz); g.y = to_tf32(v.y * rz);
            g.z = to_tf32(v.z * rz); g.w = to_tf32(v.w * rz);
            *(float4*)&G_s[row][c4] = g;
        }
        __syncthreads();
        // gemm1: S[128 x 64] = Qq @ Qp^T (warp: 16 x 32)
        float s[4][4] = {};
#pragma unroll
        for (int kt = 0; kt < 8; kt++) {
            int k0 = kt * 8;
            unsigned a0 = FU(Qq_s[m1 + gid][k0 + t4]), a1 = FU(Qq_s[m1 + gid + 8][k0 + t4]);
            unsigned a2 = FU(Qq_s[m1 + gid][k0 + t4 + 4]), a3 = FU(Qq_s[m1 + gid + 8][k0 + t4 + 4]);
#pragma unroll
            for (int nt = 0; nt < 4; nt++) {
                unsigned b0 = FU(Qp_s[n1 + nt * 8 + gid][k0 + t4]);
                unsigned b1 = FU(Qp_s[n1 + nt * 8 + gid][k0 + t4 + 4]);
                mma8(s[nt], a0, a1, a2, a3, b0, b1);
            }
        }
#pragma unroll
        for (int nt = 0; nt < 4; nt++) {
            int cb = n1 + nt * 8 + 2 * t4;
            E_s[m1 + gid][cb]         = to_tf32(ex2f(s[nt][0]));
            E_s[m1 + gid][cb + 1]     = to_tf32(ex2f(s[nt][1]));
            E_s[m1 + gid + 8][cb]     = to_tf32(ex2f(s[nt][2]));
            E_s[m1 + gid + 8][cb + 1] = to_tf32(ex2f(s[nt][3]));
        }
        __syncthreads();
        // gemm2: acc += E(128x64) @ G(64x128) (warp: 32 x 32)
#pragma unroll
        for (int kt = 0; kt < 8; kt++) {
            int k0 = kt * 8;
            unsigned b0[4], b1[4];
#pragma unroll
            for (int nt = 0; nt < 4; nt++) {
                b0[nt] = FU(G_s[k0 + t4][wc + nt * 8 + gid]);
                b1[nt] = FU(G_s[k0 + t4 + 4][wc + nt * 8 + gid]);
            }
#pragma unroll
            for (int mt = 0; mt < 2; mt++) {
                unsigned a0 = FU(E_s[wr + mt * 16 + gid][k0 + t4]);
                unsigned a1 = FU(E_s[wr + mt * 16 + gid + 8][k0 + t4]);
                unsigned a2 = FU(E_s[wr + mt * 16 + gid][k0 + t4 + 4]);
                unsigned a3 = FU(E_s[wr + mt * 16 + gid + 8][k0 + t4 + 4]);
#pragma unroll
                for (int nt = 0; nt < 4; nt++)
                    mma8(acc[mt][nt], a0, a1, a2, a3, b0[nt], b1[nt]);
            }
        }
    }
    float* ab = g_att + (size_t)n * CI * HW;
#pragma unroll
    for (int mt = 0; mt < 2; mt++)
#pragma unroll
        for (int nt = 0; nt < 4; nt++)
#pragma unroll
            for (int i = 0; i < 2; i++)
#pragma unroll
                for (int j = 0; j < 2; j++) {
                    int q = q0 + wr + mt * 16 + gid + i * 8;
                    int c = c0 + wc + nt * 8 + 2 * t4 + j;
                    ab[(size_t)c * HW + q] = acc[mt][nt][i * 2 + j];
                }
}

// ---------------------------------------------------------------------------
// K4: epilogue. att slab is exactly linear in (r*256+cc) per batch.
// ---------------------------------------------------------------------------
__global__ void k_out(const float* __restrict__ mask, const float* __restrict__ ref,
                      float* __restrict__ out) {
    const int total = NB * HW * (CI / 4);  // 2097152 float4 groups
    const int stride = gridDim.x * blockDim.x;
    for (int g = blockIdx.x * blockDim.x + threadIdx.x; g < total; g += stride) {
        int n = g >> 18;
        int rem = g & 262143;
        int r = rem >> 6;
        int c4 = (rem & 63) << 2;
        float4 a  = *(const float4*)(g_att + (size_t)n * CI * HW + (size_t)r * CI + c4);
        float4 rf = *(const float4*)(ref + ((size_t)n * HW + r) * CI + c4);
        float m = mask[n * HW + r];
        float4 e;
        e.x = m * a.x + (1.f - m) * rf.x;
        e.y = m * a.y + (1.f - m) * rf.y;
        e.z = m * a.z + (1.f - m) * rf.z;
        e.w = m * a.w + (1.f - m) * rf.w;
        size_t ob = ((size_t)n * HW + r) * (2 * CI);
        *(float4*)(out + ob + c4) = e;
        *(float4*)(out + ob + CI + c4) = a;
    }
}

extern "C" void kernel_launch(void* const* d_in, const int* in_sizes, int n_in,
                              void* d_out, int out_size) {
    const float* mask = (const float*)d_in[0];
    const float* F    = (const float*)d_in[1];
    const float* ref  = (const float*)d_in[2];
    const float* W    = (const float*)d_in[3];
    float* out = (float*)d_out;
    (void)in_sizes; (void)n_in; (void)out_size;

    cudaFuncSetAttribute(k_att, cudaFuncAttributeMaxDynamicSharedMemorySize, K3_SMEM);

    k_query<<<dim3(32, 8), 256>>>(F, W);
    k_rowsum<<<dim3(64, 8), 256>>>();
    k_att<<<dim3(32, 2, 8), 512, K3_SMEM>>>(F);
    k_out<<<2048, 256>>>(mask, ref, out);
}

// round 4
// speedup vs baseline: 1.1725x; 1.1725x over previous
#include <cuda_runtime.h>
#include <cstdint>
#include <cstddef>

#define NB 8
#define HW 4096
#define CI 256
#define DQ 64

// scratch (device globals -- no allocation allowed)
__device__ float g_Q[(size_t)NB * HW * DQ];          // tf32-rounded, pre-scaled by sqrt(log2 e)
__device__ float g_E[(size_t)NB * HW * HW];          // E[n][q][p] = tf32(2^(Qq.Qp))  (537 MB)
__device__ float g_Zp[(size_t)NB * 32 * HW];         // partial Z per q-block of 128
__device__ float g_rZ[NB * HW];                      // 1 / softmax row sum
__device__ float g_att[(size_t)NB * CI * HW];        // att in (C, HW)-linear layout per batch

static __device__ __forceinline__ float to_tf32(float x) {
    unsigned r; asm("cvt.rna.tf32.f32 %0, %1;" : "=r"(r) : "f"(x));
    return __uint_as_float(r);
}
static __device__ __forceinline__ float ex2f(float x) {
    float y; asm("ex2.approx.ftz.f32 %0, %1;" : "=f"(y) : "f"(x));
    return y;
}
static __device__ __forceinline__ void mma8(float c[4], unsigned a0, unsigned a1, unsigned a2,
                                            unsigned a3, unsigned b0, unsigned b1) {
    asm volatile(
        "mma.sync.aligned.m16n8k8.row.col.f32.tf32.tf32.f32 "
        "{%0,%1,%2,%3},{%4,%5,%6,%7},{%8,%9},{%0,%1,%2,%3};"
        : "+f"(c[0]), "+f"(c[1]), "+f"(c[2]), "+f"(c[3])
        : "r"(a0), "r"(a1), "r"(a2), "r"(a3), "r"(b0), "r"(b1));
}
#define FU __float_as_uint

// ---------------------------------------------------------------------------
// K1: Q = (F @ W) * sqrt(log2 e), fp32 FMA, tf32-rounded on store.
// ---------------------------------------------------------------------------
__global__ __launch_bounds__(256) void k_query(const float* __restrict__ F,
                                               const float* __restrict__ W) {
    __shared__ float A_s[32][132];
    __shared__ float W_s[32][68];
    const int tid = threadIdx.x;
    const int n = blockIdx.y, p0 = blockIdx.x * 128;
    const int tx = tid & 15, ty = tid >> 4;
    float acc[8][4];
#pragma unroll
    for (int i = 0; i < 8; i++)
#pragma unroll
        for (int j = 0; j < 4; j++) acc[i][j] = 0.f;
    const float* Fb = F + ((size_t)n * HW + p0) * CI;

    for (int kc = 0; kc < 8; kc++) {
        __syncthreads();
#pragma unroll
        for (int i = 0; i < 4; i++) {
            int idx = tid + i * 256;
            int row = idx >> 3, c4 = (idx & 7) * 4;
            float4 v = *(const float4*)(Fb + (size_t)row * CI + kc * 32 + c4);
            A_s[c4 + 0][row] = v.x; A_s[c4 + 1][row] = v.y;
            A_s[c4 + 2][row] = v.z; A_s[c4 + 3][row] = v.w;
        }
#pragma unroll
        for (int i = 0; i < 2; i++) {
            int idx = tid + i * 256;
            int row = idx >> 4, c4 = (idx & 15) * 4;
            *(float4*)&W_s[row][c4] = *(const float4*)(W + (kc * 32 + row) * DQ + c4);
        }
        __syncthreads();
#pragma unroll
        for (int k = 0; k < 32; k++) {
            float4 a0 = *(float4*)&A_s[k][8 * ty];
            float4 a1 = *(float4*)&A_s[k][8 * ty + 4];
            float4 b  = *(float4*)&W_s[k][4 * tx];
            float av[8] = {a0.x, a0.y, a0.z, a0.w, a1.x, a1.y, a1.z, a1.w};
            float bv[4] = {b.x, b.y, b.z, b.w};
#pragma unroll
            for (int i = 0; i < 8; i++)
#pragma unroll
                for (int j = 0; j < 4; j++) acc[i][j] += av[i] * bv[j];
        }
    }
    const float s = 1.2011224087864498f;  // sqrt(log2 e)
#pragma unroll
    for (int i = 0; i < 8; i++) {
        int p = p0 + 8 * ty + i;
        float4 o;
        o.x = to_tf32(acc[i][0] * s); o.y = to_tf32(acc[i][1] * s);
        o.z = to_tf32(acc[i][2] * s); o.w = to_tf32(acc[i][3] * s);
        *(float4*)(g_Q + ((size_t)n * HW + p) * DQ + 4 * tx) = o;
    }
}

// ---------------------------------------------------------------------------
// K2: E[q,p] = tf32(2^(Qq.Qp)) for one 128q x 128p tile + partial column sums.
// 512 threads, 16 warps in 4(m=q) x 4(n=p), warp tile 32x32.
// ---------------------------------------------------------------------------
#define K2_QQ 0
#define K2_QP (128 * 68)
#define K2_E  (2 * 128 * 68)
#define K2_ZR (2 * 128 * 68 + 128 * 132)
#define K2_SMEM ((2 * 128 * 68 + 128 * 132 + 4 * 128) * 4)

__global__ __launch_bounds__(512, 1) void k_escore() {
    extern __shared__ float sm[];
    float(*Qq_s)[68]  = (float(*)[68])(sm + K2_QQ);
    float(*Qp_s)[68]  = (float(*)[68])(sm + K2_QP);
    float(*E_s)[132]  = (float(*)[132])(sm + K2_E);
    float(*Zr)[128]   = (float(*)[128])(sm + K2_ZR);
    const int tid = threadIdx.x, w = tid >> 5, lane = tid & 31;
    const int gid = lane >> 2, t4 = lane & 3;
    const int qb = blockIdx.x, pb = blockIdx.y, n = blockIdx.z;
    const int q0 = qb * 128, p0 = pb * 128;
    const int m0 = (w & 3) * 32, n0 = (w >> 2) * 32;
    const float* Qb = g_Q + (size_t)n * HW * DQ;

#pragma unroll
    for (int i = 0; i < 4; i++) {
        int idx = tid + i * 512;
        int row = idx >> 4, c4 = (idx & 15) * 4;
        *(float4*)&Qq_s[row][c4] = *(const float4*)(Qb + (size_t)(q0 + row) * DQ + c4);
        *(float4*)&Qp_s[row][c4] = *(const float4*)(Qb + (size_t)(p0 + row) * DQ + c4);
    }
    __syncthreads();

    float acc[2][4][4] = {};
#pragma unroll
    for (int kt = 0; kt < 8; kt++) {
        int k0 = kt * 8;
        unsigned b0[4], b1[4];
#pragma unroll
        for (int nt = 0; nt < 4; nt++) {
            b0[nt] = FU(Qp_s[n0 + nt * 8 + gid][k0 + t4]);
            b1[nt] = FU(Qp_s[n0 + nt * 8 + gid][k0 + t4 + 4]);
        }
#pragma unroll
        for (int mt = 0; mt < 2; mt++) {
            int m = m0 + mt * 16;
            unsigned a0 = FU(Qq_s[m + gid][k0 + t4]),     a1 = FU(Qq_s[m + gid + 8][k0 + t4]);
            unsigned a2 = FU(Qq_s[m + gid][k0 + t4 + 4]), a3 = FU(Qq_s[m + gid + 8][k0 + t4 + 4]);
#pragma unroll
            for (int nt = 0; nt < 4; nt++)
                mma8(acc[mt][nt], a0, a1, a2, a3, b0[nt], b1[nt]);
        }
    }
    // exp -> E_s (tf32-rounded; gemm2 and Z both consume these exact values)
#pragma unroll
    for (int mt = 0; mt < 2; mt++)
#pragma unroll
        for (int nt = 0; nt < 4; nt++) {
            int r = m0 + mt * 16 + gid, cb = n0 + nt * 8 + 2 * t4;
            E_s[r][cb]         = to_tf32(ex2f(acc[mt][nt][0]));
            E_s[r][cb + 1]     = to_tf32(ex2f(acc[mt][nt][1]));
            E_s[r + 8][cb]     = to_tf32(ex2f(acc[mt][nt][2]));
            E_s[r + 8][cb + 1] = to_tf32(ex2f(acc[mt][nt][3]));
        }
    __syncthreads();

    // partial Z: column sums over this block's 128 q-rows (fixed order)
    {
        int col = tid & 127, qp = tid >> 7;
        float zs = 0.f;
#pragma unroll 8
        for (int r = qp * 32; r < qp * 32 + 32; r++) zs += E_s[r][col];
        Zr[qp][col] = zs;
    }
    // store E tile, q-major (coalesced float4)
    float* Eb = g_E + (size_t)n * HW * HW + (size_t)q0 * HW + p0;
#pragma unroll
    for (int i = 0; i < 8; i++) {
        int idx = tid + i * 512;
        int row = idx >> 5, c4 = (idx & 31) * 4;
        *(float4*)(Eb + (size_t)row * HW + c4) = *(float4*)&E_s[row][c4];
    }
    __syncthreads();
    if (tid < 128) {
        float z = Zr[0][tid] + Zr[1][tid] + Zr[2][tid] + Zr[3][tid];
        g_Zp[((size_t)n * 32 + qb) * HW + p0 + tid] = z;
    }
}

// ---------------------------------------------------------------------------
// K2b: rZ[p] = 1 / sum over 32 q-block partials (fixed order).
// ---------------------------------------------------------------------------
__global__ void k_zred() {
    int p = blockIdx.x * 256 + threadIdx.x;
    int n = blockIdx.y;
    float z = 0.f;
#pragma unroll
    for (int qb = 0; qb < 32; qb++) z += g_Zp[((size_t)n * 32 + qb) * HW + p];
    g_rZ[n * HW + p] = 1.f / z;
}

// ---------------------------------------------------------------------------
// K3: att[q,c] = sum_p E[q,p] * (F[p,c] * rZ[p]).  Tile 128q x 256c (full C),
// p streamed in 128s.  512 threads, 16 warps in 4(q) x 4(c), warp 32q x 64c.
// ---------------------------------------------------------------------------
#define K3_E 0
#define K3_G (128 * 132)
#define K3_SMEM ((128 * 132 + 128 * 264) * 4)

__global__ __launch_bounds__(512, 1) void k_att2(const float* __restrict__ F) {
    extern __shared__ float sm[];
    float(*E_s)[132] = (float(*)[132])(sm + K3_E);
    float(*G_s)[264] = (float(*)[264])(sm + K3_G);
    const int tid = threadIdx.x, w = tid >> 5, lane = tid & 31;
    const int gid = lane >> 2, t4 = lane & 3;
    const int q0 = blockIdx.x * 128, n = blockIdx.y;
    const int wr = (w & 3) * 32, wc = (w >> 2) * 64;
    const float* Eb = F ? g_E + (size_t)n * HW * HW + (size_t)q0 * HW : nullptr;
    const float* Fb = F + (size_t)n * HW * CI;
    const float* rZb = g_rZ + n * HW;

    float acc[2][8][4] = {};
    for (int pc = 0; pc < 32; pc++) {
        const int p0 = pc * 128;
        __syncthreads();
#pragma unroll
        for (int i = 0; i < 8; i++) {
            int idx = tid + i * 512;
            int row = idx >> 5, c4 = (idx & 31) * 4;
            *(float4*)&E_s[row][c4] = *(const float4*)(Eb + (size_t)row * HW + p0 + c4);
        }
#pragma unroll
        for (int i = 0; i < 16; i++) {
            int idx = tid + i * 512;
            int row = idx >> 6, c4 = (idx & 63) * 4;
            float rz = rZb[p0 + row];
            float4 v = *(const float4*)(Fb + (size_t)(p0 + row) * CI + c4);
            float4 g;
            g.x = to_tf32(v.x * rz); g.y = to_tf32(v.y * rz);
            g.z = to_tf32(v.z * rz); g.w = to_tf32(v.w * rz);
            *(float4*)&G_s[row][c4] = g;
        }
        __syncthreads();
#pragma unroll
        for (int kt = 0; kt < 16; kt++) {
            int k0 = kt * 8;
            unsigned b0[8], b1[8];
#pragma unroll
            for (int nt = 0; nt < 8; nt++) {
                b0[nt] = FU(G_s[k0 + t4][wc + nt * 8 + gid]);
                b1[nt] = FU(G_s[k0 + t4 + 4][wc + nt * 8 + gid]);
            }
#pragma unroll
            for (int mt = 0; mt < 2; mt++) {
                int m = wr + mt * 16;
                unsigned a0 = FU(E_s[m + gid][k0 + t4]),     a1 = FU(E_s[m + gid + 8][k0 + t4]);
                unsigned a2 = FU(E_s[m + gid][k0 + t4 + 4]), a3 = FU(E_s[m + gid + 8][k0 + t4 + 4]);
#pragma unroll
                for (int nt = 0; nt < 8; nt++)
                    mma8(acc[mt][nt], a0, a1, a2, a3, b0[nt], b1[nt]);
            }
        }
    }
    float* ab = g_att + (size_t)n * CI * HW;
#pragma unroll
    for (int mt = 0; mt < 2; mt++)
#pragma unroll
        for (int nt = 0; nt < 8; nt++)
#pragma unroll
            for (int i = 0; i < 2; i++)
#pragma unroll
                for (int j = 0; j < 2; j++) {
                    int q = q0 + wr + mt * 16 + gid + i * 8;
                    int c = wc + nt * 8 + 2 * t4 + j;
                    ab[(size_t)c * HW + q] = acc[mt][nt][i * 2 + j];
                }
}

// ---------------------------------------------------------------------------
// K4: epilogue.  att slab is exactly linear in (r*256+cc) per batch.
// ---------------------------------------------------------------------------
__global__ void k_out(const float* __restrict__ mask, const float* __restrict__ ref,
                      float* __restrict__ out) {
    const int total = NB * HW * (CI / 4);
    const int stride = gridDim.x * blockDim.x;
    for (int g = blockIdx.x * blockDim.x + threadIdx.x; g < total; g += stride) {
        int n = g >> 18;
        int rem = g & 262143;
        int r = rem >> 6;
        int c4 = (rem & 63) << 2;
        float4 a  = *(const float4*)(g_att + (size_t)n * CI * HW + (size_t)r * CI + c4);
        float4 rf = *(const float4*)(ref + ((size_t)n * HW + r) * CI + c4);
        float m = mask[n * HW + r];
        float4 e;
        e.x = m * a.x + (1.f - m) * rf.x;
        e.y = m * a.y + (1.f - m) * rf.y;
        e.z = m * a.z + (1.f - m) * rf.z;
        e.w = m * a.w + (1.f - m) * rf.w;
        size_t ob = ((size_t)n * HW + r) * (2 * CI);
        *(float4*)(out + ob + c4) = e;
        *(float4*)(out + ob + CI + c4) = a;
    }
}

extern "C" void kernel_launch(void* const* d_in, const int* in_sizes, int n_in,
                              void* d_out, int out_size) {
    const float* mask = (const float*)d_in[0];
    const float* F    = (const float*)d_in[1];
    const float* ref  = (const float*)d_in[2];
    const float* W    = (const float*)d_in[3];
    float* out = (float*)d_out;
    (void)in_sizes; (void)n_in; (void)out_size;

    cudaFuncSetAttribute(k_escore, cudaFuncAttributeMaxDynamicSharedMemorySize, K2_SMEM);
    cudaFuncSetAttribute(k_att2,   cudaFuncAttributeMaxDynamicSharedMemorySize, K3_SMEM);

    k_query<<<dim3(32, 8), 256>>>(F, W);
    k_escore<<<dim3(32, 32, 8), 512, K2_SMEM>>>();
    k_zred<<<dim3(16, 8), 256>>>();
    k_att2<<<dim3(32, 8), 512, K3_SMEM>>>(F);
    k_out<<<2048, 256>>>(mask, ref, out);
}

// round 7
// speedup vs baseline: 1.9052x; 1.6249x over previous
#include <cuda_runtime.h>
#include <cuda_fp16.h>
#include <cstdint>
#include <cstddef>

#define NB 8
#define HW 4096
#define CI 256
#define DQ 64

// scratch (device globals -- no allocation allowed)
__device__ float  g_Q[(size_t)NB * HW * DQ];      // tf32-rounded, pre-scaled by sqrt(log2 e)
__device__ __half g_Eh[(size_t)NB * HW * HW];     // Eh[n][q][p] = half(2^(S - m[p] + 12))
__device__ __half g_Ft[(size_t)NB * CI * HW];     // F^T in fp16: Ft[n][c][p]
__device__ float  g_Zp[(size_t)NB * 32 * HW];     // partial Z per q-block of 128
__device__ float  g_rZ[NB * HW];                  // 1 / sum_q Eh[q,p]
__device__ float  g_rn[NB * HW];                  // row norms of Q (log2-scaled space)
__device__ float  g_Mp[NB * 32];                  // per-block partial max norms
__device__ float  g_M[NB];                        // max row norm per batch
__device__ float  g_att[(size_t)NB * CI * HW];    // att in (C, HW)-linear layout per batch

static __device__ __forceinline__ float to_tf32(float x) {
    unsigned r; asm("cvt.rna.tf32.f32 %0, %1;" : "=r"(r) : "f"(x));
    return __uint_as_float(r);
}
static __device__ __forceinline__ float ex2f(float x) {
    float y; asm("ex2.approx.ftz.f32 %0, %1;" : "=f"(y) : "f"(x));
    return y;
}
static __device__ __forceinline__ void mma8(float c[4], unsigned a0, unsigned a1, unsigned a2,
                                            unsigned a3, unsigned b0, unsigned b1) {
    asm volatile(
        "mma.sync.aligned.m16n8k8.row.col.f32.tf32.tf32.f32 "
        "{%0,%1,%2,%3},{%4,%5,%6,%7},{%8,%9},{%0,%1,%2,%3};"
        : "+f"(c[0]), "+f"(c[1]), "+f"(c[2]), "+f"(c[3])
        : "r"(a0), "r"(a1), "r"(a2), "r"(a3), "r"(b0), "r"(b1));
}
static __device__ __forceinline__ void mma16h(float c[4], unsigned a0, unsigned a1, unsigned a2,
                                              unsigned a3, unsigned b0, unsigned b1) {
    asm volatile(
        "mma.sync.aligned.m16n8k16.row.col.f32.f16.f16.f32 "
        "{%0,%1,%2,%3},{%4,%5,%6,%7},{%8,%9},{%0,%1,%2,%3};"
        : "+f"(c[0]), "+f"(c[1]), "+f"(c[2]), "+f"(c[3])
        : "r"(a0), "r"(a1), "r"(a2), "r"(a3), "r"(b0), "r"(b1));
}
#define FU __float_as_uint

// ---------------------------------------------------------------------------
// K1: Q = (F @ W) * sqrt(log2 e), fp32 FMA, tf32-rounded on store.
// ---------------------------------------------------------------------------
__global__ __launch_bounds__(256) void k_query(const float* __restrict__ F,
                                               const float* __restrict__ W) {
    __shared__ float A_s[32][132];
    __shared__ float W_s[32][68];
    const int tid = threadIdx.x;
    const int n = blockIdx.y, p0 = blockIdx.x * 128;
    const int tx = tid & 15, ty = tid >> 4;
    float acc[8][4];
#pragma unroll
    for (int i = 0; i < 8; i++)
#pragma unroll
        for (int j = 0; j < 4; j++) acc[i][j] = 0.f;
    const float* Fb = F + ((size_t)n * HW + p0) * CI;

    for (int kc = 0; kc < 8; kc++) {
        __syncthreads();
#pragma unroll
        for (int i = 0; i < 4; i++) {
            int idx = tid + i * 256;
            int row = idx >> 3, c4 = (idx & 7) * 4;
            float4 v = *(const float4*)(Fb + (size_t)row * CI + kc * 32 + c4);
            A_s[c4 + 0][row] = v.x; A_s[c4 + 1][row] = v.y;
            A_s[c4 + 2][row] = v.z; A_s[c4 + 3][row] = v.w;
        }
#pragma unroll
        for (int i = 0; i < 2; i++) {
            int idx = tid + i * 256;
            int row = idx >> 4, c4 = (idx & 15) * 4;
            *(float4*)&W_s[row][c4] = *(const float4*)(W + (kc * 32 + row) * DQ + c4);
        }
        __syncthreads();
#pragma unroll
        for (int k = 0; k < 32; k++) {
            float4 a0 = *(float4*)&A_s[k][8 * ty];
            float4 a1 = *(float4*)&A_s[k][8 * ty + 4];
            float4 b  = *(float4*)&W_s[k][4 * tx];
            float av[8] = {a0.x, a0.y, a0.z, a0.w, a1.x, a1.y, a1.z, a1.w};
            float bv[4] = {b.x, b.y, b.z, b.w};
#pragma unroll
            for (int i = 0; i < 8; i++)
#pragma unroll
                for (int j = 0; j < 4; j++) acc[i][j] += av[i] * bv[j];
        }
    }
    const float s = 1.2011224087864498f;  // sqrt(log2 e)
#pragma unroll
    for (int i = 0; i < 8; i++) {
        int p = p0 + 8 * ty + i;
        float4 o;
        o.x = to_tf32(acc[i][0] * s); o.y = to_tf32(acc[i][1] * s);
        o.z = to_tf32(acc[i][2] * s); o.w = to_tf32(acc[i][3] * s);
        *(float4*)(g_Q + ((size_t)n * HW + p) * DQ + 4 * tx) = o;
    }
}

// ---------------------------------------------------------------------------
// K1b: row norms of Q + per-block max.  128 rows/block, 1 thread per row.
// ---------------------------------------------------------------------------
__global__ __launch_bounds__(128) void k_norm1() {
    __shared__ float mx[128];
    const int n = blockIdx.y, p = blockIdx.x * 128 + threadIdx.x;
    const float* q = g_Q + (size_t)(n * HW + p) * DQ;
    float s = 0.f;
#pragma unroll
    for (int i = 0; i < 16; i++) {
        float4 v = *(const float4*)(q + i * 4);
        s += v.x * v.x + v.y * v.y + v.z * v.z + v.w * v.w;
    }
    float rn = sqrtf(s);
    g_rn[n * HW + p] = rn;
    mx[threadIdx.x] = rn;
    __syncthreads();
    for (int d = 64; d > 0; d >>= 1) {
        if (threadIdx.x < d) mx[threadIdx.x] = fmaxf(mx[threadIdx.x], mx[threadIdx.x + d]);
        __syncthreads();
    }
    if (threadIdx.x == 0) g_Mp[n * 32 + blockIdx.x] = mx[0];
}
__global__ void k_norm2() {
    const int n = blockIdx.x;
    float m = g_Mp[n * 32 + threadIdx.x];
#pragma unroll
    for (int d = 16; d > 0; d >>= 1) m = fmaxf(m, __shfl_xor_sync(0xffffffffu, m, d));
    if (threadIdx.x == 0) g_M[n] = m;
}

// ---------------------------------------------------------------------------
// K2: Eh[q,p] = half(2^(S[q,p] - rn[p]*M + 12)) per 128x128 tile + partial
// column sums.  Z sums the SAME half-rounded values -> weights exactly E/sum.
// ---------------------------------------------------------------------------
#define K2_QQ 0
#define K2_QP (128 * 68)
#define K2_E  (2 * 128 * 68)
#define K2_ZR (2 * 128 * 68 + 128 * 132)
#define K2_MS (2 * 128 * 68 + 128 * 132 + 4 * 128)
#define K2_SMEM ((2 * 128 * 68 + 128 * 132 + 4 * 128 + 128) * 4)

__global__ __launch_bounds__(512, 1) void k_escore() {
    extern __shared__ float sm[];
    float(*Qq_s)[68]  = (float(*)[68])(sm + K2_QQ);
    float(*Qp_s)[68]  = (float(*)[68])(sm + K2_QP);
    float(*E_s)[132]  = (float(*)[132])(sm + K2_E);
    float(*Zr)[128]   = (float(*)[128])(sm + K2_ZR);
    float* ms         = sm + K2_MS;
    const int tid = threadIdx.x, w = tid >> 5, lane = tid & 31;
    const int gid = lane >> 2, t4 = lane & 3;
    const int qb = blockIdx.x, pb = blockIdx.y, n = blockIdx.z;
    const int q0 = qb * 128, p0 = pb * 128;
    const int m0 = (w & 3) * 32, n0 = (w >> 2) * 32;
    const float* Qb = g_Q + (size_t)n * HW * DQ;
    const float M = g_M[n];

#pragma unroll
    for (int i = 0; i < 4; i++) {
        int idx = tid + i * 512;
        int row = idx >> 4, c4 = (idx & 15) * 4;
        *(float4*)&Qq_s[row][c4] = *(const float4*)(Qb + (size_t)(q0 + row) * DQ + c4);
        *(float4*)&Qp_s[row][c4] = *(const float4*)(Qb + (size_t)(p0 + row) * DQ + c4);
    }
    if (tid < 128) ms[tid] = 12.f - g_rn[n * HW + p0 + tid] * M;
    __syncthreads();

    float acc[2][4][4] = {};
#pragma unroll
    for (int kt = 0; kt < 8; kt++) {
        int k0 = kt * 8;
        unsigned b0[4], b1[4];
#pragma unroll
        for (int nt = 0; nt < 4; nt++) {
            b0[nt] = FU(Qp_s[n0 + nt * 8 + gid][k0 + t4]);
            b1[nt] = FU(Qp_s[n0 + nt * 8 + gid][k0 + t4 + 4]);
        }
#pragma unroll
        for (int mt = 0; mt < 2; mt++) {
            int m = m0 + mt * 16;
            unsigned a0 = FU(Qq_s[m + gid][k0 + t4]),     a1 = FU(Qq_s[m + gid + 8][k0 + t4]);
            unsigned a2 = FU(Qq_s[m + gid][k0 + t4 + 4]), a3 = FU(Qq_s[m + gid + 8][k0 + t4 + 4]);
#pragma unroll
            for (int nt = 0; nt < 4; nt++)
                mma8(acc[mt][nt], a0, a1, a2, a3, b0[nt], b1[nt]);
        }
    }
    // exp(S + shift[p]) -> round through fp16 -> E_s
#pragma unroll
    for (int mt = 0; mt < 2; mt++)
#pragma unroll
        for (int nt = 0; nt < 4; nt++) {
            int r = m0 + mt * 16 + gid, cb = n0 + nt * 8 + 2 * t4;
            float s0 = ms[cb], s1 = ms[cb + 1];
            E_s[r][cb]         = __half2float(__float2half(ex2f(acc[mt][nt][0] + s0)));
            E_s[r][cb + 1]     = __half2float(__float2half(ex2f(acc[mt][nt][1] + s1)));
            E_s[r + 8][cb]     = __half2float(__float2half(ex2f(acc[mt][nt][2] + s0)));
            E_s[r + 8][cb + 1] = __half2float(__float2half(ex2f(acc[mt][nt][3] + s1)));
        }
    __syncthreads();
    {
        int col = tid & 127, qp = tid >> 7;
        float zs = 0.f;
#pragma unroll 8
        for (int r = qp * 32; r < qp * 32 + 32; r++) zs += E_s[r][col];
        Zr[qp][col] = zs;
    }
    __half* Eb = g_Eh + (size_t)n * HW * HW + (size_t)q0 * HW + p0;
#pragma unroll
    for (int i = 0; i < 8; i++) {
        int idx = tid + i * 512;
        int row = idx >> 5, c4 = (idx & 31) * 4;
        float4 v = *(float4*)&E_s[row][c4];
        union { __half2 h[2]; uint2 u; } cv;
        cv.h[0] = __floats2half2_rn(v.x, v.y);
        cv.h[1] = __floats2half2_rn(v.z, v.w);
        *(uint2*)(Eb + (size_t)row * HW + c4) = cv.u;
    }
    __syncthreads();
    if (tid < 128) {
        float z = Zr[0][tid] + Zr[1][tid] + Zr[2][tid] + Zr[3][tid];
        g_Zp[((size_t)n * 32 + qb) * HW + p0 + tid] = z;
    }
}

// ---------------------------------------------------------------------------
// K2b: rZ[p] = 1 / sum over 32 q-block partials (fixed order).
// ---------------------------------------------------------------------------
__global__ void k_zred() {
    int p = blockIdx.x * 256 + threadIdx.x;
    int n = blockIdx.y;
    float z = 0.f;
#pragma unroll
    for (int qb = 0; qb < 32; qb++) z += g_Zp[((size_t)n * 32 + qb) * HW + p];
    g_rZ[n * HW + p] = 1.f / z;
}

// ---------------------------------------------------------------------------
// K2c: Ft[c][p] = half(F[p][c])  (transpose, 32x32 tiles)
// ---------------------------------------------------------------------------
__global__ __launch_bounds__(256) void k_ft(const float* __restrict__ F) {
    __shared__ float t[32][33];
    const int n = blockIdx.z, c0 = blockIdx.y * 32, p0 = blockIdx.x * 32;
    const int tx = threadIdx.x & 7, ty = threadIdx.x >> 3;
    const float* Fb = F + ((size_t)n * HW + p0) * CI;
    float4 v = *(const float4*)(Fb + (size_t)ty * CI + c0 + tx * 4);
    t[ty][tx * 4 + 0] = v.x; t[ty][tx * 4 + 1] = v.y;
    t[ty][tx * 4 + 2] = v.z; t[ty][tx * 4 + 3] = v.w;
    __syncthreads();
    const int cl = threadIdx.x >> 3, p4 = (threadIdx.x & 7) * 4;
    union { __half2 h[2]; uint2 u; } cv;
    cv.h[0] = __floats2half2_rn(t[p4 + 0][cl], t[p4 + 1][cl]);
    cv.h[1] = __floats2half2_rn(t[p4 + 2][cl], t[p4 + 3][cl]);
    *(uint2*)(g_Ft + ((size_t)n * CI + c0 + cl) * HW + p0 + p4) = cv.u;
}

// ---------------------------------------------------------------------------
// K3: fp16 mma m16n8k16.  att[q,c] = sum_p (Eh[q,p]*rZ[p]) * Ft[c,p].
// Block tile 128q x 128c, p chunk 128, 512 threads, 16 warps (4q x 4c),
// warp tile 32x32 (32 accum regs) -> <=64 regs -> 2 CTAs/SM.
// ---------------------------------------------------------------------------
#define K3PAD 136
#define K3_SMEMH ((128 * K3PAD * 2) * 2)  // E_s + F_s, halves

__global__ __launch_bounds__(512, 2) void k_attf() {
    extern __shared__ __half smh[];
    __half* Es = smh;
    __half* Fs = smh + 128 * K3PAD;
    const int tid = threadIdx.x, w = tid >> 5, lane = tid & 31;
    const int gid = lane >> 2, t4 = lane & 3;
    const int q0 = blockIdx.x * 128, c0 = blockIdx.y * 128, n = blockIdx.z;
    const int wq = (w & 3) * 32, wc = (w >> 2) * 32;
    const __half* Ebase = g_Eh + (size_t)n * HW * HW + (size_t)q0 * HW;
    const __half* Fbase = g_Ft + ((size_t)n * CI + c0) * HW;
    const float* rZb = g_rZ + n * HW;

    const int lrow = tid >> 4, lch = tid & 15;
    float acc[2][4][4] = {};

    for (int pc = 0; pc < 32; pc++) {
        const int p0 = pc * 128;
        __syncthreads();
#pragma unroll
        for (int i = 0; i < 4; i++) {
            int row = lrow + i * 32;
            uint4 ev = *(const uint4*)(Ebase + (size_t)row * HW + p0 + lch * 8);
            const float* rp = rZb + p0 + lch * 8;
            float4 r0 = *(const float4*)rp, r1 = *(const float4*)(rp + 4);
            union { uint4 u; __half2 h[4]; } in, ov;
            in.u = ev;
            float2 f;
            f = __half22float2(in.h[0]); f.x *= r0.x; f.y *= r0.y; ov.h[0] = __float22half2_rn(f);
            f = __half22float2(in.h[1]); f.x *= r0.z; f.y *= r0.w; ov.h[1] = __float22half2_rn(f);
            f = __half22float2(in.h[2]); f.x *= r1.x; f.y *= r1.y; ov.h[2] = __float22half2_rn(f);
            f = __half22float2(in.h[3]); f.x *= r1.z; f.y *= r1.w; ov.h[3] = __float22half2_rn(f);
            *(uint4*)(Es + row * K3PAD + lch * 8) = ov.u;
            *(uint4*)(Fs + row * K3PAD + lch * 8) =
                *(const uint4*)(Fbase + (size_t)row * HW + p0 + lch * 8);
        }
        __syncthreads();
#pragma unroll
        for (int kt = 0; kt < 8; kt++) {
            const int k0 = kt * 16 + 2 * t4;
            unsigned b0[4], b1[4];
#pragma unroll
            for (int nt = 0; nt < 4; nt++) {
                const __half* bp = Fs + (wc + nt * 8 + gid) * K3PAD + k0;
                b0[nt] = *(const unsigned*)bp;
                b1[nt] = *(const unsigned*)(bp + 8);
            }
#pragma unroll
            for (int mt = 0; mt < 2; mt++) {
                const __half* ap = Es + (wq + mt * 16 + gid) * K3PAD + k0;
                unsigned a0 = *(const unsigned*)ap;
                unsigned a2 = *(const unsigned*)(ap + 8);
                const __half* ap8 = ap + 8 * K3PAD;
                unsigned a1 = *(const unsigned*)ap8;
                unsigned a3 = *(const unsigned*)(ap8 + 8);
#pragma unroll
                for (int nt = 0; nt < 4; nt++)
                    mma16h(acc[mt][nt], a0, a1, a2, a3, b0[nt], b1[nt]);
            }
        }
    }
    float* ab = g_att + (size_t)n * CI * HW;
#pragma unroll
    for (int mt = 0; mt < 2; mt++)
#pragma unroll
        for (int nt = 0; nt < 4; nt++)
#pragma unroll
            for (int i = 0; i < 2; i++)
#pragma unroll
                for (int j = 0; j < 2; j++) {
                    int q = q0 + wq + mt * 16 + gid + i * 8;
                    int c = c0 + wc + nt * 8 + 2 * t4 + j;
                    ab[(size_t)c * HW + q] = acc[mt][nt][i * 2 + j];
                }
}

// ---------------------------------------------------------------------------
// K4: epilogue.  att slab is exactly linear in (r*256+cc) per batch.
// ---------------------------------------------------------------------------
__global__ void k_out(const float* __restrict__ mask, const float* __restrict__ ref,
                      float* __restrict__ out) {
    const int total = NB * HW * (CI / 4);
    const int stride = gridDim.x * blockDim.x;
    for (int g = blockIdx.x * blockDim.x + threadIdx.x; g < total; g += stride) {
        int n = g >> 18;
        int rem = g & 262143;
        int r = rem >> 6;
        int c4 = (rem & 63) << 2;
        float4 a  = *(const float4*)(g_att + (size_t)n * CI * HW + (size_t)r * CI + c4);
        float4 rf = *(const float4*)(ref + ((size_t)n * HW + r) * CI + c4);
        float m = mask[n * HW + r];
        float4 e;
        e.x = m * a.x + (1.f - m) * rf.x;
        e.y = m * a.y + (1.f - m) * rf.y;
        e.z = m * a.z + (1.f - m) * rf.z;
        e.w = m * a.w + (1.f - m) * rf.w;
        size_t ob = ((size_t)n * HW + r) * (2 * CI);
        *(float4*)(out + ob + c4) = e;
        *(float4*)(out + ob + CI + c4) = a;
    }
}

extern "C" void kernel_launch(void* const* d_in, const int* in_sizes, int n_in,
                              void* d_out, int out_size) {
    const float* mask = (const float*)d_in[0];
    const float* F    = (const float*)d_in[1];
    const float* ref  = (const float*)d_in[2];
    const float* W    = (const float*)d_in[3];
    float* out = (float*)d_out;
    (void)in_sizes; (void)n_in; (void)out_size;

    cudaFuncSetAttribute(k_escore, cudaFuncAttributeMaxDynamicSharedMemorySize, K2_SMEM);
    cudaFuncSetAttribute(k_attf,   cudaFuncAttributeMaxDynamicSharedMemorySize, K3_SMEMH);

    k_query<<<dim3(32, 8), 256>>>(F, W);
    k_norm1<<<dim3(32, 8), 128>>>();
    k_norm2<<<8, 32>>>();
    k_escore<<<dim3(32, 32, 8), 512, K2_SMEM>>>();
    k_zred<<<dim3(16, 8), 256>>>();
    k_ft<<<dim3(128, 8, 8), 256>>>(F);
    k_attf<<<dim3(32, 2, 8), 512, K3_SMEMH>>>();
    k_out<<<2048, 256>>>(mask, ref, out);
}

// round 8
// speedup vs baseline: 2.3028x; 1.2087x over previous
#include <cuda_runtime.h>
#include <cuda_fp16.h>
#include <cstdint>
#include <cstddef>

#define NB 8
#define HW 4096
#define CI 256
#define DQ 64

// scratch (device globals -- no allocation allowed)
__device__ __half g_Qh[(size_t)NB * HW * DQ];     // fp16 Q, pre-scaled by sqrt(log2 e)
__device__ __half g_Eh[(size_t)NB * HW * HW];     // Eh[n][q][p] = half(2^(S - m[p] + 12))
__device__ __half g_Ft[(size_t)NB * CI * HW];     // F^T in fp16: Ft[n][c][p]
__device__ float  g_Zp[(size_t)NB * 32 * HW];     // partial Z per q-block of 128
__device__ float  g_rZ[NB * HW];                  // 1 / sum_q Eh[q,p]
__device__ float  g_rn[NB * HW];                  // row norms of Q (log2-scaled space)
__device__ float  g_Mp[NB * 32];                  // per-block partial max norms
__device__ float  g_M[NB];                        // max row norm per batch
__device__ float  g_att[(size_t)NB * CI * HW];    // att in (C, HW)-linear layout per batch

static __device__ __forceinline__ float ex2f(float x) {
    float y; asm("ex2.approx.ftz.f32 %0, %1;" : "=f"(y) : "f"(x));
    return y;
}
static __device__ __forceinline__ void mma16h(float c[4], unsigned a0, unsigned a1, unsigned a2,
                                              unsigned a3, unsigned b0, unsigned b1) {
    asm volatile(
        "mma.sync.aligned.m16n8k16.row.col.f32.f16.f16.f32 "
        "{%0,%1,%2,%3},{%4,%5,%6,%7},{%8,%9},{%0,%1,%2,%3};"
        : "+f"(c[0]), "+f"(c[1]), "+f"(c[2]), "+f"(c[3])
        : "r"(a0), "r"(a1), "r"(a2), "r"(a3), "r"(b0), "r"(b1));
}
static __device__ __forceinline__ void ldsm4(unsigned r[4], uint32_t a) {
    asm volatile("ldmatrix.sync.aligned.m8n8.x4.shared.b16 {%0,%1,%2,%3}, [%4];"
                 : "=r"(r[0]), "=r"(r[1]), "=r"(r[2]), "=r"(r[3]) : "r"(a));
}
static __device__ __forceinline__ uint32_t smem_u32(const void* p) {
    return (uint32_t)__cvta_generic_to_shared(p);
}

// ---------------------------------------------------------------------------
// K1: Q = (F @ W) * sqrt(log2 e), fp32 FMA, stored fp16.
// ---------------------------------------------------------------------------
__global__ __launch_bounds__(256) void k_query(const float* __restrict__ F,
                                               const float* __restrict__ W) {
    __shared__ float A_s[32][132];
    __shared__ float W_s[32][68];
    const int tid = threadIdx.x;
    const int n = blockIdx.y, p0 = blockIdx.x * 128;
    const int tx = tid & 15, ty = tid >> 4;
    float acc[8][4];
#pragma unroll
    for (int i = 0; i < 8; i++)
#pragma unroll
        for (int j = 0; j < 4; j++) acc[i][j] = 0.f;
    const float* Fb = F + ((size_t)n * HW + p0) * CI;

    for (int kc = 0; kc < 8; kc++) {
        __syncthreads();
#pragma unroll
        for (int i = 0; i < 4; i++) {
            int idx = tid + i * 256;
            int row = idx >> 3, c4 = (idx & 7) * 4;
            float4 v = *(const float4*)(Fb + (size_t)row * CI + kc * 32 + c4);
            A_s[c4 + 0][row] = v.x; A_s[c4 + 1][row] = v.y;
            A_s[c4 + 2][row] = v.z; A_s[c4 + 3][row] = v.w;
        }
#pragma unroll
        for (int i = 0; i < 2; i++) {
            int idx = tid + i * 256;
            int row = idx >> 4, c4 = (idx & 15) * 4;
            *(float4*)&W_s[row][c4] = *(const float4*)(W + (kc * 32 + row) * DQ + c4);
        }
        __syncthreads();
#pragma unroll
        for (int k = 0; k < 32; k++) {
            float4 a0 = *(float4*)&A_s[k][8 * ty];
            float4 a1 = *(float4*)&A_s[k][8 * ty + 4];
            float4 b  = *(float4*)&W_s[k][4 * tx];
            float av[8] = {a0.x, a0.y, a0.z, a0.w, a1.x, a1.y, a1.z, a1.w};
            float bv[4] = {b.x, b.y, b.z, b.w};
#pragma unroll
            for (int i = 0; i < 8; i++)
#pragma unroll
                for (int j = 0; j < 4; j++) acc[i][j] += av[i] * bv[j];
        }
    }
    const float s = 1.2011224087864498f;  // sqrt(log2 e)
#pragma unroll
    for (int i = 0; i < 8; i++) {
        int p = p0 + 8 * ty + i;
        union { __half2 h[2]; uint2 u; } cv;
        cv.h[0] = __floats2half2_rn(acc[i][0] * s, acc[i][1] * s);
        cv.h[1] = __floats2half2_rn(acc[i][2] * s, acc[i][3] * s);
        *(uint2*)(g_Qh + ((size_t)n * HW + p) * DQ + 4 * tx) = cv.u;
    }
}

// ---------------------------------------------------------------------------
// K1b: row norms of Q (from the stored halves) + per-block max.
// ---------------------------------------------------------------------------
__global__ __launch_bounds__(128) void k_norm1() {
    __shared__ float mx[128];
    const int n = blockIdx.y, p = blockIdx.x * 128 + threadIdx.x;
    const __half2* q = (const __half2*)(g_Qh + (size_t)(n * HW + p) * DQ);
    float s = 0.f;
#pragma unroll
    for (int i = 0; i < 32; i++) {
        float2 f = __half22float2(q[i]);
        s += f.x * f.x + f.y * f.y;
    }
    float rn = sqrtf(s);
    g_rn[n * HW + p] = rn;
    mx[threadIdx.x] = rn;
    __syncthreads();
    for (int d = 64; d > 0; d >>= 1) {
        if (threadIdx.x < d) mx[threadIdx.x] = fmaxf(mx[threadIdx.x], mx[threadIdx.x + d]);
        __syncthreads();
    }
    if (threadIdx.x == 0) g_Mp[n * 32 + blockIdx.x] = mx[0];
}
__global__ void k_norm2() {
    const int n = blockIdx.x;
    float m = g_Mp[n * 32 + threadIdx.x];
#pragma unroll
    for (int d = 16; d > 0; d >>= 1) m = fmaxf(m, __shfl_xor_sync(0xffffffffu, m, d));
    if (threadIdx.x == 0) g_M[n] = m;
}

// ---------------------------------------------------------------------------
// K2: Eh[q,p] = half(2^(S - rn[p]*M + 12)) per 128x128 tile, fp16 mma +
// ldmatrix feed, direct half2 global stores, Z summed from the same halves
// via shfl reduction (numerator/denominator exactly consistent).
// ---------------------------------------------------------------------------
__global__ __launch_bounds__(512, 2) void k_escore() {
    __shared__ __half Qq[128][72];
    __shared__ __half Qp[128][72];
    __shared__ float Zp[4][128];
    __shared__ float ms[128];
    const int tid = threadIdx.x, w = tid >> 5, lane = tid & 31;
    const int gid = lane >> 2, t4 = lane & 3;
    const int qb = blockIdx.x, pb = blockIdx.y, n = blockIdx.z;
    const int q0 = qb * 128, p0 = pb * 128;
    const int m0 = (w & 3) * 32, n0 = (w >> 2) * 32;
    const __half* Qh = g_Qh + (size_t)n * HW * DQ;

#pragma unroll
    for (int i = 0; i < 2; i++) {
        int idx = tid + i * 512;
        int row = idx >> 3, ch = (idx & 7) * 8;
        *(uint4*)&Qq[row][ch] = *(const uint4*)(Qh + (size_t)(q0 + row) * DQ + ch);
        *(uint4*)&Qp[row][ch] = *(const uint4*)(Qh + (size_t)(p0 + row) * DQ + ch);
    }
    if (tid < 128) ms[tid] = 12.f - g_rn[n * HW + p0 + tid] * g_M[n];
    __syncthreads();

    const int l7 = lane & 7, lb3 = (lane >> 3) & 1, lb4 = lane >> 4;
    uint32_t aAddr[2], bAddr[2];
#pragma unroll
    for (int mt = 0; mt < 2; mt++)
        aAddr[mt] = smem_u32(&Qq[m0 + mt * 16 + l7 + lb3 * 8][lb4 * 8]);
#pragma unroll
    for (int ntp = 0; ntp < 2; ntp++)
        bAddr[ntp] = smem_u32(&Qp[n0 + ntp * 16 + l7 + lb4 * 8][lb3 * 8]);

    float acc[2][4][4] = {};
#pragma unroll
    for (int kt = 0; kt < 4; kt++) {
        unsigned a[2][4], b[2][4];
        ldsm4(a[0], aAddr[0] + kt * 32);
        ldsm4(a[1], aAddr[1] + kt * 32);
        ldsm4(b[0], bAddr[0] + kt * 32);
        ldsm4(b[1], bAddr[1] + kt * 32);
#pragma unroll
        for (int mt = 0; mt < 2; mt++)
#pragma unroll
            for (int nt = 0; nt < 4; nt++)
                mma16h(acc[mt][nt], a[mt][0], a[mt][1], a[mt][2], a[mt][3],
                       b[nt >> 1][(nt & 1) * 2], b[nt >> 1][(nt & 1) * 2 + 1]);
    }

    // exp + shift, convert to half, store direct, accumulate column sums
    __half* Eb = g_Eh + (size_t)n * HW * HW + (size_t)q0 * HW + p0;
    float cs0[4], cs1[4];
#pragma unroll
    for (int nt = 0; nt < 4; nt++) { cs0[nt] = 0.f; cs1[nt] = 0.f; }
#pragma unroll
    for (int nt = 0; nt < 4; nt++) {
        int cb = n0 + nt * 8 + 2 * t4;
        float s0 = ms[cb], s1 = ms[cb + 1];
#pragma unroll
        for (int mt = 0; mt < 2; mt++) {
            int r = m0 + mt * 16 + gid;
            __half2 h0 = __floats2half2_rn(ex2f(acc[mt][nt][0] + s0), ex2f(acc[mt][nt][1] + s1));
            __half2 h1 = __floats2half2_rn(ex2f(acc[mt][nt][2] + s0), ex2f(acc[mt][nt][3] + s1));
            *(__half2*)(Eb + (size_t)r * HW + cb) = h0;
            *(__half2*)(Eb + (size_t)(r + 8) * HW + cb) = h1;
            float2 f0 = __half22float2(h0), f1 = __half22float2(h1);
            cs0[nt] += f0.x + f1.x;
            cs1[nt] += f0.y + f1.y;
        }
    }
#pragma unroll
    for (int nt = 0; nt < 4; nt++) {
        cs0[nt] += __shfl_xor_sync(0xffffffffu, cs0[nt], 4);
        cs0[nt] += __shfl_xor_sync(0xffffffffu, cs0[nt], 8);
        cs0[nt] += __shfl_xor_sync(0xffffffffu, cs0[nt], 16);
        cs1[nt] += __shfl_xor_sync(0xffffffffu, cs1[nt], 4);
        cs1[nt] += __shfl_xor_sync(0xffffffffu, cs1[nt], 8);
        cs1[nt] += __shfl_xor_sync(0xffffffffu, cs1[nt], 16);
    }
    if (lane < 4) {
#pragma unroll
        for (int nt = 0; nt < 4; nt++) {
            Zp[w & 3][n0 + nt * 8 + 2 * lane]     = cs0[nt];
            Zp[w & 3][n0 + nt * 8 + 2 * lane + 1] = cs1[nt];
        }
    }
    __syncthreads();
    if (tid < 128) {
        float z = Zp[0][tid] + Zp[1][tid] + Zp[2][tid] + Zp[3][tid];
        g_Zp[((size_t)n * 32 + qb) * HW + p0 + tid] = z;
    }
}

// ---------------------------------------------------------------------------
// K2b: rZ[p] = 1 / sum over 32 q-block partials (fixed order).
// ---------------------------------------------------------------------------
__global__ void k_zred() {
    int p = blockIdx.x * 256 + threadIdx.x;
    int n = blockIdx.y;
    float z = 0.f;
#pragma unroll
    for (int qb = 0; qb < 32; qb++) z += g_Zp[((size_t)n * 32 + qb) * HW + p];
    g_rZ[n * HW + p] = 1.f / z;
}

// ---------------------------------------------------------------------------
// K2c: Ft[c][p] = half(F[p][c])  (transpose, 32x32 tiles)
// ---------------------------------------------------------------------------
__global__ __launch_bounds__(256) void k_ft(const float* __restrict__ F) {
    __shared__ float t[32][33];
    const int n = blockIdx.z, c0 = blockIdx.y * 32, p0 = blockIdx.x * 32;
    const int tx = threadIdx.x & 7, ty = threadIdx.x >> 3;
    const float* Fb = F + ((size_t)n * HW + p0) * CI;
    float4 v = *(const float4*)(Fb + (size_t)ty * CI + c0 + tx * 4);
    t[ty][tx * 4 + 0] = v.x; t[ty][tx * 4 + 1] = v.y;
    t[ty][tx * 4 + 2] = v.z; t[ty][tx * 4 + 3] = v.w;
    __syncthreads();
    const int cl = threadIdx.x >> 3, p4 = (threadIdx.x & 7) * 4;
    union { __half2 h[2]; uint2 u; } cv;
    cv.h[0] = __floats2half2_rn(t[p4 + 0][cl], t[p4 + 1][cl]);
    cv.h[1] = __floats2half2_rn(t[p4 + 2][cl], t[p4 + 3][cl]);
    *(uint2*)(g_Ft + ((size_t)n * CI + c0 + cl) * HW + p0 + p4) = cv.u;
}

// ---------------------------------------------------------------------------
// K3: fp16 mma m16n8k16 + ldmatrix feed.
// att[q,c] = sum_p (Eh[q,p]*rZ[p]) * Ft[c,p].  Block 128q x 128c, p chunk 128,
// 512 threads, 16 warps (4q x 4c), warp 32x32, 2 CTAs/SM.
// ---------------------------------------------------------------------------
#define K3PAD 136
#define K3_SMEMH ((128 * K3PAD * 2) * 2)  // E_s + F_s, halves

__global__ __launch_bounds__(512, 2) void k_attf() {
    extern __shared__ __half smh[];
    __half* Es = smh;
    __half* Fs = smh + 128 * K3PAD;
    const int tid = threadIdx.x, w = tid >> 5, lane = tid & 31;
    const int gid = lane >> 2, t4 = lane & 3;
    const int q0 = blockIdx.x * 128, c0 = blockIdx.y * 128, n = blockIdx.z;
    const int wq = (w & 3) * 32, wc = (w >> 2) * 32;
    const __half* Ebase = g_Eh + (size_t)n * HW * HW + (size_t)q0 * HW;
    const __half* Fbase = g_Ft + ((size_t)n * CI + c0) * HW;
    const float* rZb = g_rZ + n * HW;

    const int lrow = tid >> 4, lch = tid & 15;
    const int l7 = lane & 7, lb3 = (lane >> 3) & 1, lb4 = lane >> 4;
    uint32_t aAddr[2], bAddr[2];
#pragma unroll
    for (int mt = 0; mt < 2; mt++)
        aAddr[mt] = smem_u32(Es + (wq + mt * 16 + l7 + lb3 * 8) * K3PAD + lb4 * 8);
#pragma unroll
    for (int ntp = 0; ntp < 2; ntp++)
        bAddr[ntp] = smem_u32(Fs + (wc + ntp * 16 + l7 + lb4 * 8) * K3PAD + lb3 * 8);

    float acc[2][4][4] = {};

    for (int pc = 0; pc < 32; pc++) {
        const int p0 = pc * 128;
        __syncthreads();
#pragma unroll
        for (int i = 0; i < 4; i++) {
            int row = lrow + i * 32;
            uint4 ev = *(const uint4*)(Ebase + (size_t)row * HW + p0 + lch * 8);
            const float* rp = rZb + p0 + lch * 8;
            float4 r0 = *(const float4*)rp, r1 = *(const float4*)(rp + 4);
            union { uint4 u; __half2 h[4]; } in, ov;
            in.u = ev;
            float2 f;
            f = __half22float2(in.h[0]); f.x *= r0.x; f.y *= r0.y; ov.h[0] = __float22half2_rn(f);
            f = __half22float2(in.h[1]); f.x *= r0.z; f.y *= r0.w; ov.h[1] = __float22half2_rn(f);
            f = __half22float2(in.h[2]); f.x *= r1.x; f.y *= r1.y; ov.h[2] = __float22half2_rn(f);
            f = __half22float2(in.h[3]); f.x *= r1.z; f.y *= r1.w; ov.h[3] = __float22half2_rn(f);
            *(uint4*)(Es + row * K3PAD + lch * 8) = ov.u;
            *(uint4*)(Fs + row * K3PAD + lch * 8) =
                *(const uint4*)(Fbase + (size_t)row * HW + p0 + lch * 8);
        }
        __syncthreads();
#pragma unroll
        for (int kt = 0; kt < 8; kt++) {
            unsigned a[2][4], b[2][4];
            ldsm4(a[0], aAddr[0] + kt * 32);
            ldsm4(a[1], aAddr[1] + kt * 32);
            ldsm4(b[0], bAddr[0] + kt * 32);
            ldsm4(b[1], bAddr[1] + kt * 32);
#pragma unroll
            for (int mt = 0; mt < 2; mt++)
#pragma unroll
                for (int nt = 0; nt < 4; nt++)
                    mma16h(acc[mt][nt], a[mt][0], a[mt][1], a[mt][2], a[mt][3],
                           b[nt >> 1][(nt & 1) * 2], b[nt >> 1][(nt & 1) * 2 + 1]);
        }
    }
    float* ab = g_att + (size_t)n * CI * HW;
#pragma unroll
    for (int mt = 0; mt < 2; mt++)
#pragma unroll
        for (int nt = 0; nt < 4; nt++)
#pragma unroll
            for (int i = 0; i < 2; i++)
#pragma unroll
                for (int j = 0; j < 2; j++) {
                    int q = q0 + wq + mt * 16 + gid + i * 8;
                    int c = c0 + wc + nt * 8 + 2 * t4 + j;
                    ab[(size_t)c * HW + q] = acc[mt][nt][i * 2 + j];
                }
}

// ---------------------------------------------------------------------------
// K4: epilogue.  att slab is exactly linear in (r*256+cc) per batch.
// ---------------------------------------------------------------------------
__global__ void k_out(const float* __restrict__ mask, const float* __restrict__ ref,
                      float* __restrict__ out) {
    const int total = NB * HW * (CI / 4);
    const int stride = gridDim.x * blockDim.x;
    for (int g = blockIdx.x * blockDim.x + threadIdx.x; g < total; g += stride) {
        int n = g >> 18;
        int rem = g & 262143;
        int r = rem >> 6;
        int c4 = (rem & 63) << 2;
        float4 a  = *(const float4*)(g_att + (size_t)n * CI * HW + (size_t)r * CI + c4);
        float4 rf = *(const float4*)(ref + ((size_t)n * HW + r) * CI + c4);
        float m = mask[n * HW + r];
        float4 e;
        e.x = m * a.x + (1.f - m) * rf.x;
        e.y = m * a.y + (1.f - m) * rf.y;
        e.z = m * a.z + (1.f - m) * rf.z;
        e.w = m * a.w + (1.f - m) * rf.w;
        size_t ob = ((size_t)n * HW + r) * (2 * CI);
        *(float4*)(out + ob + c4) = e;
        *(float4*)(out + ob + CI + c4) = a;
    }
}

extern "C" void kernel_launch(void* const* d_in, const int* in_sizes, int n_in,
                              void* d_out, int out_size) {
    const float* mask = (const float*)d_in[0];
    const float* F    = (const float*)d_in[1];
    const float* ref  = (const float*)d_in[2];
    const float* W    = (const float*)d_in[3];
    float* out = (float*)d_out;
    (void)in_sizes; (void)n_in; (void)out_size;

    cudaFuncSetAttribute(k_attf, cudaFuncAttributeMaxDynamicSharedMemorySize, K3_SMEMH);

    k_query<<<dim3(32, 8), 256>>>(F, W);
    k_norm1<<<dim3(32, 8), 128>>>();
    k_norm2<<<8, 32>>>();
    k_escore<<<dim3(32, 32, 8), 512>>>();
    k_zred<<<dim3(16, 8), 256>>>();
    k_ft<<<dim3(128, 8, 8), 256>>>(F);
    k_attf<<<dim3(32, 2, 8), 512, K3_SMEMH>>>();
    k_out<<<2048, 256>>>(mask, ref, out);
}

// round 9
// speedup vs baseline: 2.3629x; 1.0261x over previous
#include <cuda_runtime.h>
#include <cuda_fp16.h>
#include <cstdint>
#include <cstddef>

#define NB 8
#define HW 4096
#define CI 256
#define DQ 64

// scratch (device globals -- no allocation allowed)
__device__ __half g_Qh[(size_t)NB * HW * DQ];     // fp16 Q, pre-scaled by sqrt(log2 e)
__device__ __half g_Eh[(size_t)NB * HW * HW];     // Eh[n][q][p] = half(2^(S - m[p] + 12))
__device__ __half g_Ft[(size_t)NB * CI * HW];     // F^T in fp16: Ft[n][c][p]
__device__ float  g_Zp[(size_t)NB * 32 * HW];     // partial Z per q-block of 128
__device__ float  g_rZ[NB * HW];                  // 1 / sum_q Eh[q,p]
__device__ float  g_rn[NB * HW];                  // row norms of Q (log2-scaled space)
__device__ float  g_Mp[NB * 32];                  // per-block partial max norms
__device__ float  g_M[NB];                        // max row norm per batch
__device__ float  g_att[(size_t)NB * CI * HW];    // att in (C, HW)-linear layout per batch

static __device__ __forceinline__ float ex2f(float x) {
    float y; asm("ex2.approx.ftz.f32 %0, %1;" : "=f"(y) : "f"(x));
    return y;
}
static __device__ __forceinline__ void mma16h(float c[4], unsigned a0, unsigned a1, unsigned a2,
                                              unsigned a3, unsigned b0, unsigned b1) {
    asm volatile(
        "mma.sync.aligned.m16n8k16.row.col.f32.f16.f16.f32 "
        "{%0,%1,%2,%3},{%4,%5,%6,%7},{%8,%9},{%0,%1,%2,%3};"
        : "+f"(c[0]), "+f"(c[1]), "+f"(c[2]), "+f"(c[3])
        : "r"(a0), "r"(a1), "r"(a2), "r"(a3), "r"(b0), "r"(b1));
}
static __device__ __forceinline__ void ldsm4(unsigned r[4], uint32_t a) {
    asm volatile("ldmatrix.sync.aligned.m8n8.x4.shared.b16 {%0,%1,%2,%3}, [%4];"
                 : "=r"(r[0]), "=r"(r[1]), "=r"(r[2]), "=r"(r[3]) : "r"(a));
}
static __device__ __forceinline__ uint32_t smem_u32(const void* p) {
    return (uint32_t)__cvta_generic_to_shared(p);
}
static __device__ __forceinline__ void cp16(uint32_t dst, const void* src) {
    asm volatile("cp.async.cg.shared.global [%0], [%1], 16;" :: "r"(dst), "l"(src) : "memory");
}

// ---------------------------------------------------------------------------
// K1: Q = (F @ W) * sqrt(log2 e), fp32 FMA, stored fp16.
// ---------------------------------------------------------------------------
__global__ __launch_bounds__(256) void k_query(const float* __restrict__ F,
                                               const float* __restrict__ W) {
    __shared__ float A_s[32][132];
    __shared__ float W_s[32][68];
    const int tid = threadIdx.x;
    const int n = blockIdx.y, p0 = blockIdx.x * 128;
    const int tx = tid & 15, ty = tid >> 4;
    float acc[8][4];
#pragma unroll
    for (int i = 0; i < 8; i++)
#pragma unroll
        for (int j = 0; j < 4; j++) acc[i][j] = 0.f;
    const float* Fb = F + ((size_t)n * HW + p0) * CI;

    for (int kc = 0; kc < 8; kc++) {
        __syncthreads();
#pragma unroll
        for (int i = 0; i < 4; i++) {
            int idx = tid + i * 256;
            int row = idx >> 3, c4 = (idx & 7) * 4;
            float4 v = *(const float4*)(Fb + (size_t)row * CI + kc * 32 + c4);
            A_s[c4 + 0][row] = v.x; A_s[c4 + 1][row] = v.y;
            A_s[c4 + 2][row] = v.z; A_s[c4 + 3][row] = v.w;
        }
#pragma unroll
        for (int i = 0; i < 2; i++) {
            int idx = tid + i * 256;
            int row = idx >> 4, c4 = (idx & 15) * 4;
            *(float4*)&W_s[row][c4] = *(const float4*)(W + (kc * 32 + row) * DQ + c4);
        }
        __syncthreads();
#pragma unroll
        for (int k = 0; k < 32; k++) {
            float4 a0 = *(float4*)&A_s[k][8 * ty];
            float4 a1 = *(float4*)&A_s[k][8 * ty + 4];
            float4 b  = *(float4*)&W_s[k][4 * tx];
            float av[8] = {a0.x, a0.y, a0.z, a0.w, a1.x, a1.y, a1.z, a1.w};
            float bv[4] = {b.x, b.y, b.z, b.w};
#pragma unroll
            for (int i = 0; i < 8; i++)
#pragma unroll
                for (int j = 0; j < 4; j++) acc[i][j] += av[i] * bv[j];
        }
    }
    const float s = 1.2011224087864498f;  // sqrt(log2 e)
#pragma unroll
    for (int i = 0; i < 8; i++) {
        int p = p0 + 8 * ty + i;
        union { __half2 h[2]; uint2 u; } cv;
        cv.h[0] = __floats2half2_rn(acc[i][0] * s, acc[i][1] * s);
        cv.h[1] = __floats2half2_rn(acc[i][2] * s, acc[i][3] * s);
        *(uint2*)(g_Qh + ((size_t)n * HW + p) * DQ + 4 * tx) = cv.u;
    }
}

// ---------------------------------------------------------------------------
// K1b: row norms of Q (from the stored halves) + per-block max.
// ---------------------------------------------------------------------------
__global__ __launch_bounds__(128) void k_norm1() {
    __shared__ float mx[128];
    const int n = blockIdx.y, p = blockIdx.x * 128 + threadIdx.x;
    const __half2* q = (const __half2*)(g_Qh + (size_t)(n * HW + p) * DQ);
    float s = 0.f;
#pragma unroll
    for (int i = 0; i < 32; i++) {
        float2 f = __half22float2(q[i]);
        s += f.x * f.x + f.y * f.y;
    }
    float rn = sqrtf(s);
    g_rn[n * HW + p] = rn;
    mx[threadIdx.x] = rn;
    __syncthreads();
    for (int d = 64; d > 0; d >>= 1) {
        if (threadIdx.x < d) mx[threadIdx.x] = fmaxf(mx[threadIdx.x], mx[threadIdx.x + d]);
        __syncthreads();
    }
    if (threadIdx.x == 0) g_Mp[n * 32 + blockIdx.x] = mx[0];
}
__global__ void k_norm2() {
    const int n = blockIdx.x;
    float m = g_Mp[n * 32 + threadIdx.x];
#pragma unroll
    for (int d = 16; d > 0; d >>= 1) m = fmaxf(m, __shfl_xor_sync(0xffffffffu, m, d));
    if (threadIdx.x == 0) g_M[n] = m;
}

// ---------------------------------------------------------------------------
// K2: Eh[q,p] = half(2^(S - rn[p]*M + 12)) per 128x128 tile.  fp16 mma +
// ldmatrix feed; E tile staged in smem (pad 136, conflict-free) then stored
// coalesced uint4.  Z summed from the same rounded halves via shfl.
// ---------------------------------------------------------------------------
#define K2_QQ_OFF 0
#define K2_QP_OFF (128 * 72)
#define K2_ET_OFF (2 * 128 * 72)
#define K2_F32_OFF ((2 * 128 * 72 + 128 * 136) * 2)
#define K2_SMEM (K2_F32_OFF + (4 * 128 + 128) * 4)

__global__ __launch_bounds__(512, 2) void k_escore() {
    extern __shared__ char k2sm[];
    __half(*Qq)[72]  = (__half(*)[72])(k2sm);
    __half(*Qp)[72]  = (__half(*)[72])(k2sm + K2_QP_OFF * 2);
    __half(*Et)[136] = (__half(*)[136])(k2sm + K2_ET_OFF * 2);
    float* Zp        = (float*)(k2sm + K2_F32_OFF);
    float* ms        = Zp + 512;
    const int tid = threadIdx.x, w = tid >> 5, lane = tid & 31;
    const int gid = lane >> 2, t4 = lane & 3;
    const int qb = blockIdx.x, pb = blockIdx.y, n = blockIdx.z;
    const int q0 = qb * 128, p0 = pb * 128;
    const int m0 = (w & 3) * 32, n0 = (w >> 2) * 32;
    const __half* Qh = g_Qh + (size_t)n * HW * DQ;

#pragma unroll
    for (int i = 0; i < 2; i++) {
        int idx = tid + i * 512;
        int row = idx >> 3, ch = (idx & 7) * 8;
        *(uint4*)&Qq[row][ch] = *(const uint4*)(Qh + (size_t)(q0 + row) * DQ + ch);
        *(uint4*)&Qp[row][ch] = *(const uint4*)(Qh + (size_t)(p0 + row) * DQ + ch);
    }
    if (tid < 128) ms[tid] = 12.f - g_rn[n * HW + p0 + tid] * g_M[n];
    __syncthreads();

    const int l7 = lane & 7, lb3 = (lane >> 3) & 1, lb4 = lane >> 4;
    uint32_t aAddr[2], bAddr[2];
#pragma unroll
    for (int mt = 0; mt < 2; mt++)
        aAddr[mt] = smem_u32(&Qq[m0 + mt * 16 + l7 + lb3 * 8][lb4 * 8]);
#pragma unroll
    for (int ntp = 0; ntp < 2; ntp++)
        bAddr[ntp] = smem_u32(&Qp[n0 + ntp * 16 + l7 + lb4 * 8][lb3 * 8]);

    float acc[2][4][4] = {};
#pragma unroll
    for (int kt = 0; kt < 4; kt++) {
        unsigned a[2][4], b[2][4];
        ldsm4(a[0], aAddr[0] + kt * 32);
        ldsm4(a[1], aAddr[1] + kt * 32);
        ldsm4(b[0], bAddr[0] + kt * 32);
        ldsm4(b[1], bAddr[1] + kt * 32);
#pragma unroll
        for (int mt = 0; mt < 2; mt++)
#pragma unroll
            for (int nt = 0; nt < 4; nt++)
                mma16h(acc[mt][nt], a[mt][0], a[mt][1], a[mt][2], a[mt][3],
                       b[nt >> 1][(nt & 1) * 2], b[nt >> 1][(nt & 1) * 2 + 1]);
    }

    // exp + shift -> half, stage into smem tile, accumulate column sums
    float cs0[4], cs1[4];
#pragma unroll
    for (int nt = 0; nt < 4; nt++) { cs0[nt] = 0.f; cs1[nt] = 0.f; }
#pragma unroll
    for (int nt = 0; nt < 4; nt++) {
        int cb = n0 + nt * 8 + 2 * t4;
        float s0 = ms[cb], s1 = ms[cb + 1];
#pragma unroll
        for (int mt = 0; mt < 2; mt++) {
            int r = m0 + mt * 16 + gid;
            __half2 h0 = __floats2half2_rn(ex2f(acc[mt][nt][0] + s0), ex2f(acc[mt][nt][1] + s1));
            __half2 h1 = __floats2half2_rn(ex2f(acc[mt][nt][2] + s0), ex2f(acc[mt][nt][3] + s1));
            *(__half2*)&Et[r][cb] = h0;
            *(__half2*)&Et[r + 8][cb] = h1;
            float2 f0 = __half22float2(h0), f1 = __half22float2(h1);
            cs0[nt] += f0.x + f1.x;
            cs1[nt] += f0.y + f1.y;
        }
    }
#pragma unroll
    for (int nt = 0; nt < 4; nt++) {
        cs0[nt] += __shfl_xor_sync(0xffffffffu, cs0[nt], 4);
        cs0[nt] += __shfl_xor_sync(0xffffffffu, cs0[nt], 8);
        cs0[nt] += __shfl_xor_sync(0xffffffffu, cs0[nt], 16);
        cs1[nt] += __shfl_xor_sync(0xffffffffu, cs1[nt], 4);
        cs1[nt] += __shfl_xor_sync(0xffffffffu, cs1[nt], 8);
        cs1[nt] += __shfl_xor_sync(0xffffffffu, cs1[nt], 16);
    }
    if (lane < 4) {
#pragma unroll
        for (int nt = 0; nt < 4; nt++) {
            Zp[(w & 3) * 128 + n0 + nt * 8 + 2 * lane]     = cs0[nt];
            Zp[(w & 3) * 128 + n0 + nt * 8 + 2 * lane + 1] = cs1[nt];
        }
    }
    __syncthreads();
    // coalesced copy-out of the E tile
    __half* Eb = g_Eh + (size_t)n * HW * HW + (size_t)q0 * HW + p0;
#pragma unroll
    for (int i = 0; i < 4; i++) {
        int idx = tid + i * 512;
        int row = idx >> 4, ch = (idx & 15) * 8;
        *(uint4*)(Eb + (size_t)row * HW + ch) = *(uint4*)&Et[row][ch];
    }
    if (tid < 128) {
        float z = Zp[tid] + Zp[128 + tid] + Zp[256 + tid] + Zp[384 + tid];
        g_Zp[((size_t)n * 32 + qb) * HW + p0 + tid] = z;
    }
}

// ---------------------------------------------------------------------------
// K2b: rZ[p] = 1 / sum over 32 q-block partials (fixed order).
// ---------------------------------------------------------------------------
__global__ void k_zred() {
    int p = blockIdx.x * 256 + threadIdx.x;
    int n = blockIdx.y;
    float z = 0.f;
#pragma unroll
    for (int qb = 0; qb < 32; qb++) z += g_Zp[((size_t)n * 32 + qb) * HW + p];
    g_rZ[n * HW + p] = 1.f / z;
}

// ---------------------------------------------------------------------------
// K2c: Ft[c][p] = half(F[p][c])  (transpose, 32x32 tiles)
// ---------------------------------------------------------------------------
__global__ __launch_bounds__(256) void k_ft(const float* __restrict__ F) {
    __shared__ float t[32][33];
    const int n = blockIdx.z, c0 = blockIdx.y * 32, p0 = blockIdx.x * 32;
    const int tx = threadIdx.x & 7, ty = threadIdx.x >> 3;
    const float* Fb = F + ((size_t)n * HW + p0) * CI;
    float4 v = *(const float4*)(Fb + (size_t)ty * CI + c0 + tx * 4);
    t[ty][tx * 4 + 0] = v.x; t[ty][tx * 4 + 1] = v.y;
    t[ty][tx * 4 + 2] = v.z; t[ty][tx * 4 + 3] = v.w;
    __syncthreads();
    const int cl = threadIdx.x >> 3, p4 = (threadIdx.x & 7) * 4;
    union { __half2 h[2]; uint2 u; } cv;
    cv.h[0] = __floats2half2_rn(t[p4 + 0][cl], t[p4 + 1][cl]);
    cv.h[1] = __floats2half2_rn(t[p4 + 2][cl], t[p4 + 3][cl]);
    *(uint2*)(g_Ft + ((size_t)n * CI + c0 + cl) * HW + p0 + p4) = cv.u;
}

// ---------------------------------------------------------------------------
// K3: fp16 mma m16n8k16 + ldmatrix feed.  Full c=256 tile -> E read ONCE.
// att[q,c] = sum_p (Eh[q,p]*rZ[p]) * Ft[c,p].  Block 128q x 256c, p chunk 128,
// 1024 threads, 32 warps (4q x 8c), warp 32x32.  F fetched via cp.async.
// ---------------------------------------------------------------------------
#define K3PAD 136
#define K3_ES_OFF 0
#define K3_FS_OFF (128 * K3PAD)
#define K3_SMEMH ((128 * K3PAD + 256 * K3PAD) * 2)

__global__ __launch_bounds__(1024, 1) void k_attf() {
    extern __shared__ __half smh[];
    __half* Es = smh + K3_ES_OFF;
    __half* Fs = smh + K3_FS_OFF;
    const int tid = threadIdx.x, w = tid >> 5, lane = tid & 31;
    const int gid = lane >> 2, t4 = lane & 3;
    const int q0 = blockIdx.x * 128, n = blockIdx.y;
    const int wq = (w & 3) * 32, wc = (w >> 2) * 32;
    const __half* Ebase = g_Eh + (size_t)n * HW * HW + (size_t)q0 * HW;
    const __half* Fbase = g_Ft + (size_t)n * CI * HW;
    const float* rZb = g_rZ + n * HW;

    const int lrow = tid >> 4, lch = tid & 15;
    const int l7 = lane & 7, lb3 = (lane >> 3) & 1, lb4 = lane >> 4;
    uint32_t aAddr[2], bAddr[2];
#pragma unroll
    for (int mt = 0; mt < 2; mt++)
        aAddr[mt] = smem_u32(Es + (wq + mt * 16 + l7 + lb3 * 8) * K3PAD + lb4 * 8);
#pragma unroll
    for (int ntp = 0; ntp < 2; ntp++)
        bAddr[ntp] = smem_u32(Fs + (wc + ntp * 16 + l7 + lb4 * 8) * K3PAD + lb3 * 8);

    float acc[2][4][4] = {};

    for (int pc = 0; pc < 32; pc++) {
        const int p0 = pc * 128;
        __syncthreads();
        // F: cp.async direct into padded smem (no conversion needed)
#pragma unroll
        for (int i = 0; i < 4; i++) {
            int row = lrow + i * 64;
            cp16(smem_u32(Fs + row * K3PAD + lch * 8),
                 Fbase + (size_t)row * HW + p0 + lch * 8);
        }
        asm volatile("cp.async.commit_group;" ::: "memory");
        // E: load, fold rZ (fp32), store to padded smem
#pragma unroll
        for (int i = 0; i < 2; i++) {
            int row = lrow + i * 64;
            uint4 ev = *(const uint4*)(Ebase + (size_t)row * HW + p0 + lch * 8);
            const float* rp = rZb + p0 + lch * 8;
            float4 r0 = *(const float4*)rp, r1 = *(const float4*)(rp + 4);
            union { uint4 u; __half2 h[4]; } in, ov;
            in.u = ev;
            float2 f;
            f = __half22float2(in.h[0]); f.x *= r0.x; f.y *= r0.y; ov.h[0] = __float22half2_rn(f);
            f = __half22float2(in.h[1]); f.x *= r0.z; f.y *= r0.w; ov.h[1] = __float22half2_rn(f);
            f = __half22float2(in.h[2]); f.x *= r1.x; f.y *= r1.y; ov.h[2] = __float22half2_rn(f);
            f = __half22float2(in.h[3]); f.x *= r1.z; f.y *= r1.w; ov.h[3] = __float22half2_rn(f);
            *(uint4*)(Es + row * K3PAD + lch * 8) = ov.u;
        }
        asm volatile("cp.async.wait_group 0;" ::: "memory");
        __syncthreads();
#pragma unroll
        for (int kt = 0; kt < 8; kt++) {
            unsigned a[2][4], b[2][4];
            ldsm4(a[0], aAddr[0] + kt * 32);
            ldsm4(a[1], aAddr[1] + kt * 32);
            ldsm4(b[0], bAddr[0] + kt * 32);
            ldsm4(b[1], bAddr[1] + kt * 32);
#pragma unroll
            for (int mt = 0; mt < 2; mt++)
#pragma unroll
                for (int nt = 0; nt < 4; nt++)
                    mma16h(acc[mt][nt], a[mt][0], a[mt][1], a[mt][2], a[mt][3],
                           b[nt >> 1][(nt & 1) * 2], b[nt >> 1][(nt & 1) * 2 + 1]);
        }
    }
    float* ab = g_att + (size_t)n * CI * HW;
#pragma unroll
    for (int mt = 0; mt < 2; mt++)
#pragma unroll
        for (int nt = 0; nt < 4; nt++)
#pragma unroll
            for (int i = 0; i < 2; i++)
#pragma unroll
                for (int j = 0; j < 2; j++) {
                    int q = q0 + wq + mt * 16 + gid + i * 8;
                    int c = wc + nt * 8 + 2 * t4 + j;
                    ab[(size_t)c * HW + q] = acc[mt][nt][i * 2 + j];
                }
}

// ---------------------------------------------------------------------------
// K4: epilogue.  att slab is exactly linear in (r*256+cc) per batch.
// ---------------------------------------------------------------------------
__global__ void k_out(const float* __restrict__ mask, const float* __restrict__ ref,
                      float* __restrict__ out) {
    const int total = NB * HW * (CI / 4);
    const int stride = gridDim.x * blockDim.x;
    for (int g = blockIdx.x * blockDim.x + threadIdx.x; g < total; g += stride) {
        int n = g >> 18;
        int rem = g & 262143;
        int r = rem >> 6;
        int c4 = (rem & 63) << 2;
        float4 a  = *(const float4*)(g_att + (size_t)n * CI * HW + (size_t)r * CI + c4);
        float4 rf = *(const float4*)(ref + ((size_t)n * HW + r) * CI + c4);
        float m = mask[n * HW + r];
        float4 e;
        e.x = m * a.x + (1.f - m) * rf.x;
        e.y = m * a.y + (1.f - m) * rf.y;
        e.z = m * a.z + (1.f - m) * rf.z;
        e.w = m * a.w + (1.f - m) * rf.w;
        size_t ob = ((size_t)n * HW + r) * (2 * CI);
        *(float4*)(out + ob + c4) = e;
        *(float4*)(out + ob + CI + c4) = a;
    }
}

extern "C" void kernel_launch(void* const* d_in, const int* in_sizes, int n_in,
                              void* d_out, int out_size) {
    const float* mask = (const float*)d_in[0];
    const float* F    = (const float*)d_in[1];
    const float* ref  = (const float*)d_in[2];
    const float* W    = (const float*)d_in[3];
    float* out = (float*)d_out;
    (void)in_sizes; (void)n_in; (void)out_size;

    cudaFuncSetAttribute(k_escore, cudaFuncAttributeMaxDynamicSharedMemorySize, K2_SMEM);
    cudaFuncSetAttribute(k_attf,   cudaFuncAttributeMaxDynamicSharedMemorySize, K3_SMEMH);

    k_query<<<dim3(32, 8), 256>>>(F, W);
    k_norm1<<<dim3(32, 8), 128>>>();
    k_norm2<<<8, 32>>>();
    k_escore<<<dim3(32, 32, 8), 512, K2_SMEM>>>();
    k_zred<<<dim3(16, 8), 256>>>();
    k_ft<<<dim3(128, 8, 8), 256>>>(F);
    k_attf<<<dim3(32, 8), 1024, K3_SMEMH>>>();
    k_out<<<2048, 256>>>(mask, ref, out);
}

// round 11
// speedup vs baseline: 2.6685x; 1.1293x over previous
#include <cuda_runtime.h>
#include <cuda_fp16.h>
#include <cstdint>
#include <cstddef>

#define NB 8
#define HW 4096
#define CI 256
#define DQ 64

// scratch (device globals -- no allocation allowed)
__device__ __half g_Qh[(size_t)NB * HW * DQ];     // fp16 Q, pre-scaled by sqrt(log2 e)
__device__ __half g_Eh[(size_t)NB * HW * HW];     // Eh[n][q][p] = half(2^(S - m[p] + 12))
__device__ __half g_Gt[(size_t)NB * CI * HW];     // G[n][c][p] = half(F[p][c] * 4096 * rZ[p])
__device__ float  g_Zp[(size_t)NB * 32 * HW];     // partial Z per q-block of 128
__device__ float  g_rZ[NB * HW];                  // 4096 / sum_q Eh[q,p]
__device__ float  g_rn[NB * HW];                  // row norms of Q (log2-scaled space)
__device__ float  g_Mp[NB * 32];                  // per-block partial max norms
__device__ float  g_M[NB];                        // max row norm per batch
__device__ float  g_att[(size_t)NB * CI * HW];    // att in (C, HW)-linear layout per batch

static __device__ __forceinline__ float ex2f(float x) {
    float y; asm("ex2.approx.ftz.f32 %0, %1;" : "=f"(y) : "f"(x));
    return y;
}
static __device__ __forceinline__ void mma16h(float c[4], unsigned a0, unsigned a1, unsigned a2,
                                              unsigned a3, unsigned b0, unsigned b1) {
    asm volatile(
        "mma.sync.aligned.m16n8k16.row.col.f32.f16.f16.f32 "
        "{%0,%1,%2,%3},{%4,%5,%6,%7},{%8,%9},{%0,%1,%2,%3};"
        : "+f"(c[0]), "+f"(c[1]), "+f"(c[2]), "+f"(c[3])
        : "r"(a0), "r"(a1), "r"(a2), "r"(a3), "r"(b0), "r"(b1));
}
static __device__ __forceinline__ void ldsm4(unsigned r[4], uint32_t a) {
    asm volatile("ldmatrix.sync.aligned.m8n8.x4.shared.b16 {%0,%1,%2,%3}, [%4];"
                 : "=r"(r[0]), "=r"(r[1]), "=r"(r[2]), "=r"(r[3]) : "r"(a));
}
static __device__ __forceinline__ uint32_t smem_u32(const void* p) {
    return (uint32_t)__cvta_generic_to_shared(p);
}
static __device__ __forceinline__ void cp16(uint32_t dst, const void* src) {
    asm volatile("cp.async.cg.shared.global [%0], [%1], 16;" :: "r"(dst), "l"(src) : "memory");
}

// ---------------------------------------------------------------------------
// K1: Q = (F @ W) * sqrt(log2 e), fp32 FMA, stored fp16.
// ---------------------------------------------------------------------------
__global__ __launch_bounds__(256) void k_query(const float* __restrict__ F,
                                               const float* __restrict__ W) {
    __shared__ float A_s[32][132];
    __shared__ float W_s[32][68];
    const int tid = threadIdx.x;
    const int n = blockIdx.y, p0 = blockIdx.x * 128;
    const int tx = tid & 15, ty = tid >> 4;
    float acc[8][4];
#pragma unroll
    for (int i = 0; i < 8; i++)
#pragma unroll
        for (int j = 0; j < 4; j++) acc[i][j] = 0.f;
    const float* Fb = F + ((size_t)n * HW + p0) * CI;

    for (int kc = 0; kc < 8; kc++) {
        __syncthreads();
#pragma unroll
        for (int i = 0; i < 4; i++) {
            int idx = tid + i * 256;
            int row = idx >> 3, c4 = (idx & 7) * 4;
            float4 v = *(const float4*)(Fb + (size_t)row * CI + kc * 32 + c4);
            A_s[c4 + 0][row] = v.x; A_s[c4 + 1][row] = v.y;
            A_s[c4 + 2][row] = v.z; A_s[c4 + 3][row] = v.w;
        }
#pragma unroll
        for (int i = 0; i < 2; i++) {
            int idx = tid + i * 256;
            int row = idx >> 4, c4 = (idx & 15) * 4;
            *(float4*)&W_s[row][c4] = *(const float4*)(W + (kc * 32 + row) * DQ + c4);
        }
        __syncthreads();
#pragma unroll
        for (int k = 0; k < 32; k++) {
            float4 a0 = *(float4*)&A_s[k][8 * ty];
            float4 a1 = *(float4*)&A_s[k][8 * ty + 4];
            float4 b  = *(float4*)&W_s[k][4 * tx];
            float av[8] = {a0.x, a0.y, a0.z, a0.w, a1.x, a1.y, a1.z, a1.w};
            float bv[4] = {b.x, b.y, b.z, b.w};
#pragma unroll
            for (int i = 0; i < 8; i++)
#pragma unroll
                for (int j = 0; j < 4; j++) acc[i][j] += av[i] * bv[j];
        }
    }
    const float s = 1.2011224087864498f;  // sqrt(log2 e)
#pragma unroll
    for (int i = 0; i < 8; i++) {
        int p = p0 + 8 * ty + i;
        union { __half2 h[2]; uint2 u; } cv;
        cv.h[0] = __floats2half2_rn(acc[i][0] * s, acc[i][1] * s);
        cv.h[1] = __floats2half2_rn(acc[i][2] * s, acc[i][3] * s);
        *(uint2*)(g_Qh + ((size_t)n * HW + p) * DQ + 4 * tx) = cv.u;
    }
}

// ---------------------------------------------------------------------------
// K1b: row norms of Q (from the stored halves) + per-block max.
// ---------------------------------------------------------------------------
__global__ __launch_bounds__(128) void k_norm1() {
    __shared__ float mx[128];
    const int n = blockIdx.y, p = blockIdx.x * 128 + threadIdx.x;
    const __half2* q = (const __half2*)(g_Qh + (size_t)(n * HW + p) * DQ);
    float s = 0.f;
#pragma unroll
    for (int i = 0; i < 32; i++) {
        float2 f = __half22float2(q[i]);
        s += f.x * f.x + f.y * f.y;
    }
    float rn = sqrtf(s);
    g_rn[n * HW + p] = rn;
    mx[threadIdx.x] = rn;
    __syncthreads();
    for (int d = 64; d > 0; d >>= 1) {
        if (threadIdx.x < d) mx[threadIdx.x] = fmaxf(mx[threadIdx.x], mx[threadIdx.x + d]);
        __syncthreads();
    }
    if (threadIdx.x == 0) g_Mp[n * 32 + blockIdx.x] = mx[0];
}
__global__ void k_norm2() {
    const int n = blockIdx.x;
    float m = g_Mp[n * 32 + threadIdx.x];
#pragma unroll
    for (int d = 16; d > 0; d >>= 1) m = fmaxf(m, __shfl_xor_sync(0xffffffffu, m, d));
    if (threadIdx.x == 0) g_M[n] = m;
}

// ---------------------------------------------------------------------------
// K2: Eh[q,p] = half(2^(S - rn[p]*M + 12)) per 128x128 tile.  fp16 mma +
// ldmatrix feed; E tile staged in smem then stored coalesced uint4.
// Z summed from the same rounded halves via shfl.
// ---------------------------------------------------------------------------
#define K2_QP_OFF (128 * 72)
#define K2_ET_OFF (2 * 128 * 72)
#define K2_F32_OFF ((2 * 128 * 72 + 128 * 136) * 2)
#define K2_SMEM (K2_F32_OFF + (4 * 128 + 128) * 4)

__global__ __launch_bounds__(512, 2) void k_escore() {
    extern __shared__ char k2sm[];
    __half(*Qq)[72]  = (__half(*)[72])(k2sm);
    __half(*Qp)[72]  = (__half(*)[72])(k2sm + K2_QP_OFF * 2);
    __half(*Et)[136] = (__half(*)[136])(k2sm + K2_ET_OFF * 2);
    float* Zp        = (float*)(k2sm + K2_F32_OFF);
    float* ms        = Zp + 512;
    const int tid = threadIdx.x, w = tid >> 5, lane = tid & 31;
    const int gid = lane >> 2, t4 = lane & 3;
    const int qb = blockIdx.x, pb = blockIdx.y, n = blockIdx.z;
    const int q0 = qb * 128, p0 = pb * 128;
    const int m0 = (w & 3) * 32, n0 = (w >> 2) * 32;
    const __half* Qh = g_Qh + (size_t)n * HW * DQ;

#pragma unroll
    for (int i = 0; i < 2; i++) {
        int idx = tid + i * 512;
        int row = idx >> 3, ch = (idx & 7) * 8;
        *(uint4*)&Qq[row][ch] = *(const uint4*)(Qh + (size_t)(q0 + row) * DQ + ch);
        *(uint4*)&Qp[row][ch] = *(const uint4*)(Qh + (size_t)(p0 + row) * DQ + ch);
    }
    if (tid < 128) ms[tid] = 12.f - g_rn[n * HW + p0 + tid] * g_M[n];
    __syncthreads();

    const int l7 = lane & 7, lb3 = (lane >> 3) & 1, lb4 = lane >> 4;
    uint32_t aAddr[2], bAddr[2];
#pragma unroll
    for (int mt = 0; mt < 2; mt++)
        aAddr[mt] = smem_u32(&Qq[m0 + mt * 16 + l7 + lb3 * 8][lb4 * 8]);
#pragma unroll
    for (int ntp = 0; ntp < 2; ntp++)
        bAddr[ntp] = smem_u32(&Qp[n0 + ntp * 16 + l7 + lb4 * 8][lb3 * 8]);

    float acc[2][4][4] = {};
#pragma unroll
    for (int kt = 0; kt < 4; kt++) {
        unsigned a[2][4], b[2][4];
        ldsm4(a[0], aAddr[0] + kt * 32);
        ldsm4(a[1], aAddr[1] + kt * 32);
        ldsm4(b[0], bAddr[0] + kt * 32);
        ldsm4(b[1], bAddr[1] + kt * 32);
#pragma unroll
        for (int mt = 0; mt < 2; mt++)
#pragma unroll
            for (int nt = 0; nt < 4; nt++)
                mma16h(acc[mt][nt], a[mt][0], a[mt][1], a[mt][2], a[mt][3],
                       b[nt >> 1][(nt & 1) * 2], b[nt >> 1][(nt & 1) * 2 + 1]);
    }

    // exp + shift -> half, stage into smem tile, accumulate column sums
    float cs0[4], cs1[4];
#pragma unroll
    for (int nt = 0; nt < 4; nt++) { cs0[nt] = 0.f; cs1[nt] = 0.f; }
#pragma unroll
    for (int nt = 0; nt < 4; nt++) {
        int cb = n0 + nt * 8 + 2 * t4;
        float s0 = ms[cb], s1 = ms[cb + 1];
#pragma unroll
        for (int mt = 0; mt < 2; mt++) {
            int r = m0 + mt * 16 + gid;
            __half2 h0 = __floats2half2_rn(ex2f(acc[mt][nt][0] + s0), ex2f(acc[mt][nt][1] + s1));
            __half2 h1 = __floats2half2_rn(ex2f(acc[mt][nt][2] + s0), ex2f(acc[mt][nt][3] + s1));
            *(__half2*)&Et[r][cb] = h0;
            *(__half2*)&Et[r + 8][cb] = h1;
            float2 f0 = __half22float2(h0), f1 = __half22float2(h1);
            cs0[nt] += f0.x + f1.x;
            cs1[nt] += f0.y + f1.y;
        }
    }
#pragma unroll
    for (int nt = 0; nt < 4; nt++) {
        cs0[nt] += __shfl_xor_sync(0xffffffffu, cs0[nt], 4);
        cs0[nt] += __shfl_xor_sync(0xffffffffu, cs0[nt], 8);
        cs0[nt] += __shfl_xor_sync(0xffffffffu, cs0[nt], 16);
        cs1[nt] += __shfl_xor_sync(0xffffffffu, cs1[nt], 4);
        cs1[nt] += __shfl_xor_sync(0xffffffffu, cs1[nt], 8);
        cs1[nt] += __shfl_xor_sync(0xffffffffu, cs1[nt], 16);
    }
    if (lane < 4) {
#pragma unroll
        for (int nt = 0; nt < 4; nt++) {
            Zp[(w & 3) * 128 + n0 + nt * 8 + 2 * lane]     = cs0[nt];
            Zp[(w & 3) * 128 + n0 + nt * 8 + 2 * lane + 1] = cs1[nt];
        }
    }
    __syncthreads();
    __half* Eb = g_Eh + (size_t)n * HW * HW + (size_t)q0 * HW + p0;
#pragma unroll
    for (int i = 0; i < 4; i++) {
        int idx = tid + i * 512;
        int row = idx >> 4, ch = (idx & 15) * 8;
        *(uint4*)(Eb + (size_t)row * HW + ch) = *(uint4*)&Et[row][ch];
    }
    if (tid < 128) {
        float z = Zp[tid] + Zp[128 + tid] + Zp[256 + tid] + Zp[384 + tid];
        g_Zp[((size_t)n * 32 + qb) * HW + p0 + tid] = z;
    }
}

// ---------------------------------------------------------------------------
// K2b: rZ[p] = 4096 / sum over 32 q-block partials (fixed order).
// ---------------------------------------------------------------------------
__global__ void k_zred() {
    int p = blockIdx.x * 256 + threadIdx.x;
    int n = blockIdx.y;
    float z = 0.f;
#pragma unroll
    for (int qb = 0; qb < 32; qb++) z += g_Zp[((size_t)n * 32 + qb) * HW + p];
    g_rZ[n * HW + p] = 4096.f / z;
}

// ---------------------------------------------------------------------------
// K2c: G[c][p] = half(F[p][c] * rZ[p])  (transpose + fold, 32x32 tiles)
// ---------------------------------------------------------------------------
__global__ __launch_bounds__(256) void k_gt(const float* __restrict__ F) {
    __shared__ float t[32][33];
    __shared__ float rz[32];
    const int n = blockIdx.z, c0 = blockIdx.y * 32, p0 = blockIdx.x * 32;
    const int tx = threadIdx.x & 7, ty = threadIdx.x >> 3;
    const float* Fb = F + ((size_t)n * HW + p0) * CI;
    float4 v = *(const float4*)(Fb + (size_t)ty * CI + c0 + tx * 4);
    t[ty][tx * 4 + 0] = v.x; t[ty][tx * 4 + 1] = v.y;
    t[ty][tx * 4 + 2] = v.z; t[ty][tx * 4 + 3] = v.w;
    if (threadIdx.x < 32) rz[threadIdx.x] = g_rZ[n * HW + p0 + threadIdx.x];
    __syncthreads();
    const int cl = threadIdx.x >> 3, p4 = (threadIdx.x & 7) * 4;
    union { __half2 h[2]; uint2 u; } cv;
    cv.h[0] = __floats2half2_rn(t[p4 + 0][cl] * rz[p4 + 0], t[p4 + 1][cl] * rz[p4 + 1]);
    cv.h[1] = __floats2half2_rn(t[p4 + 2][cl] * rz[p4 + 2], t[p4 + 3][cl] * rz[p4 + 3]);
    *(uint2*)(g_Gt + ((size_t)n * CI + c0 + cl) * HW + p0 + p4) = cv.u;
}

// ---------------------------------------------------------------------------
// K3: PURE fp16 GEMM, double-buffered cp.async.  att[q,c] = (sum_p Eh[q,p] *
// G[c,p]) / 4096.  Block 128q x 128c, k chunk 64, 2 stages, 512 threads,
// 16 warps (4q x 4c), warp 32x32, 2 CTAs/SM.
// Each thread loads TWO rows per operand per chunk (128 rows total).
// ---------------------------------------------------------------------------
#define K5PAD 72
#define K5_STAGE (128 * K5PAD)              // halves per array per stage
#define K5_SMEM (4 * K5_STAGE * 2)          // bytes (E0,E1,G0,G1)

__global__ __launch_bounds__(512, 2) void k_attf() {
    extern __shared__ __half smh[];
    __half* Es0 = smh;
    __half* Gs0 = smh + 2 * K5_STAGE;
    const int tid = threadIdx.x, w = tid >> 5, lane = tid & 31;
    const int gid = lane >> 2, t4 = lane & 3;
    const int q0 = blockIdx.x * 128, c0 = blockIdx.y * 128, n = blockIdx.z;
    const int wq = (w & 3) * 32, wc = (w >> 2) * 32;
    const __half* Ebase = g_Eh + (size_t)n * HW * HW + (size_t)q0 * HW;
    const __half* Gbase = g_Gt + ((size_t)n * CI + c0) * HW;

    const int lrow = tid >> 3, lch = (tid & 7) * 8;  // rows lrow, lrow+64
    const int l7 = lane & 7, lb3 = (lane >> 3) & 1, lb4 = lane >> 4;
    uint32_t aAddr[2], bAddr[2];
#pragma unroll
    for (int mt = 0; mt < 2; mt++)
        aAddr[mt] = smem_u32(Es0 + (wq + mt * 16 + l7 + lb3 * 8) * K5PAD + lb4 * 8);
#pragma unroll
    for (int ntp = 0; ntp < 2; ntp++)
        bAddr[ntp] = smem_u32(Gs0 + (wc + ntp * 16 + l7 + lb4 * 8) * K5PAD + lb3 * 8);
    const uint32_t sdelta = K5_STAGE * 2;  // bytes between stages
    const uint32_t rdelta = 64 * K5PAD * 2;  // bytes between row lrow and lrow+64

    const uint32_t eDst = smem_u32(Es0 + lrow * K5PAD + lch);
    const uint32_t gDst = smem_u32(Gs0 + lrow * K5PAD + lch);
    const __half* eSrc0 = Ebase + (size_t)lrow * HW + lch;
    const __half* eSrc1 = Ebase + (size_t)(lrow + 64) * HW + lch;
    const __half* gSrc0 = Gbase + (size_t)lrow * HW + lch;
    const __half* gSrc1 = Gbase + (size_t)(lrow + 64) * HW + lch;

    float acc[2][4][4] = {};

    // prologue: load chunk 0 into stage 0
    cp16(eDst, eSrc0);
    cp16(eDst + rdelta, eSrc1);
    cp16(gDst, gSrc0);
    cp16(gDst + rdelta, gSrc1);
    asm volatile("cp.async.commit_group;" ::: "memory");

    for (int it = 0; it < 64; it++) {
        const int s = it & 1;
        if (it + 1 < 64) {
            const int p1 = (it + 1) * 64;
            const uint32_t so = (s ^ 1) ? sdelta : 0u;
            cp16(eDst + so, eSrc0 + p1);
            cp16(eDst + so + rdelta, eSrc1 + p1);
            cp16(gDst + so, gSrc0 + p1);
            cp16(gDst + so + rdelta, gSrc1 + p1);
            asm volatile("cp.async.commit_group;" ::: "memory");
            asm volatile("cp.async.wait_group 1;" ::: "memory");
        } else {
            asm volatile("cp.async.wait_group 0;" ::: "memory");
        }
        __syncthreads();
        const uint32_t so = s ? sdelta : 0u;
#pragma unroll
        for (int kt = 0; kt < 4; kt++) {
            unsigned a[2][4], b[2][4];
            ldsm4(a[0], aAddr[0] + so + kt * 32);
            ldsm4(a[1], aAddr[1] + so + kt * 32);
            ldsm4(b[0], bAddr[0] + so + kt * 32);
            ldsm4(b[1], bAddr[1] + so + kt * 32);
#pragma unroll
            for (int mt = 0; mt < 2; mt++)
#pragma unroll
                for (int nt = 0; nt < 4; nt++)
                    mma16h(acc[mt][nt], a[mt][0], a[mt][1], a[mt][2], a[mt][3],
                           b[nt >> 1][(nt & 1) * 2], b[nt >> 1][(nt & 1) * 2 + 1]);
        }
        __syncthreads();
    }
    const float inv = 1.f / 4096.f;
    float* ab = g_att + (size_t)n * CI * HW;
#pragma unroll
    for (int mt = 0; mt < 2; mt++)
#pragma unroll
        for (int nt = 0; nt < 4; nt++)
#pragma unroll
            for (int i = 0; i < 2; i++)
#pragma unroll
                for (int j = 0; j < 2; j++) {
                    int q = q0 + wq + mt * 16 + gid + i * 8;
                    int c = c0 + wc + nt * 8 + 2 * t4 + j;
                    ab[(size_t)c * HW + q] = acc[mt][nt][i * 2 + j] * inv;
                }
}

// ---------------------------------------------------------------------------
// K4: epilogue.  att slab is exactly linear in (r*256+cc) per batch.
// ---------------------------------------------------------------------------
__global__ void k_out(const float* __restrict__ mask, const float* __restrict__ ref,
                      float* __restrict__ out) {
    const int total = NB * HW * (CI / 4);
    const int stride = gridDim.x * blockDim.x;
    for (int g = blockIdx.x * blockDim.x + threadIdx.x; g < total; g += stride) {
        int n = g >> 18;
        int rem = g & 262143;
        int r = rem >> 6;
        int c4 = (rem & 63) << 2;
        float4 a  = *(const float4*)(g_att + (size_t)n * CI * HW + (size_t)r * CI + c4);
        float4 rf = *(const float4*)(ref + ((size_t)n * HW + r) * CI + c4);
        float m = mask[n * HW + r];
        float4 e;
        e.x = m * a.x + (1.f - m) * rf.x;
        e.y = m * a.y + (1.f - m) * rf.y;
        e.z = m * a.z + (1.f - m) * rf.z;
        e.w = m * a.w + (1.f - m) * rf.w;
        size_t ob = ((size_t)n * HW + r) * (2 * CI);
        *(float4*)(out + ob + c4) = e;
        *(float4*)(out + ob + CI + c4) = a;
    }
}

extern "C" void kernel_launch(void* const* d_in, const int* in_sizes, int n_in,
                              void* d_out, int out_size) {
    const float* mask = (const float*)d_in[0];
    const float* F    = (const float*)d_in[1];
    const float* ref  = (const float*)d_in[2];
    const float* W    = (const float*)d_in[3];
    float* out = (float*)d_out;
    (void)in_sizes; (void)n_in; (void)out_size;

    cudaFuncSetAttribute(k_escore, cudaFuncAttributeMaxDynamicSharedMemorySize, K2_SMEM);
    cudaFuncSetAttribute(k_attf,   cudaFuncAttributeMaxDynamicSharedMemorySize, K5_SMEM);

    k_query<<<dim3(32, 8), 256>>>(F, W);
    k_norm1<<<dim3(32, 8), 128>>>();
    k_norm2<<<8, 32>>>();
    k_escore<<<dim3(32, 32, 8), 512, K2_SMEM>>>();
    k_zred<<<dim3(16, 8), 256>>>();
    k_gt<<<dim3(128, 8, 8), 256>>>(F);
    k_attf<<<dim3(32, 2, 8), 512, K5_SMEM>>>();
    k_out<<<2048, 256>>>(mask, ref, out);
}

// round 12
// speedup vs baseline: 2.7634x; 1.0356x over previous
#include <cuda_runtime.h>
#include <cuda_fp16.h>
#include <cstdint>
#include <cstddef>

#define NB 8
#define HW 4096
#define CI 256
#define DQ 64

// scratch (device globals -- no allocation allowed)
__device__ __half g_Qh[(size_t)NB * HW * DQ];     // fp16 Q, pre-scaled by sqrt(log2 e)
__device__ __half g_Eh[(size_t)NB * HW * HW];     // Eh[n][q][p] = half(2^(S - m[p] + 12))
__device__ __half g_Gt[(size_t)NB * CI * HW];     // G[n][c][p] = half(F[p][c] * 4096 * rZ[p])
__device__ float  g_Zp[(size_t)NB * 32 * HW];     // partial Z per q-block of 128
__device__ float  g_rZ[NB * HW];                  // 4096 / sum_q Eh[q,p]
__device__ float  g_rn[NB * HW];                  // row norms of Q (log2-scaled space)
__device__ float  g_Mp[NB * 32];                  // per-block partial max norms
__device__ float  g_M[NB];                        // max row norm per batch

static __device__ __forceinline__ float ex2f(float x) {
    float y; asm("ex2.approx.ftz.f32 %0, %1;" : "=f"(y) : "f"(x));
    return y;
}
static __device__ __forceinline__ void mma16h(float c[4], unsigned a0, unsigned a1, unsigned a2,
                                              unsigned a3, unsigned b0, unsigned b1) {
    asm volatile(
        "mma.sync.aligned.m16n8k16.row.col.f32.f16.f16.f32 "
        "{%0,%1,%2,%3},{%4,%5,%6,%7},{%8,%9},{%0,%1,%2,%3};"
        : "+f"(c[0]), "+f"(c[1]), "+f"(c[2]), "+f"(c[3])
        : "r"(a0), "r"(a1), "r"(a2), "r"(a3), "r"(b0), "r"(b1));
}
static __device__ __forceinline__ void ldsm4(unsigned r[4], uint32_t a) {
    asm volatile("ldmatrix.sync.aligned.m8n8.x4.shared.b16 {%0,%1,%2,%3}, [%4];"
                 : "=r"(r[0]), "=r"(r[1]), "=r"(r[2]), "=r"(r[3]) : "r"(a));
}
static __device__ __forceinline__ uint32_t smem_u32(const void* p) {
    return (uint32_t)__cvta_generic_to_shared(p);
}
static __device__ __forceinline__ void cp16(uint32_t dst, const void* src) {
    asm volatile("cp.async.cg.shared.global [%0], [%1], 16;" :: "r"(dst), "l"(src) : "memory");
}

// ---------------------------------------------------------------------------
// K1: Q = (F @ W) * sqrt(log2 e), fp32 FMA, stored fp16.
// ---------------------------------------------------------------------------
__global__ __launch_bounds__(256) void k_query(const float* __restrict__ F,
                                               const float* __restrict__ W) {
    __shared__ float A_s[32][132];
    __shared__ float W_s[32][68];
    const int tid = threadIdx.x;
    const int n = blockIdx.y, p0 = blockIdx.x * 128;
    const int tx = tid & 15, ty = tid >> 4;
    float acc[8][4];
#pragma unroll
    for (int i = 0; i < 8; i++)
#pragma unroll
        for (int j = 0; j < 4; j++) acc[i][j] = 0.f;
    const float* Fb = F + ((size_t)n * HW + p0) * CI;

    for (int kc = 0; kc < 8; kc++) {
        __syncthreads();
#pragma unroll
        for (int i = 0; i < 4; i++) {
            int idx = tid + i * 256;
            int row = idx >> 3, c4 = (idx & 7) * 4;
            float4 v = *(const float4*)(Fb + (size_t)row * CI + kc * 32 + c4);
            A_s[c4 + 0][row] = v.x; A_s[c4 + 1][row] = v.y;
            A_s[c4 + 2][row] = v.z; A_s[c4 + 3][row] = v.w;
        }
#pragma unroll
        for (int i = 0; i < 2; i++) {
            int idx = tid + i * 256;
            int row = idx >> 4, c4 = (idx & 15) * 4;
            *(float4*)&W_s[row][c4] = *(const float4*)(W + (kc * 32 + row) * DQ + c4);
        }
        __syncthreads();
#pragma unroll
        for (int k = 0; k < 32; k++) {
            float4 a0 = *(float4*)&A_s[k][8 * ty];
            float4 a1 = *(float4*)&A_s[k][8 * ty + 4];
            float4 b  = *(float4*)&W_s[k][4 * tx];
            float av[8] = {a0.x, a0.y, a0.z, a0.w, a1.x, a1.y, a1.z, a1.w};
            float bv[4] = {b.x, b.y, b.z, b.w};
#pragma unroll
            for (int i = 0; i < 8; i++)
#pragma unroll
                for (int j = 0; j < 4; j++) acc[i][j] += av[i] * bv[j];
        }
    }
    const float s = 1.2011224087864498f;  // sqrt(log2 e)
#pragma unroll
    for (int i = 0; i < 8; i++) {
        int p = p0 + 8 * ty + i;
        union { __half2 h[2]; uint2 u; } cv;
        cv.h[0] = __floats2half2_rn(acc[i][0] * s, acc[i][1] * s);
        cv.h[1] = __floats2half2_rn(acc[i][2] * s, acc[i][3] * s);
        *(uint2*)(g_Qh + ((size_t)n * HW + p) * DQ + 4 * tx) = cv.u;
    }
}

// ---------------------------------------------------------------------------
// K1b: row norms of Q (from the stored halves) + per-block max.
// ---------------------------------------------------------------------------
__global__ __launch_bounds__(128) void k_norm1() {
    __shared__ float mx[128];
    const int n = blockIdx.y, p = blockIdx.x * 128 + threadIdx.x;
    const __half2* q = (const __half2*)(g_Qh + (size_t)(n * HW + p) * DQ);
    float s = 0.f;
#pragma unroll
    for (int i = 0; i < 32; i++) {
        float2 f = __half22float2(q[i]);
        s += f.x * f.x + f.y * f.y;
    }
    float rn = sqrtf(s);
    g_rn[n * HW + p] = rn;
    mx[threadIdx.x] = rn;
    __syncthreads();
    for (int d = 64; d > 0; d >>= 1) {
        if (threadIdx.x < d) mx[threadIdx.x] = fmaxf(mx[threadIdx.x], mx[threadIdx.x + d]);
        __syncthreads();
    }
    if (threadIdx.x == 0) g_Mp[n * 32 + blockIdx.x] = mx[0];
}
__global__ void k_norm2() {
    const int n = blockIdx.x;
    float m = g_Mp[n * 32 + threadIdx.x];
#pragma unroll
    for (int d = 16; d > 0; d >>= 1) m = fmaxf(m, __shfl_xor_sync(0xffffffffu, m, d));
    if (threadIdx.x == 0) g_M[n] = m;
}

// ---------------------------------------------------------------------------
// K2: Eh[q,p] = half(2^(S - rn[p]*M + 12)) per 128x128 tile.  fp16 mma +
// ldmatrix feed; E tile staged in smem then stored coalesced uint4.
// Z summed from the same rounded halves via shfl.
// ---------------------------------------------------------------------------
#define K2_QP_OFF (128 * 72)
#define K2_ET_OFF (2 * 128 * 72)
#define K2_F32_OFF ((2 * 128 * 72 + 128 * 136) * 2)
#define K2_SMEM (K2_F32_OFF + (4 * 128 + 128) * 4)

__global__ __launch_bounds__(512, 2) void k_escore() {
    extern __shared__ char k2sm[];
    __half(*Qq)[72]  = (__half(*)[72])(k2sm);
    __half(*Qp)[72]  = (__half(*)[72])(k2sm + K2_QP_OFF * 2);
    __half(*Et)[136] = (__half(*)[136])(k2sm + K2_ET_OFF * 2);
    float* Zp        = (float*)(k2sm + K2_F32_OFF);
    float* ms        = Zp + 512;
    const int tid = threadIdx.x, w = tid >> 5, lane = tid & 31;
    const int gid = lane >> 2, t4 = lane & 3;
    const int qb = blockIdx.x, pb = blockIdx.y, n = blockIdx.z;
    const int q0 = qb * 128, p0 = pb * 128;
    const int m0 = (w & 3) * 32, n0 = (w >> 2) * 32;
    const __half* Qh = g_Qh + (size_t)n * HW * DQ;

#pragma unroll
    for (int i = 0; i < 2; i++) {
        int idx = tid + i * 512;
        int row = idx >> 3, ch = (idx & 7) * 8;
        *(uint4*)&Qq[row][ch] = *(const uint4*)(Qh + (size_t)(q0 + row) * DQ + ch);
        *(uint4*)&Qp[row][ch] = *(const uint4*)(Qh + (size_t)(p0 + row) * DQ + ch);
    }
    if (tid < 128) ms[tid] = 12.f - g_rn[n * HW + p0 + tid] * g_M[n];
    __syncthreads();

    const int l7 = lane & 7, lb3 = (lane >> 3) & 1, lb4 = lane >> 4;
    uint32_t aAddr[2], bAddr[2];
#pragma unroll
    for (int mt = 0; mt < 2; mt++)
        aAddr[mt] = smem_u32(&Qq[m0 + mt * 16 + l7 + lb3 * 8][lb4 * 8]);
#pragma unroll
    for (int ntp = 0; ntp < 2; ntp++)
        bAddr[ntp] = smem_u32(&Qp[n0 + ntp * 16 + l7 + lb4 * 8][lb3 * 8]);

    float acc[2][4][4] = {};
#pragma unroll
    for (int kt = 0; kt < 4; kt++) {
        unsigned a[2][4], b[2][4];
        ldsm4(a[0], aAddr[0] + kt * 32);
        ldsm4(a[1], aAddr[1] + kt * 32);
        ldsm4(b[0], bAddr[0] + kt * 32);
        ldsm4(b[1], bAddr[1] + kt * 32);
#pragma unroll
        for (int mt = 0; mt < 2; mt++)
#pragma unroll
            for (int nt = 0; nt < 4; nt++)
                mma16h(acc[mt][nt], a[mt][0], a[mt][1], a[mt][2], a[mt][3],
                       b[nt >> 1][(nt & 1) * 2], b[nt >> 1][(nt & 1) * 2 + 1]);
    }

    // exp + shift -> half, stage into smem tile, accumulate column sums
    float cs0[4], cs1[4];
#pragma unroll
    for (int nt = 0; nt < 4; nt++) { cs0[nt] = 0.f; cs1[nt] = 0.f; }
#pragma unroll
    for (int nt = 0; nt < 4; nt++) {
        int cb = n0 + nt * 8 + 2 * t4;
        float s0 = ms[cb], s1 = ms[cb + 1];
#pragma unroll
        for (int mt = 0; mt < 2; mt++) {
            int r = m0 + mt * 16 + gid;
            __half2 h0 = __floats2half2_rn(ex2f(acc[mt][nt][0] + s0), ex2f(acc[mt][nt][1] + s1));
            __half2 h1 = __floats2half2_rn(ex2f(acc[mt][nt][2] + s0), ex2f(acc[mt][nt][3] + s1));
            *(__half2*)&Et[r][cb] = h0;
            *(__half2*)&Et[r + 8][cb] = h1;
            float2 f0 = __half22float2(h0), f1 = __half22float2(h1);
            cs0[nt] += f0.x + f1.x;
            cs1[nt] += f0.y + f1.y;
        }
    }
#pragma unroll
    for (int nt = 0; nt < 4; nt++) {
        cs0[nt] += __shfl_xor_sync(0xffffffffu, cs0[nt], 4);
        cs0[nt] += __shfl_xor_sync(0xffffffffu, cs0[nt], 8);
        cs0[nt] += __shfl_xor_sync(0xffffffffu, cs0[nt], 16);
        cs1[nt] += __shfl_xor_sync(0xffffffffu, cs1[nt], 4);
        cs1[nt] += __shfl_xor_sync(0xffffffffu, cs1[nt], 8);
        cs1[nt] += __shfl_xor_sync(0xffffffffu, cs1[nt], 16);
    }
    if (lane < 4) {
#pragma unroll
        for (int nt = 0; nt < 4; nt++) {
            Zp[(w & 3) * 128 + n0 + nt * 8 + 2 * lane]     = cs0[nt];
            Zp[(w & 3) * 128 + n0 + nt * 8 + 2 * lane + 1] = cs1[nt];
        }
    }
    __syncthreads();
    __half* Eb = g_Eh + (size_t)n * HW * HW + (size_t)q0 * HW + p0;
#pragma unroll
    for (int i = 0; i < 4; i++) {
        int idx = tid + i * 512;
        int row = idx >> 4, ch = (idx & 15) * 8;
        *(uint4*)(Eb + (size_t)row * HW + ch) = *(uint4*)&Et[row][ch];
    }
    if (tid < 128) {
        float z = Zp[tid] + Zp[128 + tid] + Zp[256 + tid] + Zp[384 + tid];
        g_Zp[((size_t)n * 32 + qb) * HW + p0 + tid] = z;
    }
}

// ---------------------------------------------------------------------------
// K2b: rZ[p] = 4096 / sum over 32 q-block partials (fixed order).
// ---------------------------------------------------------------------------
__global__ void k_zred() {
    int p = blockIdx.x * 256 + threadIdx.x;
    int n = blockIdx.y;
    float z = 0.f;
#pragma unroll
    for (int qb = 0; qb < 32; qb++) z += g_Zp[((size_t)n * 32 + qb) * HW + p];
    g_rZ[n * HW + p] = 4096.f / z;
}

// ---------------------------------------------------------------------------
// K2c: G[c][p] = half(F[p][c] * rZ[p])  (transpose + fold, 32x32 tiles)
// ---------------------------------------------------------------------------
__global__ __launch_bounds__(256) void k_gt(const float* __restrict__ F) {
    __shared__ float t[32][33];
    __shared__ float rz[32];
    const int n = blockIdx.z, c0 = blockIdx.y * 32, p0 = blockIdx.x * 32;
    const int tx = threadIdx.x & 7, ty = threadIdx.x >> 3;
    const float* Fb = F + ((size_t)n * HW + p0) * CI;
    float4 v = *(const float4*)(Fb + (size_t)ty * CI + c0 + tx * 4);
    t[ty][tx * 4 + 0] = v.x; t[ty][tx * 4 + 1] = v.y;
    t[ty][tx * 4 + 2] = v.z; t[ty][tx * 4 + 3] = v.w;
    if (threadIdx.x < 32) rz[threadIdx.x] = g_rZ[n * HW + p0 + threadIdx.x];
    __syncthreads();
    const int cl = threadIdx.x >> 3, p4 = (threadIdx.x & 7) * 4;
    union { __half2 h[2]; uint2 u; } cv;
    cv.h[0] = __floats2half2_rn(t[p4 + 0][cl] * rz[p4 + 0], t[p4 + 1][cl] * rz[p4 + 1]);
    cv.h[1] = __floats2half2_rn(t[p4 + 2][cl] * rz[p4 + 2], t[p4 + 3][cl] * rz[p4 + 3]);
    *(uint2*)(g_Gt + ((size_t)n * CI + c0 + cl) * HW + p0 + p4) = cv.u;
}

// ---------------------------------------------------------------------------
// K3: PURE fp16 GEMM with FUSED output epilogue.
// att[q,c] = (sum_p Eh[q,p] * G[c,p]) / 4096, blended with mask/ref and
// written straight to out (no g_att round-trip).  Grid (c=2, q=32, n=8) so
// the two c-halves of the same E q-tile are co-resident -> E L2 reuse.
// Block 128q x 128c, k chunk 64, 2 stages, 512 threads, 2 CTAs/SM.
// ---------------------------------------------------------------------------
#define K5PAD 72
#define K5_STAGE (128 * K5PAD)              // halves per array per stage
#define K5_SMEM (4 * K5_STAGE * 2)          // bytes (E0,E1,G0,G1)

__global__ __launch_bounds__(512, 2) void k_attf(const float* __restrict__ mask,
                                                 const float* __restrict__ ref,
                                                 float* __restrict__ out) {
    extern __shared__ __half smh[];
    __half* Es0 = smh;
    __half* Gs0 = smh + 2 * K5_STAGE;
    const int tid = threadIdx.x, w = tid >> 5, lane = tid & 31;
    const int gid = lane >> 2, t4 = lane & 3;
    const int c0 = blockIdx.x * 128, q0 = blockIdx.y * 128, n = blockIdx.z;
    const int wq = (w & 3) * 32, wc = (w >> 2) * 32;
    const __half* Ebase = g_Eh + (size_t)n * HW * HW + (size_t)q0 * HW;
    const __half* Gbase = g_Gt + ((size_t)n * CI + c0) * HW;

    const int lrow = tid >> 3, lch = (tid & 7) * 8;  // rows lrow, lrow+64
    const int l7 = lane & 7, lb3 = (lane >> 3) & 1, lb4 = lane >> 4;
    uint32_t aAddr[2], bAddr[2];
#pragma unroll
    for (int mt = 0; mt < 2; mt++)
        aAddr[mt] = smem_u32(Es0 + (wq + mt * 16 + l7 + lb3 * 8) * K5PAD + lb4 * 8);
#pragma unroll
    for (int ntp = 0; ntp < 2; ntp++)
        bAddr[ntp] = smem_u32(Gs0 + (wc + ntp * 16 + l7 + lb4 * 8) * K5PAD + lb3 * 8);
    const uint32_t sdelta = K5_STAGE * 2;    // bytes between stages
    const uint32_t rdelta = 64 * K5PAD * 2;  // bytes between row lrow and lrow+64

    const uint32_t eDst = smem_u32(Es0 + lrow * K5PAD + lch);
    const uint32_t gDst = smem_u32(Gs0 + lrow * K5PAD + lch);
    const __half* eSrc0 = Ebase + (size_t)lrow * HW + lch;
    const __half* eSrc1 = Ebase + (size_t)(lrow + 64) * HW + lch;
    const __half* gSrc0 = Gbase + (size_t)lrow * HW + lch;
    const __half* gSrc1 = Gbase + (size_t)(lrow + 64) * HW + lch;

    float acc[2][4][4] = {};

    // prologue: load chunk 0 into stage 0
    cp16(eDst, eSrc0);
    cp16(eDst + rdelta, eSrc1);
    cp16(gDst, gSrc0);
    cp16(gDst + rdelta, gSrc1);
    asm volatile("cp.async.commit_group;" ::: "memory");

    for (int it = 0; it < 64; it++) {
        const int s = it & 1;
        if (it + 1 < 64) {
            const int p1 = (it + 1) * 64;
            const uint32_t so = (s ^ 1) ? sdelta : 0u;
            cp16(eDst + so, eSrc0 + p1);
            cp16(eDst + so + rdelta, eSrc1 + p1);
            cp16(gDst + so, gSrc0 + p1);
            cp16(gDst + so + rdelta, gSrc1 + p1);
            asm volatile("cp.async.commit_group;" ::: "memory");
            asm volatile("cp.async.wait_group 1;" ::: "memory");
        } else {
            asm volatile("cp.async.wait_group 0;" ::: "memory");
        }
        __syncthreads();
        const uint32_t so = s ? sdelta : 0u;
#pragma unroll
        for (int kt = 0; kt < 4; kt++) {
            unsigned a[2][4], b[2][4];
            ldsm4(a[0], aAddr[0] + so + kt * 32);
            ldsm4(a[1], aAddr[1] + so + kt * 32);
            ldsm4(b[0], bAddr[0] + so + kt * 32);
            ldsm4(b[1], bAddr[1] + so + kt * 32);
#pragma unroll
            for (int mt = 0; mt < 2; mt++)
#pragma unroll
                for (int nt = 0; nt < 4; nt++)
                    mma16h(acc[mt][nt], a[mt][0], a[mt][1], a[mt][2], a[mt][3],
                           b[nt >> 1][(nt & 1) * 2], b[nt >> 1][(nt & 1) * 2 + 1]);
        }
        __syncthreads();
    }

    // Fused epilogue.  For this q-tile (128 rows), q>>8 is constant:
    //   r  = c*16 + (q0>>8)   (out pixel)
    //   cc = q & 255          (out channel)
    const float inv = 1.f / 4096.f;
    const int qh8 = q0 >> 8;
    const float* refb = ref + (size_t)n * HW * CI;
    const float* maskb = mask + (size_t)n * HW;
    float* outb = out + (size_t)n * HW * (2 * CI);
#pragma unroll
    for (int mt = 0; mt < 2; mt++)
#pragma unroll
        for (int nt = 0; nt < 4; nt++)
#pragma unroll
            for (int i = 0; i < 2; i++)
#pragma unroll
                for (int j = 0; j < 2; j++) {
                    int q = q0 + wq + mt * 16 + gid + i * 8;
                    int c = c0 + wc + nt * 8 + 2 * t4 + j;
                    float a = acc[mt][nt][i * 2 + j] * inv;
                    int r = c * 16 + qh8;
                    int cc = q & 255;
                    float m = maskb[r];
                    float e = m * a + (1.f - m) * refb[(size_t)r * CI + cc];
                    size_t ob = (size_t)r * (2 * CI);
                    outb[ob + cc] = e;
                    outb[ob + CI + cc] = a;
                }
}

extern "C" void kernel_launch(void* const* d_in, const int* in_sizes, int n_in,
                              void* d_out, int out_size) {
    const float* mask = (const float*)d_in[0];
    const float* F    = (const float*)d_in[1];
    const float* ref  = (const float*)d_in[2];
    const float* W    = (const float*)d_in[3];
    float* out = (float*)d_out;
    (void)in_sizes; (void)n_in; (void)out_size;

    cudaFuncSetAttribute(k_escore, cudaFuncAttributeMaxDynamicSharedMemorySize, K2_SMEM);
    cudaFuncSetAttribute(k_attf,   cudaFuncAttributeMaxDynamicSharedMemorySize, K5_SMEM);

    k_query<<<dim3(32, 8), 256>>>(F, W);
    k_norm1<<<dim3(32, 8), 128>>>();
    k_norm2<<<8, 32>>>();
    k_escore<<<dim3(32, 32, 8), 512, K2_SMEM>>>();
    k_zred<<<dim3(16, 8), 256>>>();
    k_gt<<<dim3(128, 8, 8), 256>>>(F);
    k_attf<<<dim3(2, 32, 8), 512, K5_SMEM>>>(mask, ref, out);
}

// round 13
// speedup vs baseline: 2.8090x; 1.0165x over previous
#include <cuda_runtime.h>
#include <cuda_fp16.h>
#include <cstdint>
#include <cstddef>

#define NB 8
#define HW 4096
#define CI 256
#define DQ 64

// scratch (device globals -- no allocation allowed)
__device__ __half g_Qh[(size_t)NB * HW * DQ];     // fp16 Q, pre-scaled by sqrt(log2 e)
__device__ __half g_Eh[(size_t)NB * HW * HW];     // Eh[n][q][p] = half(2^(S - m[p] + 12))
__device__ __half g_Gt[(size_t)NB * CI * HW];     // G[n][c][p] = half(F[p][c] * 4096 * rZ[p])
__device__ float  g_Zp[(size_t)NB * 32 * HW];     // partial Z per q-block of 128
__device__ float  g_rZ[NB * HW];                  // 4096 / sum_q Eh[q,p]
__device__ float  g_rn[NB * HW];                  // row norms of Q (log2-scaled space)
__device__ float  g_Mp[NB * 32];                  // per-block partial max norms
__device__ float  g_M[NB];                        // max row norm per batch

static __device__ __forceinline__ float ex2f(float x) {
    float y; asm("ex2.approx.ftz.f32 %0, %1;" : "=f"(y) : "f"(x));
    return y;
}
static __device__ __forceinline__ void mma16h(float c[4], unsigned a0, unsigned a1, unsigned a2,
                                              unsigned a3, unsigned b0, unsigned b1) {
    asm volatile(
        "mma.sync.aligned.m16n8k16.row.col.f32.f16.f16.f32 "
        "{%0,%1,%2,%3},{%4,%5,%6,%7},{%8,%9},{%0,%1,%2,%3};"
        : "+f"(c[0]), "+f"(c[1]), "+f"(c[2]), "+f"(c[3])
        : "r"(a0), "r"(a1), "r"(a2), "r"(a3), "r"(b0), "r"(b1));
}
static __device__ __forceinline__ void ldsm4(unsigned r[4], uint32_t a) {
    asm volatile("ldmatrix.sync.aligned.m8n8.x4.shared.b16 {%0,%1,%2,%3}, [%4];"
                 : "=r"(r[0]), "=r"(r[1]), "=r"(r[2]), "=r"(r[3]) : "r"(a));
}
static __device__ __forceinline__ void stsm4(uint32_t a, unsigned r0, unsigned r1,
                                             unsigned r2, unsigned r3) {
    asm volatile("stmatrix.sync.aligned.m8n8.x4.shared.b16 [%0], {%1,%2,%3,%4};"
                 :: "r"(a), "r"(r0), "r"(r1), "r"(r2), "r"(r3) : "memory");
}
static __device__ __forceinline__ uint32_t smem_u32(const void* p) {
    return (uint32_t)__cvta_generic_to_shared(p);
}
static __device__ __forceinline__ void cp16(uint32_t dst, const void* src) {
    asm volatile("cp.async.cg.shared.global [%0], [%1], 16;" :: "r"(dst), "l"(src) : "memory");
}

// ---------------------------------------------------------------------------
// K1: Q = (F @ W) * sqrt(log2 e), fp16 mma (same fragment code as k_escore).
// Block 256 thr / 8 warps (4p x 2d), tile 128p x 64d, K=256 in chunks of 64.
// ---------------------------------------------------------------------------
__global__ __launch_bounds__(256) void k_query(const float* __restrict__ F,
                                               const float* __restrict__ W) {
    __shared__ __half Fs[128][72];
    __shared__ __half Ws[64][72];
    const int tid = threadIdx.x, w = tid >> 5, lane = tid & 31;
    const int gid = lane >> 2, t4 = lane & 3;
    const int n = blockIdx.y, p0 = blockIdx.x * 128;
    const int wq = (w & 3) * 32, wd = (w >> 2) * 32;
    const float* Fb = F + ((size_t)n * HW + p0) * CI;

    const int l7 = lane & 7, lb3 = (lane >> 3) & 1, lb4 = lane >> 4;
    uint32_t aAddr[2], bAddr[2];
#pragma unroll
    for (int mt = 0; mt < 2; mt++)
        aAddr[mt] = smem_u32(&Fs[wq + mt * 16 + l7 + lb3 * 8][lb4 * 8]);
#pragma unroll
    for (int ntp = 0; ntp < 2; ntp++)
        bAddr[ntp] = smem_u32(&Ws[wd + ntp * 16 + l7 + lb4 * 8][lb3 * 8]);

    float acc[2][4][4] = {};
    for (int kc = 0; kc < 4; kc++) {
        __syncthreads();
        // F chunk 128 x 64 fp32 -> fp16
#pragma unroll
        for (int i = 0; i < 8; i++) {
            int idx = tid + i * 256;
            int row = idx >> 4, c4 = (idx & 15) * 4;
            float4 v = *(const float4*)(Fb + (size_t)row * CI + kc * 64 + c4);
            *(__half2*)&Fs[row][c4]     = __floats2half2_rn(v.x, v.y);
            *(__half2*)&Fs[row][c4 + 2] = __floats2half2_rn(v.z, v.w);
        }
        // W chunk 64 x 64, transposed: Ws[d][ck]
#pragma unroll
        for (int i = 0; i < 16; i++) {
            int idx = tid + i * 256;
            int ck = idx >> 6, d = idx & 63;
            Ws[d][ck] = __float2half(W[(size_t)(kc * 64 + ck) * DQ + d]);
        }
        __syncthreads();
#pragma unroll
        for (int kt = 0; kt < 4; kt++) {
            unsigned a[2][4], b[2][4];
            ldsm4(a[0], aAddr[0] + kt * 32);
            ldsm4(a[1], aAddr[1] + kt * 32);
            ldsm4(b[0], bAddr[0] + kt * 32);
            ldsm4(b[1], bAddr[1] + kt * 32);
#pragma unroll
            for (int mt = 0; mt < 2; mt++)
#pragma unroll
                for (int nt = 0; nt < 4; nt++)
                    mma16h(acc[mt][nt], a[mt][0], a[mt][1], a[mt][2], a[mt][3],
                           b[nt >> 1][(nt & 1) * 2], b[nt >> 1][(nt & 1) * 2 + 1]);
        }
    }
    const float s = 1.2011224087864498f;  // sqrt(log2 e)
    __half* Qb = g_Qh + (size_t)n * HW * DQ;
#pragma unroll
    for (int mt = 0; mt < 2; mt++)
#pragma unroll
        for (int nt = 0; nt < 4; nt++) {
            int p = p0 + wq + mt * 16 + gid;
            int d = wd + nt * 8 + 2 * t4;
            *(__half2*)(Qb + (size_t)p * DQ + d) =
                __floats2half2_rn(acc[mt][nt][0] * s, acc[mt][nt][1] * s);
            *(__half2*)(Qb + (size_t)(p + 8) * DQ + d) =
                __floats2half2_rn(acc[mt][nt][2] * s, acc[mt][nt][3] * s);
        }
}

// ---------------------------------------------------------------------------
// K1b: row norms of Q (from the stored halves) + per-block max.
// ---------------------------------------------------------------------------
__global__ __launch_bounds__(128) void k_norm1() {
    __shared__ float mx[128];
    const int n = blockIdx.y, p = blockIdx.x * 128 + threadIdx.x;
    const __half2* q = (const __half2*)(g_Qh + (size_t)(n * HW + p) * DQ);
    float s = 0.f;
#pragma unroll
    for (int i = 0; i < 32; i++) {
        float2 f = __half22float2(q[i]);
        s += f.x * f.x + f.y * f.y;
    }
    float rn = sqrtf(s);
    g_rn[n * HW + p] = rn;
    mx[threadIdx.x] = rn;
    __syncthreads();
    for (int d = 64; d > 0; d >>= 1) {
        if (threadIdx.x < d) mx[threadIdx.x] = fmaxf(mx[threadIdx.x], mx[threadIdx.x + d]);
        __syncthreads();
    }
    if (threadIdx.x == 0) g_Mp[n * 32 + blockIdx.x] = mx[0];
}
__global__ void k_norm2() {
    const int n = blockIdx.x;
    float m = g_Mp[n * 32 + threadIdx.x];
#pragma unroll
    for (int d = 16; d > 0; d >>= 1) m = fmaxf(m, __shfl_xor_sync(0xffffffffu, m, d));
    if (threadIdx.x == 0) g_M[n] = m;
}

// ---------------------------------------------------------------------------
// K2: Eh[q,p] = half(2^(S - rn[p]*M + 12)) per 128x128 tile.  fp16 mma +
// ldmatrix feed; epilogue via stmatrix.x4 into the smem tile (conflict-free,
// pad 136 = 68 words = 4 mod 32), then coalesced uint4 copy-out.
// Z summed from the same rounded halves via shfl.
// ---------------------------------------------------------------------------
#define K2_QP_OFF (128 * 72)
#define K2_ET_OFF (2 * 128 * 72)
#define K2_F32_OFF ((2 * 128 * 72 + 128 * 136) * 2)
#define K2_SMEM (K2_F32_OFF + (4 * 128 + 128) * 4)

__global__ __launch_bounds__(512, 2) void k_escore() {
    extern __shared__ char k2sm[];
    __half(*Qq)[72]  = (__half(*)[72])(k2sm);
    __half(*Qp)[72]  = (__half(*)[72])(k2sm + K2_QP_OFF * 2);
    __half(*Et)[136] = (__half(*)[136])(k2sm + K2_ET_OFF * 2);
    float* Zp        = (float*)(k2sm + K2_F32_OFF);
    float* ms        = Zp + 512;
    const int tid = threadIdx.x, w = tid >> 5, lane = tid & 31;
    const int gid = lane >> 2, t4 = lane & 3;
    const int qb = blockIdx.x, pb = blockIdx.y, n = blockIdx.z;
    const int q0 = qb * 128, p0 = pb * 128;
    const int m0 = (w & 3) * 32, n0 = (w >> 2) * 32;
    const __half* Qh = g_Qh + (size_t)n * HW * DQ;

#pragma unroll
    for (int i = 0; i < 2; i++) {
        int idx = tid + i * 512;
        int row = idx >> 3, ch = (idx & 7) * 8;
        *(uint4*)&Qq[row][ch] = *(const uint4*)(Qh + (size_t)(q0 + row) * DQ + ch);
        *(uint4*)&Qp[row][ch] = *(const uint4*)(Qh + (size_t)(p0 + row) * DQ + ch);
    }
    if (tid < 128) ms[tid] = 12.f - g_rn[n * HW + p0 + tid] * g_M[n];
    __syncthreads();

    const int l7 = lane & 7, lb3 = (lane >> 3) & 1, lb4 = lane >> 4;
    uint32_t aAddr[2], bAddr[2];
#pragma unroll
    for (int mt = 0; mt < 2; mt++)
        aAddr[mt] = smem_u32(&Qq[m0 + mt * 16 + l7 + lb3 * 8][lb4 * 8]);
#pragma unroll
    for (int ntp = 0; ntp < 2; ntp++)
        bAddr[ntp] = smem_u32(&Qp[n0 + ntp * 16 + l7 + lb4 * 8][lb3 * 8]);

    float acc[2][4][4] = {};
#pragma unroll
    for (int kt = 0; kt < 4; kt++) {
        unsigned a[2][4], b[2][4];
        ldsm4(a[0], aAddr[0] + kt * 32);
        ldsm4(a[1], aAddr[1] + kt * 32);
        ldsm4(b[0], bAddr[0] + kt * 32);
        ldsm4(b[1], bAddr[1] + kt * 32);
#pragma unroll
        for (int mt = 0; mt < 2; mt++)
#pragma unroll
            for (int nt = 0; nt < 4; nt++)
                mma16h(acc[mt][nt], a[mt][0], a[mt][1], a[mt][2], a[mt][3],
                       b[nt >> 1][(nt & 1) * 2], b[nt >> 1][(nt & 1) * 2 + 1]);
    }

    // exp + shift -> half2 regs; column sums; then stmatrix into Et
    float cs0[4], cs1[4];
    unsigned uh[2][4][2];
#pragma unroll
    for (int nt = 0; nt < 4; nt++) { cs0[nt] = 0.f; cs1[nt] = 0.f; }
#pragma unroll
    for (int nt = 0; nt < 4; nt++) {
        int cb = n0 + nt * 8 + 2 * t4;
        float s0 = ms[cb], s1 = ms[cb + 1];
#pragma unroll
        for (int mt = 0; mt < 2; mt++) {
            __half2 h0 = __floats2half2_rn(ex2f(acc[mt][nt][0] + s0), ex2f(acc[mt][nt][1] + s1));
            __half2 h1 = __floats2half2_rn(ex2f(acc[mt][nt][2] + s0), ex2f(acc[mt][nt][3] + s1));
            uh[mt][nt][0] = reinterpret_cast<unsigned&>(h0);
            uh[mt][nt][1] = reinterpret_cast<unsigned&>(h1);
            float2 f0 = __half22float2(h0), f1 = __half22float2(h1);
            cs0[nt] += f0.x + f1.x;
            cs1[nt] += f0.y + f1.y;
        }
    }
#pragma unroll
    for (int nt = 0; nt < 4; nt++) {
        cs0[nt] += __shfl_xor_sync(0xffffffffu, cs0[nt], 4);
        cs0[nt] += __shfl_xor_sync(0xffffffffu, cs0[nt], 8);
        cs0[nt] += __shfl_xor_sync(0xffffffffu, cs0[nt], 16);
        cs1[nt] += __shfl_xor_sync(0xffffffffu, cs1[nt], 4);
        cs1[nt] += __shfl_xor_sync(0xffffffffu, cs1[nt], 8);
        cs1[nt] += __shfl_xor_sync(0xffffffffu, cs1[nt], 16);
    }
    if (lane < 4) {
#pragma unroll
        for (int nt = 0; nt < 4; nt++) {
            Zp[(w & 3) * 128 + n0 + nt * 8 + 2 * lane]     = cs0[nt];
            Zp[(w & 3) * 128 + n0 + nt * 8 + 2 * lane + 1] = cs1[nt];
        }
    }
    // stmatrix: 4 x STSM.x4 per warp (2 mt x 2 np 16x16 blocks)
    {
        const int kk = lane >> 3, rr = lane & 7;
#pragma unroll
        for (int mt = 0; mt < 2; mt++)
#pragma unroll
            for (int np = 0; np < 2; np++) {
                uint32_t ad = smem_u32(&Et[m0 + mt * 16 + (kk & 1) * 8 + rr]
                                          [n0 + np * 16 + (kk >> 1) * 8]);
                stsm4(ad, uh[mt][2 * np][0], uh[mt][2 * np][1],
                      uh[mt][2 * np + 1][0], uh[mt][2 * np + 1][1]);
            }
    }
    __syncthreads();
    __half* Eb = g_Eh + (size_t)n * HW * HW + (size_t)q0 * HW + p0;
#pragma unroll
    for (int i = 0; i < 4; i++) {
        int idx = tid + i * 512;
        int row = idx >> 4, ch = (idx & 15) * 8;
        *(uint4*)(Eb + (size_t)row * HW + ch) = *(uint4*)&Et[row][ch];
    }
    if (tid < 128) {
        float z = Zp[tid] + Zp[128 + tid] + Zp[256 + tid] + Zp[384 + tid];
        g_Zp[((size_t)n * 32 + qb) * HW + p0 + tid] = z;
    }
}

// ---------------------------------------------------------------------------
// K2b: rZ[p] = 4096 / sum over 32 q-block partials (fixed order).
// ---------------------------------------------------------------------------
__global__ void k_zred() {
    int p = blockIdx.x * 256 + threadIdx.x;
    int n = blockIdx.y;
    float z = 0.f;
#pragma unroll
    for (int qb = 0; qb < 32; qb++) z += g_Zp[((size_t)n * 32 + qb) * HW + p];
    g_rZ[n * HW + p] = 4096.f / z;
}

// ---------------------------------------------------------------------------
// K2c: G[c][p] = half(F[p][c] * rZ[p])  (transpose + fold, 32x32 tiles)
// ---------------------------------------------------------------------------
__global__ __launch_bounds__(256) void k_gt(const float* __restrict__ F) {
    __shared__ float t[32][33];
    __shared__ float rz[32];
    const int n = blockIdx.z, c0 = blockIdx.y * 32, p0 = blockIdx.x * 32;
    const int tx = threadIdx.x & 7, ty = threadIdx.x >> 3;
    const float* Fb = F + ((size_t)n * HW + p0) * CI;
    float4 v = *(const float4*)(Fb + (size_t)ty * CI + c0 + tx * 4);
    t[ty][tx * 4 + 0] = v.x; t[ty][tx * 4 + 1] = v.y;
    t[ty][tx * 4 + 2] = v.z; t[ty][tx * 4 + 3] = v.w;
    if (threadIdx.x < 32) rz[threadIdx.x] = g_rZ[n * HW + p0 + threadIdx.x];
    __syncthreads();
    const int cl = threadIdx.x >> 3, p4 = (threadIdx.x & 7) * 4;
    union { __half2 h[2]; uint2 u; } cv;
    cv.h[0] = __floats2half2_rn(t[p4 + 0][cl] * rz[p4 + 0], t[p4 + 1][cl] * rz[p4 + 1]);
    cv.h[1] = __floats2half2_rn(t[p4 + 2][cl] * rz[p4 + 2], t[p4 + 3][cl] * rz[p4 + 3]);
    *(uint2*)(g_Gt + ((size_t)n * CI + c0 + cl) * HW + p0 + p4) = cv.u;
}

// ---------------------------------------------------------------------------
// K3: PURE fp16 GEMM, 3-stage cp.async pipeline, ONE sync per iteration,
// FUSED output epilogue.  Block 128q x 128c, k chunk 64, 512 threads,
// 2 CTAs/SM.  Grid (c=2, q=32, n=8).
// ---------------------------------------------------------------------------
#define K5PAD 72
#define K5_STAGE (2 * 128 * K5PAD)          // halves per stage (E + G)
#define K5_SMEM (3 * K5_STAGE * 2)          // 110592 bytes

__global__ __launch_bounds__(512, 2) void k_attf(const float* __restrict__ mask,
                                                 const float* __restrict__ ref,
                                                 float* __restrict__ out) {
    extern __shared__ __half smh[];
    __half* Es0 = smh;                       // stage 0: E at 0, G at 128*K5PAD
    __half* Gs0 = smh + 128 * K5PAD;
    const int tid = threadIdx.x, w = tid >> 5, lane = tid & 31;
    const int gid = lane >> 2, t4 = lane & 3;
    const int c0 = blockIdx.x * 128, q0 = blockIdx.y * 128, n = blockIdx.z;
    const int wq = (w & 3) * 32, wc = (w >> 2) * 32;
    const __half* Ebase = g_Eh + (size_t)n * HW * HW + (size_t)q0 * HW;
    const __half* Gbase = g_Gt + ((size_t)n * CI + c0) * HW;

    const int lrow = tid >> 3, lch = (tid & 7) * 8;  // rows lrow, lrow+64
    const int l7 = lane & 7, lb3 = (lane >> 3) & 1, lb4 = lane >> 4;
    uint32_t aAddr[2], bAddr[2];
#pragma unroll
    for (int mt = 0; mt < 2; mt++)
        aAddr[mt] = smem_u32(Es0 + (wq + mt * 16 + l7 + lb3 * 8) * K5PAD + lb4 * 8);
#pragma unroll
    for (int ntp = 0; ntp < 2; ntp++)
        bAddr[ntp] = smem_u32(Gs0 + (wc + ntp * 16 + l7 + lb4 * 8) * K5PAD + lb3 * 8);
    const uint32_t sdelta = K5_STAGE * 2;    // bytes between stages
    const uint32_t rdelta = 64 * K5PAD * 2;  // bytes between row lrow and lrow+64

    const uint32_t eDst = smem_u32(Es0 + lrow * K5PAD + lch);
    const uint32_t gDst = smem_u32(Gs0 + lrow * K5PAD + lch);
    const __half* eSrc0 = Ebase + (size_t)lrow * HW + lch;
    const __half* eSrc1 = Ebase + (size_t)(lrow + 64) * HW + lch;
    const __half* gSrc0 = Gbase + (size_t)lrow * HW + lch;
    const __half* gSrc1 = Gbase + (size_t)(lrow + 64) * HW + lch;

    float acc[2][4][4] = {};

    // prologue: chunks 0,1 into stages 0,1
#pragma unroll
    for (int s = 0; s < 2; s++) {
        const uint32_t so = s * sdelta;
        const int pp = s * 64;
        cp16(eDst + so, eSrc0 + pp);
        cp16(eDst + so + rdelta, eSrc1 + pp);
        cp16(gDst + so, gSrc0 + pp);
        cp16(gDst + so + rdelta, gSrc1 + pp);
        asm volatile("cp.async.commit_group;" ::: "memory");
    }

    int cur = 0, nxt = 2;  // stage of iteration it, stage for it+2
    for (int it = 0; it < 64; it++) {
        asm volatile("cp.async.wait_group 1;" ::: "memory");
        __syncthreads();
        if (it + 2 < 64) {
            const int pp = (it + 2) * 64;
            const uint32_t so = nxt * sdelta;
            cp16(eDst + so, eSrc0 + pp);
            cp16(eDst + so + rdelta, eSrc1 + pp);
            cp16(gDst + so, gSrc0 + pp);
            cp16(gDst + so + rdelta, gSrc1 + pp);
        }
        asm volatile("cp.async.commit_group;" ::: "memory");
        const uint32_t so = cur * sdelta;
#pragma unroll
        for (int kt = 0; kt < 4; kt++) {
            unsigned a[2][4], b[2][4];
            ldsm4(a[0], aAddr[0] + so + kt * 32);
            ldsm4(a[1], aAddr[1] + so + kt * 32);
            ldsm4(b[0], bAddr[0] + so + kt * 32);
            ldsm4(b[1], bAddr[1] + so + kt * 32);
#pragma unroll
            for (int mt = 0; mt < 2; mt++)
#pragma unroll
                for (int nt = 0; nt < 4; nt++)
                    mma16h(acc[mt][nt], a[mt][0], a[mt][1], a[mt][2], a[mt][3],
                           b[nt >> 1][(nt & 1) * 2], b[nt >> 1][(nt & 1) * 2 + 1]);
        }
        cur = (cur == 2) ? 0 : cur + 1;
        nxt = (nxt == 2) ? 0 : nxt + 1;
    }

    // Fused epilogue: r = c*16 + (q0>>8), cc = q & 255.
    const float inv = 1.f / 4096.f;
    const int qh8 = q0 >> 8;
    const float* refb = ref + (size_t)n * HW * CI;
    const float* maskb = mask + (size_t)n * HW;
    float* outb = out + (size_t)n * HW * (2 * CI);
#pragma unroll
    for (int mt = 0; mt < 2; mt++)
#pragma unroll
        for (int nt = 0; nt < 4; nt++)
#pragma unroll
            for (int i = 0; i < 2; i++)
#pragma unroll
                for (int j = 0; j < 2; j++) {
                    int q = q0 + wq + mt * 16 + gid + i * 8;
                    int c = c0 + wc + nt * 8 + 2 * t4 + j;
                    float a = acc[mt][nt][i * 2 + j] * inv;
                    int r = c * 16 + qh8;
                    int cc = q & 255;
                    float m = maskb[r];
                    float e = m * a + (1.f - m) * refb[(size_t)r * CI + cc];
                    size_t ob = (size_t)r * (2 * CI);
                    outb[ob + cc] = e;
                    outb[ob + CI + cc] = a;
                }
}

extern "C" void kernel_launch(void* const* d_in, const int* in_sizes, int n_in,
                              void* d_out, int out_size) {
    const float* mask = (const float*)d_in[0];
    const float* F    = (const float*)d_in[1];
    const float* ref  = (const float*)d_in[2];
    const float* W    = (const float*)d_in[3];
    float* out = (float*)d_out;
    (void)in_sizes; (void)n_in; (void)out_size;

    cudaFuncSetAttribute(k_escore, cudaFuncAttributeMaxDynamicSharedMemorySize, K2_SMEM);
    cudaFuncSetAttribute(k_attf,   cudaFuncAttributeMaxDynamicSharedMemorySize, K5_SMEM);

    k_query<<<dim3(32, 8), 256>>>(F, W);
    k_norm1<<<dim3(32, 8), 128>>>();
    k_norm2<<<8, 32>>>();
    k_escore<<<dim3(32, 32, 8), 512, K2_SMEM>>>();
    k_zred<<<dim3(16, 8), 256>>>();
    k_gt<<<dim3(128, 8, 8), 256>>>(F);
    k_attf<<<dim3(2, 32, 8), 512, K5_SMEM>>>(mask, ref, out);
}

// round 15
// speedup vs baseline: 2.8604x; 1.0183x over previous
#include <cuda_runtime.h>
#include <cuda_fp16.h>
#include <cstdint>
#include <cstddef>

#define NB 8
#define HW 4096
#define CI 256
#define DQ 64

// scratch (device globals -- no allocation allowed)
__device__ __half g_Qh[(size_t)NB * HW * DQ];     // fp16 Q, pre-scaled by sqrt(log2 e)
__device__ __half g_Eh[(size_t)NB * HW * HW];     // Eh[n][q][p] = half(2^(S - m[p] + 12))
__device__ __half g_Gt[(size_t)NB * CI * HW];     // G[n][c][p] = half(F[p][c] * 4096 * rZ[p])
__device__ float  g_Zp[(size_t)NB * 32 * HW];     // partial Z per q-block of 128
__device__ float  g_rZ[NB * HW];                  // 4096 / sum_q Eh[q,p]
__device__ float  g_rn[NB * HW];                  // row norms of Q (log2-scaled space)
__device__ float  g_Mp[NB * 32];                  // per-block partial max norms
__device__ float  g_M[NB];                        // max row norm per batch

static __device__ __forceinline__ float ex2f(float x) {
    float y; asm("ex2.approx.ftz.f32 %0, %1;" : "=f"(y) : "f"(x));
    return y;
}
static __device__ __forceinline__ void mma16h(float c[4], unsigned a0, unsigned a1, unsigned a2,
                                              unsigned a3, unsigned b0, unsigned b1) {
    asm volatile(
        "mma.sync.aligned.m16n8k16.row.col.f32.f16.f16.f32 "
        "{%0,%1,%2,%3},{%4,%5,%6,%7},{%8,%9},{%0,%1,%2,%3};"
        : "+f"(c[0]), "+f"(c[1]), "+f"(c[2]), "+f"(c[3])
        : "r"(a0), "r"(a1), "r"(a2), "r"(a3), "r"(b0), "r"(b1));
}
static __device__ __forceinline__ void ldsm4(unsigned r[4], uint32_t a) {
    asm volatile("ldmatrix.sync.aligned.m8n8.x4.shared.b16 {%0,%1,%2,%3}, [%4];"
                 : "=r"(r[0]), "=r"(r[1]), "=r"(r[2]), "=r"(r[3]) : "r"(a));
}
static __device__ __forceinline__ void stsm4(uint32_t a, unsigned r0, unsigned r1,
                                             unsigned r2, unsigned r3) {
    asm volatile("stmatrix.sync.aligned.m8n8.x4.shared.b16 [%0], {%1,%2,%3,%4};"
                 :: "r"(a), "r"(r0), "r"(r1), "r"(r2), "r"(r3) : "memory");
}
static __device__ __forceinline__ uint32_t smem_u32(const void* p) {
    return (uint32_t)__cvta_generic_to_shared(p);
}
static __device__ __forceinline__ void cp16(uint32_t dst, const void* src) {
    asm volatile("cp.async.cg.shared.global [%0], [%1], 16;" :: "r"(dst), "l"(src) : "memory");
}

// ---------------------------------------------------------------------------
// K1: Q = (F @ W) * sqrt(log2 e), fp16 mma.
// ---------------------------------------------------------------------------
__global__ __launch_bounds__(256) void k_query(const float* __restrict__ F,
                                               const float* __restrict__ W) {
    __shared__ __half Fs[128][72];
    __shared__ __half Ws[64][72];
    const int tid = threadIdx.x, w = tid >> 5, lane = tid & 31;
    const int gid = lane >> 2, t4 = lane & 3;
    const int n = blockIdx.y, p0 = blockIdx.x * 128;
    const int wq = (w & 3) * 32, wd = (w >> 2) * 32;
    const float* Fb = F + ((size_t)n * HW + p0) * CI;

    const int l7 = lane & 7, lb3 = (lane >> 3) & 1, lb4 = lane >> 4;
    uint32_t aAddr[2], bAddr[2];
#pragma unroll
    for (int mt = 0; mt < 2; mt++)
        aAddr[mt] = smem_u32(&Fs[wq + mt * 16 + l7 + lb3 * 8][lb4 * 8]);
#pragma unroll
    for (int ntp = 0; ntp < 2; ntp++)
        bAddr[ntp] = smem_u32(&Ws[wd + ntp * 16 + l7 + lb4 * 8][lb3 * 8]);

    float acc[2][4][4] = {};
    for (int kc = 0; kc < 4; kc++) {
        __syncthreads();
#pragma unroll
        for (int i = 0; i < 8; i++) {
            int idx = tid + i * 256;
            int row = idx >> 4, c4 = (idx & 15) * 4;
            float4 v = *(const float4*)(Fb + (size_t)row * CI + kc * 64 + c4);
            *(__half2*)&Fs[row][c4]     = __floats2half2_rn(v.x, v.y);
            *(__half2*)&Fs[row][c4 + 2] = __floats2half2_rn(v.z, v.w);
        }
#pragma unroll
        for (int i = 0; i < 16; i++) {
            int idx = tid + i * 256;
            int ck = idx >> 6, d = idx & 63;
            Ws[d][ck] = __float2half(W[(size_t)(kc * 64 + ck) * DQ + d]);
        }
        __syncthreads();
#pragma unroll
        for (int kt = 0; kt < 4; kt++) {
            unsigned a[2][4], b[2][4];
            ldsm4(a[0], aAddr[0] + kt * 32);
            ldsm4(a[1], aAddr[1] + kt * 32);
            ldsm4(b[0], bAddr[0] + kt * 32);
            ldsm4(b[1], bAddr[1] + kt * 32);
#pragma unroll
            for (int mt = 0; mt < 2; mt++)
#pragma unroll
                for (int nt = 0; nt < 4; nt++)
                    mma16h(acc[mt][nt], a[mt][0], a[mt][1], a[mt][2], a[mt][3],
                           b[nt >> 1][(nt & 1) * 2], b[nt >> 1][(nt & 1) * 2 + 1]);
        }
    }
    const float s = 1.2011224087864498f;  // sqrt(log2 e)
    __half* Qb = g_Qh + (size_t)n * HW * DQ;
#pragma unroll
    for (int mt = 0; mt < 2; mt++)
#pragma unroll
        for (int nt = 0; nt < 4; nt++) {
            int p = p0 + wq + mt * 16 + gid;
            int d = wd + nt * 8 + 2 * t4;
            *(__half2*)(Qb + (size_t)p * DQ + d) =
                __floats2half2_rn(acc[mt][nt][0] * s, acc[mt][nt][1] * s);
            *(__half2*)(Qb + (size_t)(p + 8) * DQ + d) =
                __floats2half2_rn(acc[mt][nt][2] * s, acc[mt][nt][3] * s);
        }
}

// ---------------------------------------------------------------------------
// K1b: row norms of Q + per-block max.
// ---------------------------------------------------------------------------
__global__ __launch_bounds__(128) void k_norm1() {
    __shared__ float mx[128];
    const int n = blockIdx.y, p = blockIdx.x * 128 + threadIdx.x;
    const __half2* q = (const __half2*)(g_Qh + (size_t)(n * HW + p) * DQ);
    float s = 0.f;
#pragma unroll
    for (int i = 0; i < 32; i++) {
        float2 f = __half22float2(q[i]);
        s += f.x * f.x + f.y * f.y;
    }
    float rn = sqrtf(s);
    g_rn[n * HW + p] = rn;
    mx[threadIdx.x] = rn;
    __syncthreads();
    for (int d = 64; d > 0; d >>= 1) {
        if (threadIdx.x < d) mx[threadIdx.x] = fmaxf(mx[threadIdx.x], mx[threadIdx.x + d]);
        __syncthreads();
    }
    if (threadIdx.x == 0) g_Mp[n * 32 + blockIdx.x] = mx[0];
}
__global__ void k_norm2() {
    const int n = blockIdx.x;
    float m = g_Mp[n * 32 + threadIdx.x];
#pragma unroll
    for (int d = 16; d > 0; d >>= 1) m = fmaxf(m, __shfl_xor_sync(0xffffffffu, m, d));
    if (threadIdx.x == 0) g_M[n] = m;
}

// ---------------------------------------------------------------------------
// K2: Eh[q,p] = half(2^(S - rn[p]*M + 12)) per 128x128 tile.
// ---------------------------------------------------------------------------
#define K2_QP_OFF (128 * 72)
#define K2_ET_OFF (2 * 128 * 72)
#define K2_F32_OFF ((2 * 128 * 72 + 128 * 136) * 2)
#define K2_SMEM (K2_F32_OFF + (4 * 128 + 128) * 4)

__global__ __launch_bounds__(512, 2) void k_escore() {
    extern __shared__ char k2sm[];
    __half(*Qq)[72]  = (__half(*)[72])(k2sm);
    __half(*Qp)[72]  = (__half(*)[72])(k2sm + K2_QP_OFF * 2);
    __half(*Et)[136] = (__half(*)[136])(k2sm + K2_ET_OFF * 2);
    float* Zp        = (float*)(k2sm + K2_F32_OFF);
    float* ms        = Zp + 512;
    const int tid = threadIdx.x, w = tid >> 5, lane = tid & 31;
    const int gid = lane >> 2, t4 = lane & 3;
    const int qb = blockIdx.x, pb = blockIdx.y, n = blockIdx.z;
    const int q0 = qb * 128, p0 = pb * 128;
    const int m0 = (w & 3) * 32, n0 = (w >> 2) * 32;
    const __half* Qh = g_Qh + (size_t)n * HW * DQ;

#pragma unroll
    for (int i = 0; i < 2; i++) {
        int idx = tid + i * 512;
        int row = idx >> 3, ch = (idx & 7) * 8;
        *(uint4*)&Qq[row][ch] = *(const uint4*)(Qh + (size_t)(q0 + row) * DQ + ch);
        *(uint4*)&Qp[row][ch] = *(const uint4*)(Qh + (size_t)(p0 + row) * DQ + ch);
    }
    if (tid < 128) ms[tid] = 12.f - g_rn[n * HW + p0 + tid] * g_M[n];
    __syncthreads();

    const int l7 = lane & 7, lb3 = (lane >> 3) & 1, lb4 = lane >> 4;
    uint32_t aAddr[2], bAddr[2];
#pragma unroll
    for (int mt = 0; mt < 2; mt++)
        aAddr[mt] = smem_u32(&Qq[m0 + mt * 16 + l7 + lb3 * 8][lb4 * 8]);
#pragma unroll
    for (int ntp = 0; ntp < 2; ntp++)
        bAddr[ntp] = smem_u32(&Qp[n0 + ntp * 16 + l7 + lb4 * 8][lb3 * 8]);

    float acc[2][4][4] = {};
#pragma unroll
    for (int kt = 0; kt < 4; kt++) {
        unsigned a[2][4], b[2][4];
        ldsm4(a[0], aAddr[0] + kt * 32);
        ldsm4(a[1], aAddr[1] + kt * 32);
        ldsm4(b[0], bAddr[0] + kt * 32);
        ldsm4(b[1], bAddr[1] + kt * 32);
#pragma unroll
        for (int mt = 0; mt < 2; mt++)
#pragma unroll
            for (int nt = 0; nt < 4; nt++)
                mma16h(acc[mt][nt], a[mt][0], a[mt][1], a[mt][2], a[mt][3],
                       b[nt >> 1][(nt & 1) * 2], b[nt >> 1][(nt & 1) * 2 + 1]);
    }

    float cs0[4], cs1[4];
    unsigned uh[2][4][2];
#pragma unroll
    for (int nt = 0; nt < 4; nt++) { cs0[nt] = 0.f; cs1[nt] = 0.f; }
#pragma unroll
    for (int nt = 0; nt < 4; nt++) {
        int cb = n0 + nt * 8 + 2 * t4;
        float s0 = ms[cb], s1 = ms[cb + 1];
#pragma unroll
        for (int mt = 0; mt < 2; mt++) {
            __half2 h0 = __floats2half2_rn(ex2f(acc[mt][nt][0] + s0), ex2f(acc[mt][nt][1] + s1));
            __half2 h1 = __floats2half2_rn(ex2f(acc[mt][nt][2] + s0), ex2f(acc[mt][nt][3] + s1));
            uh[mt][nt][0] = reinterpret_cast<unsigned&>(h0);
            uh[mt][nt][1] = reinterpret_cast<unsigned&>(h1);
            float2 f0 = __half22float2(h0), f1 = __half22float2(h1);
            cs0[nt] += f0.x + f1.x;
            cs1[nt] += f0.y + f1.y;
        }
    }
#pragma unroll
    for (int nt = 0; nt < 4; nt++) {
        cs0[nt] += __shfl_xor_sync(0xffffffffu, cs0[nt], 4);
        cs0[nt] += __shfl_xor_sync(0xffffffffu, cs0[nt], 8);
        cs0[nt] += __shfl_xor_sync(0xffffffffu, cs0[nt], 16);
        cs1[nt] += __shfl_xor_sync(0xffffffffu, cs1[nt], 4);
        cs1[nt] += __shfl_xor_sync(0xffffffffu, cs1[nt], 8);
        cs1[nt] += __shfl_xor_sync(0xffffffffu, cs1[nt], 16);
    }
    if (lane < 4) {
#pragma unroll
        for (int nt = 0; nt < 4; nt++) {
            Zp[(w & 3) * 128 + n0 + nt * 8 + 2 * lane]     = cs0[nt];
            Zp[(w & 3) * 128 + n0 + nt * 8 + 2 * lane + 1] = cs1[nt];
        }
    }
    {
        const int kk = lane >> 3, rr = lane & 7;
#pragma unroll
        for (int mt = 0; mt < 2; mt++)
#pragma unroll
            for (int np = 0; np < 2; np++) {
                uint32_t ad = smem_u32(&Et[m0 + mt * 16 + (kk & 1) * 8 + rr]
                                          [n0 + np * 16 + (kk >> 1) * 8]);
                stsm4(ad, uh[mt][2 * np][0], uh[mt][2 * np][1],
                      uh[mt][2 * np + 1][0], uh[mt][2 * np + 1][1]);
            }
    }
    __syncthreads();
    __half* Eb = g_Eh + (size_t)n * HW * HW + (size_t)q0 * HW + p0;
#pragma unroll
    for (int i = 0; i < 4; i++) {
        int idx = tid + i * 512;
        int row = idx >> 4, ch = (idx & 15) * 8;
        *(uint4*)(Eb + (size_t)row * HW + ch) = *(uint4*)&Et[row][ch];
    }
    if (tid < 128) {
        float z = Zp[tid] + Zp[128 + tid] + Zp[256 + tid] + Zp[384 + tid];
        g_Zp[((size_t)n * 32 + qb) * HW + p0 + tid] = z;
    }
}

// ---------------------------------------------------------------------------
// K2b: rZ[p] = 4096 / sum over 32 q-block partials (fixed order).
// ---------------------------------------------------------------------------
__global__ void k_zred() {
    int p = blockIdx.x * 256 + threadIdx.x;
    int n = blockIdx.y;
    float z = 0.f;
#pragma unroll
    for (int qb = 0; qb < 32; qb++) z += g_Zp[((size_t)n * 32 + qb) * HW + p];
    g_rZ[n * HW + p] = 4096.f / z;
}

// ---------------------------------------------------------------------------
// K2c: G[c][p] = half(F[p][c] * rZ[p])  (transpose + fold, 32x32 tiles)
// ---------------------------------------------------------------------------
__global__ __launch_bounds__(256) void k_gt(const float* __restrict__ F) {
    __shared__ float t[32][33];
    __shared__ float rz[32];
    const int n = blockIdx.z, c0 = blockIdx.y * 32, p0 = blockIdx.x * 32;
    const int tx = threadIdx.x & 7, ty = threadIdx.x >> 3;
    const float* Fb = F + ((size_t)n * HW + p0) * CI;
    float4 v = *(const float4*)(Fb + (size_t)ty * CI + c0 + tx * 4);
    t[ty][tx * 4 + 0] = v.x; t[ty][tx * 4 + 1] = v.y;
    t[ty][tx * 4 + 2] = v.z; t[ty][tx * 4 + 3] = v.w;
    if (threadIdx.x < 32) rz[threadIdx.x] = g_rZ[n * HW + p0 + threadIdx.x];
    __syncthreads();
    const int cl = threadIdx.x >> 3, p4 = (threadIdx.x & 7) * 4;
    union { __half2 h[2]; uint2 u; } cv;
    cv.h[0] = __floats2half2_rn(t[p4 + 0][cl] * rz[p4 + 0], t[p4 + 1][cl] * rz[p4 + 1]);
    cv.h[1] = __floats2half2_rn(t[p4 + 2][cl] * rz[p4 + 2], t[p4 + 3][cl] * rz[p4 + 3]);
    *(uint2*)(g_Gt + ((size_t)n * CI + c0 + cl) * HW + p0 + p4) = cv.u;
}

// ---------------------------------------------------------------------------
// K3: PURE fp16 GEMM, FULL c=256 tile (E read ONCE from DRAM), 3-stage
// cp.async pipeline, one sync per iter, fused output epilogue.
// Block 128q x 256c, k chunk 64, 1024 threads, 32 warps (4q x 8c),
// warp tile 32x32.  Grid (q=32, n=8).
// Loader: EVERY thread does 3 cp16/chunk: E[erow], G[erow], G[erow+128].
// ---------------------------------------------------------------------------
#define K5PAD 72
#define K5_STAGE (384 * K5PAD)              // halves per stage: E 128 rows + G 256 rows
#define K5_SMEM (3 * K5_STAGE * 2)          // 165888 bytes

__global__ __launch_bounds__(1024, 1) void k_attf(const float* __restrict__ mask,
                                                  const float* __restrict__ ref,
                                                  float* __restrict__ out) {
    extern __shared__ __half smh[];
    __half* Es0 = smh;                       // stage: [E 128*72 | G 256*72]
    __half* Gs0 = smh + 128 * K5PAD;
    const int tid = threadIdx.x, w = tid >> 5, lane = tid & 31;
    const int gid = lane >> 2, t4 = lane & 3;
    const int q0 = blockIdx.x * 128, n = blockIdx.y;
    const int wq = (w & 3) * 32, wc = (w >> 2) * 32;
    const __half* Ebase = g_Eh + (size_t)n * HW * HW + (size_t)q0 * HW;
    const __half* Gbase = g_Gt + (size_t)n * CI * HW;

    const int erow = tid >> 3, lch = (tid & 7) * 8;  // erow in 0..127
    const int l7 = lane & 7, lb3 = (lane >> 3) & 1, lb4 = lane >> 4;
    uint32_t aAddr[2], bAddr[2];
#pragma unroll
    for (int mt = 0; mt < 2; mt++)
        aAddr[mt] = smem_u32(Es0 + (wq + mt * 16 + l7 + lb3 * 8) * K5PAD + lb4 * 8);
#pragma unroll
    for (int ntp = 0; ntp < 2; ntp++)
        bAddr[ntp] = smem_u32(Gs0 + (wc + ntp * 16 + l7 + lb4 * 8) * K5PAD + lb3 * 8);
    const uint32_t sdelta = K5_STAGE * 2;     // bytes between stages
    const uint32_t rdelta = 128 * K5PAD * 2;  // bytes between G row erow and erow+128

    const uint32_t eDst = smem_u32(Es0 + erow * K5PAD + lch);
    const uint32_t gDst = smem_u32(Gs0 + erow * K5PAD + lch);
    const __half* eSrc  = Ebase + (size_t)erow * HW + lch;
    const __half* gSrc0 = Gbase + (size_t)erow * HW + lch;
    const __half* gSrc1 = Gbase + (size_t)(erow + 128) * HW + lch;

    float acc[2][4][4] = {};

    // prologue: chunks 0,1 into stages 0,1
#pragma unroll
    for (int s = 0; s < 2; s++) {
        const uint32_t so = s * sdelta;
        const int pp = s * 64;
        cp16(eDst + so, eSrc + pp);
        cp16(gDst + so, gSrc0 + pp);
        cp16(gDst + so + rdelta, gSrc1 + pp);
        asm volatile("cp.async.commit_group;" ::: "memory");
    }

    int cur = 0, nxt = 2;
    for (int it = 0; it < 64; it++) {
        asm volatile("cp.async.wait_group 1;" ::: "memory");
        __syncthreads();
        if (it + 2 < 64) {
            const int pp = (it + 2) * 64;
            const uint32_t so = nxt * sdelta;
            cp16(eDst + so, eSrc + pp);
            cp16(gDst + so, gSrc0 + pp);
            cp16(gDst + so + rdelta, gSrc1 + pp);
        }
        asm volatile("cp.async.commit_group;" ::: "memory");
        const uint32_t so = cur * sdelta;
#pragma unroll
        for (int kt = 0; kt < 4; kt++) {
            unsigned a[2][4], b[2][4];
            ldsm4(a[0], aAddr[0] + so + kt * 32);
            ldsm4(a[1], aAddr[1] + so + kt * 32);
            ldsm4(b[0], bAddr[0] + so + kt * 32);
            ldsm4(b[1], bAddr[1] + so + kt * 32);
#pragma unroll
            for (int mt = 0; mt < 2; mt++)
#pragma unroll
                for (int nt = 0; nt < 4; nt++)
                    mma16h(acc[mt][nt], a[mt][0], a[mt][1], a[mt][2], a[mt][3],
                           b[nt >> 1][(nt & 1) * 2], b[nt >> 1][(nt & 1) * 2 + 1]);
        }
        cur = (cur == 2) ? 0 : cur + 1;
        nxt = (nxt == 2) ? 0 : nxt + 1;
    }

    // Fused epilogue: r = c*16 + (q0>>8), cc = q & 255.
    const float inv = 1.f / 4096.f;
    const int qh8 = q0 >> 8;
    const float* refb = ref + (size_t)n * HW * CI;
    const float* maskb = mask + (size_t)n * HW;
    float* outb = out + (size_t)n * HW * (2 * CI);
#pragma unroll
    for (int mt = 0; mt < 2; mt++)
#pragma unroll
        for (int nt = 0; nt < 4; nt++)
#pragma unroll
            for (int i = 0; i < 2; i++)
#pragma unroll
                for (int j = 0; j < 2; j++) {
                    int q = q0 + wq + mt * 16 + gid + i * 8;
                    int c = wc + nt * 8 + 2 * t4 + j;
                    float a = acc[mt][nt][i * 2 + j] * inv;
                    int r = c * 16 + qh8;
                    int cc = q & 255;
                    float m = maskb[r];
                    float e = m * a + (1.f - m) * refb[(size_t)r * CI + cc];
                    size_t ob = (size_t)r * (2 * CI);
                    outb[ob + cc] = e;
                    outb[ob + CI + cc] = a;
                }
}

extern "C" void kernel_launch(void* const* d_in, const int* in_sizes, int n_in,
                              void* d_out, int out_size) {
    const float* mask = (const float*)d_in[0];
    const float* F    = (const float*)d_in[1];
    const float* ref  = (const float*)d_in[2];
    const float* W    = (const float*)d_in[3];
    float* out = (float*)d_out;
    (void)in_sizes; (void)n_in; (void)out_size;

    cudaFuncSetAttribute(k_escore, cudaFuncAttributeMaxDynamicSharedMemorySize, K2_SMEM);
    cudaFuncSetAttribute(k_attf,   cudaFuncAttributeMaxDynamicSharedMemorySize, K5_SMEM);

    k_query<<<dim3(32, 8), 256>>>(F, W);
    k_norm1<<<dim3(32, 8), 128>>>();
    k_norm2<<<8, 32>>>();
    k_escore<<<dim3(32, 32, 8), 512, K2_SMEM>>>();
    k_zred<<<dim3(16, 8), 256>>>();
    k_gt<<<dim3(128, 8, 8), 256>>>(F);
    k_attf<<<dim3(32, 8), 1024, K5_SMEM>>>(mask, ref, out);
}

// round 16
// speedup vs baseline: 2.8711x; 1.0037x over previous
#include <cuda_runtime.h>
#include <cuda_fp16.h>
#include <cstdint>
#include <cstddef>

#define NB 8
#define HW 4096
#define CI 256
#define DQ 64

// scratch (device globals -- no allocation allowed)
__device__ __half g_Qh[(size_t)NB * HW * DQ];     // fp16 Q, pre-scaled by sqrt(log2 e)
__device__ __half g_Eh[(size_t)NB * HW * HW];     // Eh[n][q][p] = half(2^(S - m[p] + 12))
__device__ __half g_Gt[(size_t)NB * CI * HW];     // G[n][c][p] = half(F[p][c] * 4096 * rZ[p])
__device__ float  g_Zp[(size_t)NB * 32 * HW];     // partial Z per q-block of 128
__device__ float  g_rZ[NB * HW];                  // 4096 / sum_q Eh[q,p]
__device__ float  g_rn[NB * HW];                  // row norms of Q (log2-scaled space)
__device__ float  g_Mp[NB * 32];                  // per-block partial max norms
__device__ float  g_M[NB];                        // max row norm per batch

static __device__ __forceinline__ float ex2f(float x) {
    float y; asm("ex2.approx.ftz.f32 %0, %1;" : "=f"(y) : "f"(x));
    return y;
}
static __device__ __forceinline__ void mma16h(float c[4], unsigned a0, unsigned a1, unsigned a2,
                                              unsigned a3, unsigned b0, unsigned b1) {
    asm volatile(
        "mma.sync.aligned.m16n8k16.row.col.f32.f16.f16.f32 "
        "{%0,%1,%2,%3},{%4,%5,%6,%7},{%8,%9},{%0,%1,%2,%3};"
        : "+f"(c[0]), "+f"(c[1]), "+f"(c[2]), "+f"(c[3])
        : "r"(a0), "r"(a1), "r"(a2), "r"(a3), "r"(b0), "r"(b1));
}
static __device__ __forceinline__ void ldsm4(unsigned r[4], uint32_t a) {
    asm volatile("ldmatrix.sync.aligned.m8n8.x4.shared.b16 {%0,%1,%2,%3}, [%4];"
                 : "=r"(r[0]), "=r"(r[1]), "=r"(r[2]), "=r"(r[3]) : "r"(a));
}
static __device__ __forceinline__ void stsm4(uint32_t a, unsigned r0, unsigned r1,
                                             unsigned r2, unsigned r3) {
    asm volatile("stmatrix.sync.aligned.m8n8.x4.shared.b16 [%0], {%1,%2,%3,%4};"
                 :: "r"(a), "r"(r0), "r"(r1), "r"(r2), "r"(r3) : "memory");
}
static __device__ __forceinline__ uint32_t smem_u32(const void* p) {
    return (uint32_t)__cvta_generic_to_shared(p);
}
static __device__ __forceinline__ void cp16(uint32_t dst, const void* src) {
    asm volatile("cp.async.cg.shared.global [%0], [%1], 16;" :: "r"(dst), "l"(src) : "memory");
}

// ---------------------------------------------------------------------------
// K1: Q = (F @ W) * sqrt(log2 e), fp16 mma.
// ---------------------------------------------------------------------------
__global__ __launch_bounds__(256) void k_query(const float* __restrict__ F,
                                               const float* __restrict__ W) {
    __shared__ __half Fs[128][72];
    __shared__ __half Ws[64][72];
    const int tid = threadIdx.x, w = tid >> 5, lane = tid & 31;
    const int gid = lane >> 2, t4 = lane & 3;
    const int n = blockIdx.y, p0 = blockIdx.x * 128;
    const int wq = (w & 3) * 32, wd = (w >> 2) * 32;
    const float* Fb = F + ((size_t)n * HW + p0) * CI;

    const int l7 = lane & 7, lb3 = (lane >> 3) & 1, lb4 = lane >> 4;
    uint32_t aAddr[2], bAddr[2];
#pragma unroll
    for (int mt = 0; mt < 2; mt++)
        aAddr[mt] = smem_u32(&Fs[wq + mt * 16 + l7 + lb3 * 8][lb4 * 8]);
#pragma unroll
    for (int ntp = 0; ntp < 2; ntp++)
        bAddr[ntp] = smem_u32(&Ws[wd + ntp * 16 + l7 + lb4 * 8][lb3 * 8]);

    float acc[2][4][4] = {};
    for (int kc = 0; kc < 4; kc++) {
        __syncthreads();
#pragma unroll
        for (int i = 0; i < 8; i++) {
            int idx = tid + i * 256;
            int row = idx >> 4, c4 = (idx & 15) * 4;
            float4 v = *(const float4*)(Fb + (size_t)row * CI + kc * 64 + c4);
            *(__half2*)&Fs[row][c4]     = __floats2half2_rn(v.x, v.y);
            *(__half2*)&Fs[row][c4 + 2] = __floats2half2_rn(v.z, v.w);
        }
#pragma unroll
        for (int i = 0; i < 16; i++) {
            int idx = tid + i * 256;
            int ck = idx >> 6, d = idx & 63;
            Ws[d][ck] = __float2half(W[(size_t)(kc * 64 + ck) * DQ + d]);
        }
        __syncthreads();
#pragma unroll
        for (int kt = 0; kt < 4; kt++) {
            unsigned a[2][4], b[2][4];
            ldsm4(a[0], aAddr[0] + kt * 32);
            ldsm4(a[1], aAddr[1] + kt * 32);
            ldsm4(b[0], bAddr[0] + kt * 32);
            ldsm4(b[1], bAddr[1] + kt * 32);
#pragma unroll
            for (int mt = 0; mt < 2; mt++)
#pragma unroll
                for (int nt = 0; nt < 4; nt++)
                    mma16h(acc[mt][nt], a[mt][0], a[mt][1], a[mt][2], a[mt][3],
                           b[nt >> 1][(nt & 1) * 2], b[nt >> 1][(nt & 1) * 2 + 1]);
        }
    }
    const float s = 1.2011224087864498f;  // sqrt(log2 e)
    __half* Qb = g_Qh + (size_t)n * HW * DQ;
#pragma unroll
    for (int mt = 0; mt < 2; mt++)
#pragma unroll
        for (int nt = 0; nt < 4; nt++) {
            int p = p0 + wq + mt * 16 + gid;
            int d = wd + nt * 8 + 2 * t4;
            *(__half2*)(Qb + (size_t)p * DQ + d) =
                __floats2half2_rn(acc[mt][nt][0] * s, acc[mt][nt][1] * s);
            *(__half2*)(Qb + (size_t)(p + 8) * DQ + d) =
                __floats2half2_rn(acc[mt][nt][2] * s, acc[mt][nt][3] * s);
        }
}

// ---------------------------------------------------------------------------
// K1b: row norms of Q + per-block max.
// ---------------------------------------------------------------------------
__global__ __launch_bounds__(128) void k_norm1() {
    __shared__ float mx[128];
    const int n = blockIdx.y, p = blockIdx.x * 128 + threadIdx.x;
    const __half2* q = (const __half2*)(g_Qh + (size_t)(n * HW + p) * DQ);
    float s = 0.f;
#pragma unroll
    for (int i = 0; i < 32; i++) {
        float2 f = __half22float2(q[i]);
        s += f.x * f.x + f.y * f.y;
    }
    float rn = sqrtf(s);
    g_rn[n * HW + p] = rn;
    mx[threadIdx.x] = rn;
    __syncthreads();
    for (int d = 64; d > 0; d >>= 1) {
        if (threadIdx.x < d) mx[threadIdx.x] = fmaxf(mx[threadIdx.x], mx[threadIdx.x + d]);
        __syncthreads();
    }
    if (threadIdx.x == 0) g_Mp[n * 32 + blockIdx.x] = mx[0];
}
__global__ void k_norm2() {
    const int n = blockIdx.x;
    float m = g_Mp[n * 32 + threadIdx.x];
#pragma unroll
    for (int d = 16; d > 0; d >>= 1) m = fmaxf(m, __shfl_xor_sync(0xffffffffu, m, d));
    if (threadIdx.x == 0) g_M[n] = m;
}

// ---------------------------------------------------------------------------
// K2: Eh[q,p] = half(2^(S - rn[p]*M + 12)) per 128x128 tile.
// ---------------------------------------------------------------------------
#define K2_QP_OFF (128 * 72)
#define K2_ET_OFF (2 * 128 * 72)
#define K2_F32_OFF ((2 * 128 * 72 + 128 * 136) * 2)
#define K2_SMEM (K2_F32_OFF + (4 * 128 + 128) * 4)

__global__ __launch_bounds__(512, 2) void k_escore() {
    extern __shared__ char k2sm[];
    __half(*Qq)[72]  = (__half(*)[72])(k2sm);
    __half(*Qp)[72]  = (__half(*)[72])(k2sm + K2_QP_OFF * 2);
    __half(*Et)[136] = (__half(*)[136])(k2sm + K2_ET_OFF * 2);
    float* Zp        = (float*)(k2sm + K2_F32_OFF);
    float* ms        = Zp + 512;
    const int tid = threadIdx.x, w = tid >> 5, lane = tid & 31;
    const int gid = lane >> 2, t4 = lane & 3;
    const int qb = blockIdx.x, pb = blockIdx.y, n = blockIdx.z;
    const int q0 = qb * 128, p0 = pb * 128;
    const int m0 = (w & 3) * 32, n0 = (w >> 2) * 32;
    const __half* Qh = g_Qh + (size_t)n * HW * DQ;

#pragma unroll
    for (int i = 0; i < 2; i++) {
        int idx = tid + i * 512;
        int row = idx >> 3, ch = (idx & 7) * 8;
        *(uint4*)&Qq[row][ch] = *(const uint4*)(Qh + (size_t)(q0 + row) * DQ + ch);
        *(uint4*)&Qp[row][ch] = *(const uint4*)(Qh + (size_t)(p0 + row) * DQ + ch);
    }
    if (tid < 128) ms[tid] = 12.f - g_rn[n * HW + p0 + tid] * g_M[n];
    __syncthreads();

    const int l7 = lane & 7, lb3 = (lane >> 3) & 1, lb4 = lane >> 4;
    uint32_t aAddr[2], bAddr[2];
#pragma unroll
    for (int mt = 0; mt < 2; mt++)
        aAddr[mt] = smem_u32(&Qq[m0 + mt * 16 + l7 + lb3 * 8][lb4 * 8]);
#pragma unroll
    for (int ntp = 0; ntp < 2; ntp++)
        bAddr[ntp] = smem_u32(&Qp[n0 + ntp * 16 + l7 + lb4 * 8][lb3 * 8]);

    float acc[2][4][4] = {};
#pragma unroll
    for (int kt = 0; kt < 4; kt++) {
        unsigned a[2][4], b[2][4];
        ldsm4(a[0], aAddr[0] + kt * 32);
        ldsm4(a[1], aAddr[1] + kt * 32);
        ldsm4(b[0], bAddr[0] + kt * 32);
        ldsm4(b[1], bAddr[1] + kt * 32);
#pragma unroll
        for (int mt = 0; mt < 2; mt++)
#pragma unroll
            for (int nt = 0; nt < 4; nt++)
                mma16h(acc[mt][nt], a[mt][0], a[mt][1], a[mt][2], a[mt][3],
                       b[nt >> 1][(nt & 1) * 2], b[nt >> 1][(nt & 1) * 2 + 1]);
    }

    float cs0[4], cs1[4];
    unsigned uh[2][4][2];
#pragma unroll
    for (int nt = 0; nt < 4; nt++) { cs0[nt] = 0.f; cs1[nt] = 0.f; }
#pragma unroll
    for (int nt = 0; nt < 4; nt++) {
        int cb = n0 + nt * 8 + 2 * t4;
        float s0 = ms[cb], s1 = ms[cb + 1];
#pragma unroll
        for (int mt = 0; mt < 2; mt++) {
            __half2 h0 = __floats2half2_rn(ex2f(acc[mt][nt][0] + s0), ex2f(acc[mt][nt][1] + s1));
            __half2 h1 = __floats2half2_rn(ex2f(acc[mt][nt][2] + s0), ex2f(acc[mt][nt][3] + s1));
            uh[mt][nt][0] = reinterpret_cast<unsigned&>(h0);
            uh[mt][nt][1] = reinterpret_cast<unsigned&>(h1);
            float2 f0 = __half22float2(h0), f1 = __half22float2(h1);
            cs0[nt] += f0.x + f1.x;
            cs1[nt] += f0.y + f1.y;
        }
    }
#pragma unroll
    for (int nt = 0; nt < 4; nt++) {
        cs0[nt] += __shfl_xor_sync(0xffffffffu, cs0[nt], 4);
        cs0[nt] += __shfl_xor_sync(0xffffffffu, cs0[nt], 8);
        cs0[nt] += __shfl_xor_sync(0xffffffffu, cs0[nt], 16);
        cs1[nt] += __shfl_xor_sync(0xffffffffu, cs1[nt], 4);
        cs1[nt] += __shfl_xor_sync(0xffffffffu, cs1[nt], 8);
        cs1[nt] += __shfl_xor_sync(0xffffffffu, cs1[nt], 16);
    }
    if (lane < 4) {
#pragma unroll
        for (int nt = 0; nt < 4; nt++) {
            Zp[(w & 3) * 128 + n0 + nt * 8 + 2 * lane]     = cs0[nt];
            Zp[(w & 3) * 128 + n0 + nt * 8 + 2 * lane + 1] = cs1[nt];
        }
    }
    {
        const int kk = lane >> 3, rr = lane & 7;
#pragma unroll
        for (int mt = 0; mt < 2; mt++)
#pragma unroll
            for (int np = 0; np < 2; np++) {
                uint32_t ad = smem_u32(&Et[m0 + mt * 16 + (kk & 1) * 8 + rr]
                                          [n0 + np * 16 + (kk >> 1) * 8]);
                stsm4(ad, uh[mt][2 * np][0], uh[mt][2 * np][1],
                      uh[mt][2 * np + 1][0], uh[mt][2 * np + 1][1]);
            }
    }
    __syncthreads();
    __half* Eb = g_Eh + (size_t)n * HW * HW + (size_t)q0 * HW + p0;
#pragma unroll
    for (int i = 0; i < 4; i++) {
        int idx = tid + i * 512;
        int row = idx >> 4, ch = (idx & 15) * 8;
        *(uint4*)(Eb + (size_t)row * HW + ch) = *(uint4*)&Et[row][ch];
    }
    if (tid < 128) {
        float z = Zp[tid] + Zp[128 + tid] + Zp[256 + tid] + Zp[384 + tid];
        g_Zp[((size_t)n * 32 + qb) * HW + p0 + tid] = z;
    }
}

// ---------------------------------------------------------------------------
// K2b: rZ[p] = 4096 / sum over 32 q-block partials (fixed order).
// ---------------------------------------------------------------------------
__global__ void k_zred() {
    int p = blockIdx.x * 256 + threadIdx.x;
    int n = blockIdx.y;
    float z = 0.f;
#pragma unroll
    for (int qb = 0; qb < 32; qb++) z += g_Zp[((size_t)n * 32 + qb) * HW + p];
    g_rZ[n * HW + p] = 4096.f / z;
}

// ---------------------------------------------------------------------------
// K2c: G[c][p] = half(F[p][c] * rZ[p])  (transpose + fold, 32x32 tiles)
// ---------------------------------------------------------------------------
__global__ __launch_bounds__(256) void k_gt(const float* __restrict__ F) {
    __shared__ float t[32][33];
    __shared__ float rz[32];
    const int n = blockIdx.z, c0 = blockIdx.y * 32, p0 = blockIdx.x * 32;
    const int tx = threadIdx.x & 7, ty = threadIdx.x >> 3;
    const float* Fb = F + ((size_t)n * HW + p0) * CI;
    float4 v = *(const float4*)(Fb + (size_t)ty * CI + c0 + tx * 4);
    t[ty][tx * 4 + 0] = v.x; t[ty][tx * 4 + 1] = v.y;
    t[ty][tx * 4 + 2] = v.z; t[ty][tx * 4 + 3] = v.w;
    if (threadIdx.x < 32) rz[threadIdx.x] = g_rZ[n * HW + p0 + threadIdx.x];
    __syncthreads();
    const int cl = threadIdx.x >> 3, p4 = (threadIdx.x & 7) * 4;
    union { __half2 h[2]; uint2 u; } cv;
    cv.h[0] = __floats2half2_rn(t[p4 + 0][cl] * rz[p4 + 0], t[p4 + 1][cl] * rz[p4 + 1]);
    cv.h[1] = __floats2half2_rn(t[p4 + 2][cl] * rz[p4 + 2], t[p4 + 3][cl] * rz[p4 + 3]);
    *(uint2*)(g_Gt + ((size_t)n * CI + c0 + cl) * HW + p0 + p4) = cv.u;
}

// ---------------------------------------------------------------------------
// K3: PURE fp16 GEMM, FULL c=256 tile, 3-stage cp.async pipeline, fused
// output epilogue.  512 threads / 16 warps (4q x 4c), warp tile 32x64
// (128-reg budget -> no spills, deep ILP).  Block 128q x 256c, k chunk 64.
// Grid (q=32, n=8).  Loader: 6 cp16/thread/chunk:
//   E rows erow, erow+64; G rows erow, erow+64, erow+128, erow+192.
// ---------------------------------------------------------------------------
#define K5PAD 72
#define K5_STAGE (384 * K5PAD)              // halves per stage: E 128 rows + G 256 rows
#define K5_SMEM (3 * K5_STAGE * 2)          // 165888 bytes

__global__ __launch_bounds__(512, 1) void k_attf(const float* __restrict__ mask,
                                                 const float* __restrict__ ref,
                                                 float* __restrict__ out) {
    extern __shared__ __half smh[];
    __half* Es0 = smh;                       // stage: [E 128*72 | G 256*72]
    __half* Gs0 = smh + 128 * K5PAD;
    const int tid = threadIdx.x, w = tid >> 5, lane = tid & 31;
    const int gid = lane >> 2, t4 = lane & 3;
    const int q0 = blockIdx.x * 128, n = blockIdx.y;
    const int wq = (w & 3) * 32, wc = (w >> 2) * 64;
    const __half* Ebase = g_Eh + (size_t)n * HW * HW + (size_t)q0 * HW;
    const __half* Gbase = g_Gt + (size_t)n * CI * HW;

    const int erow = tid >> 3, lch = (tid & 7) * 8;  // erow in 0..63
    const int l7 = lane & 7, lb3 = (lane >> 3) & 1, lb4 = lane >> 4;
    uint32_t aAddr[2], bAddr[4];
#pragma unroll
    for (int mt = 0; mt < 2; mt++)
        aAddr[mt] = smem_u32(Es0 + (wq + mt * 16 + l7 + lb3 * 8) * K5PAD + lb4 * 8);
#pragma unroll
    for (int ntp = 0; ntp < 4; ntp++)
        bAddr[ntp] = smem_u32(Gs0 + (wc + ntp * 16 + l7 + lb4 * 8) * K5PAD + lb3 * 8);
    const uint32_t sdelta = K5_STAGE * 2;    // bytes between stages
    const uint32_t rdelta = 64 * K5PAD * 2;  // bytes between row r and r+64

    const uint32_t eDst = smem_u32(Es0 + erow * K5PAD + lch);
    const uint32_t gDst = smem_u32(Gs0 + erow * K5PAD + lch);
    const __half* eSrc0 = Ebase + (size_t)erow * HW + lch;
    const __half* eSrc1 = Ebase + (size_t)(erow + 64) * HW + lch;
    const __half* gSrc0 = Gbase + (size_t)erow * HW + lch;
    const __half* gSrc1 = Gbase + (size_t)(erow + 64) * HW + lch;
    const __half* gSrc2 = Gbase + (size_t)(erow + 128) * HW + lch;
    const __half* gSrc3 = Gbase + (size_t)(erow + 192) * HW + lch;

    float acc[2][8][4] = {};

    // prologue: chunks 0,1 into stages 0,1
#pragma unroll
    for (int s = 0; s < 2; s++) {
        const uint32_t so = s * sdelta;
        const int pp = s * 64;
        cp16(eDst + so, eSrc0 + pp);
        cp16(eDst + so + rdelta, eSrc1 + pp);
        cp16(gDst + so, gSrc0 + pp);
        cp16(gDst + so + rdelta, gSrc1 + pp);
        cp16(gDst + so + 2 * rdelta, gSrc2 + pp);
        cp16(gDst + so + 3 * rdelta, gSrc3 + pp);
        asm volatile("cp.async.commit_group;" ::: "memory");
    }

    int cur = 0, nxt = 2;
    for (int it = 0; it < 64; it++) {
        asm volatile("cp.async.wait_group 1;" ::: "memory");
        __syncthreads();
        if (it + 2 < 64) {
            const int pp = (it + 2) * 64;
            const uint32_t so = nxt * sdelta;
            cp16(eDst + so, eSrc0 + pp);
            cp16(eDst + so + rdelta, eSrc1 + pp);
            cp16(gDst + so, gSrc0 + pp);
            cp16(gDst + so + rdelta, gSrc1 + pp);
            cp16(gDst + so + 2 * rdelta, gSrc2 + pp);
            cp16(gDst + so + 3 * rdelta, gSrc3 + pp);
        }
        asm volatile("cp.async.commit_group;" ::: "memory");
        const uint32_t so = cur * sdelta;
#pragma unroll
        for (int kt = 0; kt < 4; kt++) {
            unsigned a[2][4], b[4][4];
            ldsm4(a[0], aAddr[0] + so + kt * 32);
            ldsm4(a[1], aAddr[1] + so + kt * 32);
#pragma unroll
            for (int ntp = 0; ntp < 4; ntp++)
                ldsm4(b[ntp], bAddr[ntp] + so + kt * 32);
#pragma unroll
            for (int mt = 0; mt < 2; mt++)
#pragma unroll
                for (int nt = 0; nt < 8; nt++)
                    mma16h(acc[mt][nt], a[mt][0], a[mt][1], a[mt][2], a[mt][3],
                           b[nt >> 1][(nt & 1) * 2], b[nt >> 1][(nt & 1) * 2 + 1]);
        }
        cur = (cur == 2) ? 0 : cur + 1;
        nxt = (nxt == 2) ? 0 : nxt + 1;
    }

    // Fused epilogue: r = c*16 + (q0>>8), cc = q & 255.
    const float inv = 1.f / 4096.f;
    const int qh8 = q0 >> 8;
    const float* refb = ref + (size_t)n * HW * CI;
    const float* maskb = mask + (size_t)n * HW;
    float* outb = out + (size_t)n * HW * (2 * CI);
#pragma unroll
    for (int mt = 0; mt < 2; mt++)
#pragma unroll
        for (int nt = 0; nt < 8; nt++)
#pragma unroll
            for (int i = 0; i < 2; i++)
#pragma unroll
                for (int j = 0; j < 2; j++) {
                    int q = q0 + wq + mt * 16 + gid + i * 8;
                    int c = wc + nt * 8 + 2 * t4 + j;
                    float a = acc[mt][nt][i * 2 + j] * inv;
                    int r = c * 16 + qh8;
                    int cc = q & 255;
                    float m = maskb[r];
                    float e = m * a + (1.f - m) * refb[(size_t)r * CI + cc];
                    size_t ob = (size_t)r * (2 * CI);
                    outb[ob + cc] = e;
                    outb[ob + CI + cc] = a;
                }
}

extern "C" void kernel_launch(void* const* d_in, const int* in_sizes, int n_in,
                              void* d_out, int out_size) {
    const float* mask = (const float*)d_in[0];
    const float* F    = (const float*)d_in[1];
    const float* ref  = (const float*)d_in[2];
    const float* W    = (const float*)d_in[3];
    float* out = (float*)d_out;
    (void)in_sizes; (void)n_in; (void)out_size;

    cudaFuncSetAttribute(k_escore, cudaFuncAttributeMaxDynamicSharedMemorySize, K2_SMEM);
    cudaFuncSetAttribute(k_attf,   cudaFuncAttributeMaxDynamicSharedMemorySize, K5_SMEM);

    k_query<<<dim3(32, 8), 256>>>(F, W);
    k_norm1<<<dim3(32, 8), 128>>>();
    k_norm2<<<8, 32>>>();
    k_escore<<<dim3(32, 32, 8), 512, K2_SMEM>>>();
    k_zred<<<dim3(16, 8), 256>>>();
    k_gt<<<dim3(128, 8, 8), 256>>>(F);
    k_attf<<<dim3(32, 8), 512, K5_SMEM>>>(mask, ref, out);
}